// round 8
// baseline (speedup 1.0000x reference)
#include <cuda_runtime.h>
#include <cuda_bf16.h>
#include <math.h>
#include <stdint.h>

#define NTOK 4096
#define DMODEL 320
#define FFI 1280
#define HEADS 8
#define DH 40
#define CTXN 77
#define CTXD 768

// ---------------- scratch ----------------
__device__ float g_s[DMODEL];
__device__ float g_t[DMODEL];
__device__ float g_Wp[DMODEL * DMODEL];
__device__ float g_Wq[DMODEL * DMODEL];
__device__ float g_bp[DMODEL];
__device__ float g_xt[NTOK * DMODEL];
__device__ float g_h[NTOK * DMODEL];
__device__ float g_ln[NTOK * DMODEL];
__device__ float g_qb[NTOK * DMODEL];
__device__ float g_qkv[NTOK * 3 * DMODEL];
__device__ float g_kv2[CTXN * 2 * DMODEL];
__device__ float g_ao[NTOK * DMODEL];
__device__ float g_fa[NTOK * FFI];
__device__ float g_wqkv[DMODEL * 3 * DMODEL];
__device__ float g_wkv2[CTXD * 2 * DMODEL];
__device__ float g_wff1[DMODEL * 2 * FFI];
__device__ float g_bff1[2 * FFI];

// ---------------- helpers ----------------
__device__ __forceinline__ uint32_t smem_u32(const void* p) {
    return (uint32_t)__cvta_generic_to_shared(p);
}
__device__ __forceinline__ void cp16(uint32_t dst, const void* src, bool pred) {
    int sz = pred ? 16 : 0;
    asm volatile("cp.async.cg.shared.global [%0], [%1], 16, %2;" :: "r"(dst), "l"(src), "r"(sz));
}
__device__ __forceinline__ void cp_commit() { asm volatile("cp.async.commit_group;"); }
__device__ __forceinline__ void cp_wait1() { asm volatile("cp.async.wait_group 1;"); }

__device__ __forceinline__ void mma_tf32(float* d, const uint32_t* a, const uint32_t* b) {
    asm volatile(
        "mma.sync.aligned.m16n8k8.row.col.f32.tf32.tf32.f32 "
        "{%0,%1,%2,%3}, {%4,%5,%6,%7}, {%8,%9}, {%0,%1,%2,%3};"
        : "+f"(d[0]), "+f"(d[1]), "+f"(d[2]), "+f"(d[3])
        : "r"(a[0]), "r"(a[1]), "r"(a[2]), "r"(a[3]), "r"(b[0]), "r"(b[1]));
}
__device__ __forceinline__ void mma_bf16(float* d, const uint32_t* a, uint32_t b0, uint32_t b1) {
    asm volatile(
        "mma.sync.aligned.m16n8k16.row.col.f32.bf16.bf16.f32 "
        "{%0,%1,%2,%3}, {%4,%5,%6,%7}, {%8,%9}, {%0,%1,%2,%3};"
        : "+f"(d[0]), "+f"(d[1]), "+f"(d[2]), "+f"(d[3])
        : "r"(a[0]), "r"(a[1]), "r"(a[2]), "r"(a[3]), "r"(b0), "r"(b1));
}
__device__ __forceinline__ float gelu_f(float g) {
    return 0.5f * g * (1.f + erff(g * 0.70710678118654752f));
}
__device__ __forceinline__ uint32_t packbf2(float a, float b) {
    __nv_bfloat162 p = __floats2bfloat162_rn(a, b);
    return *(uint32_t*)&p;
}

// ---------------- GroupNorm stats ----------------
__global__ void gn_stats_kernel(const float* __restrict__ x,
                                const float* __restrict__ gn_w,
                                const float* __restrict__ gn_b) {
    int g = blockIdx.x;
    int tid = threadIdx.x;
    const float* base = x + (size_t)g * 10 * 4096;
    float s = 0.f, ss = 0.f;
    for (int i = tid; i < 40960; i += 256) {
        float v = base[i];
        s += v; ss += v * v;
    }
    __shared__ float r1[256], r2[256];
    r1[tid] = s; r2[tid] = ss;
    __syncthreads();
    for (int off = 128; off > 0; off >>= 1) {
        if (tid < off) { r1[tid] += r1[tid + off]; r2[tid] += r2[tid + off]; }
        __syncthreads();
    }
    if (tid < 10) {
        float mu = r1[0] / 40960.f;
        float var = r2[0] / 40960.f - mu * mu;
        float inv = rsqrtf(var + 1e-6f);
        int c = g * 10 + tid;
        float w = gn_w[c];
        g_s[c] = inv * w;
        g_t[c] = gn_b[c] - mu * inv * w;
    }
}

__global__ void fold_pin_kernel(const float* __restrict__ pin_w,
                                const float* __restrict__ pin_b) {
    int o = blockIdx.x;
    int tid = threadIdx.x;
    float acc = 0.f;
    for (int c = tid; c < DMODEL; c += 64) {
        float w = pin_w[o * DMODEL + c];
        g_Wp[c * DMODEL + o] = w * g_s[c];
        acc += w * g_t[c];
    }
    __shared__ float r[64];
    r[tid] = acc;
    __syncthreads();
    for (int off = 32; off > 0; off >>= 1) {
        if (tid < off) r[tid] += r[tid + off];
        __syncthreads();
    }
    if (tid == 0) g_bp[o] = pin_b[o] + r[0];
}

// ---------------- transpose ----------------
__global__ void transpose_kernel(const float* __restrict__ in, float* __restrict__ out,
                                 int R, int Cc) {
    __shared__ float tile[32][33];
    int c0 = blockIdx.x * 32, r0 = blockIdx.y * 32;
    int tx = threadIdx.x, ty = threadIdx.y;
#pragma unroll
    for (int i = 0; i < 4; i++) {
        int r = r0 + ty + i * 8, c = c0 + tx;
        if (r < R && c < Cc) tile[ty + i * 8][tx] = in[(size_t)r * Cc + c];
    }
    __syncthreads();
#pragma unroll
    for (int i = 0; i < 4; i++) {
        int c = c0 + ty + i * 8, r = r0 + tx;
        if (c < Cc && r < R) out[(size_t)c * R + r] = tile[tx][ty + i * 8];
    }
}

// ---------------- weight packing ----------------
__global__ void concat3_kernel(const float* __restrict__ a, const float* __restrict__ b,
                               const float* __restrict__ c, float* __restrict__ o,
                               int K, int N) {
    int idx = blockIdx.x * 256 + threadIdx.x;
    if (idx >= K * N) return;
    int k = idx / N, n = idx - k * N;
    size_t ob = (size_t)k * 3 * N + n;
    o[ob] = a[idx]; o[ob + N] = b[idx]; o[ob + 2 * N] = c[idx];
}
__global__ void concat2_kernel(const float* __restrict__ a, const float* __restrict__ b,
                               float* __restrict__ o, int K, int N) {
    int idx = blockIdx.x * 256 + threadIdx.x;
    if (idx >= K * N) return;
    int k = idx / N, n = idx - k * N;
    size_t ob = (size_t)k * 2 * N + n;
    o[ob] = a[idx]; o[ob + N] = b[idx];
}
__global__ void ffperm_kernel(const float* __restrict__ w, const float* __restrict__ bias,
                              float* __restrict__ wo, float* __restrict__ bo) {
    int idx = blockIdx.x * 256 + threadIdx.x;
    if (idx >= DMODEL * FFI) return;
    int k = idx / FFI, j = idx - k * FFI;
    size_t rb = (size_t)k * 2 * FFI;
    wo[rb + 2 * j]     = w[rb + j];
    wo[rb + 2 * j + 1] = w[rb + FFI + j];
    if (k == 0) {
        bo[2 * j] = bias[j];
        bo[2 * j + 1] = bias[FFI + j];
    }
}

// ---------------- tf32 tensor-core GEMM ----------------
__global__ __launch_bounds__(256) void gemm_tc(
    const float* __restrict__ A, const float* __restrict__ B, float* __restrict__ C,
    const float* __restrict__ bias, const float* __restrict__ resid,
    int M, int N, int K, int lda, int ldb, int Csm, int Csn, int geglu) {
    __shared__ __align__(16) uint32_t As[2][128][20];
    __shared__ __align__(16) uint32_t Bs[2][16][72];
    int tid = threadIdx.x;
    int warp = tid >> 5, lane = tid & 31;
    int grp = lane >> 2, t4 = lane & 3;
    int m0 = blockIdx.x * 128, n0 = blockIdx.y * 64;
    int wm = (warp >> 1) * 32, wn = (warp & 1) * 32;

    float acc[2][4][4];
#pragma unroll
    for (int mi = 0; mi < 2; mi++)
#pragma unroll
        for (int ni = 0; ni < 4; ni++)
#pragma unroll
            for (int r = 0; r < 4; r++) acc[mi][ni][r] = 0.f;

    int ra0 = tid >> 2, ka0 = (tid & 3) * 4;
    int ra1 = ra0 + 64;
    bool ap0 = (m0 + ra0) < M, ap1 = (m0 + ra1) < M;
    const float* a0 = A + (size_t)(ap0 ? (m0 + ra0) : 0) * lda + ka0;
    const float* a1 = A + (size_t)(ap1 ? (m0 + ra1) : 0) * lda + ka0;
    int bk0 = tid >> 4, bn0 = (tid & 15) * 4;
    const float* bsrc = B + (size_t)bk0 * ldb + n0 + bn0;

    auto prefetch = [&](int st, int k0) {
        cp16(smem_u32(&As[st][ra0][ka0]), a0 + k0, ap0);
        cp16(smem_u32(&As[st][ra1][ka0]), a1 + k0, ap1);
        cp16(smem_u32(&Bs[st][bk0][bn0]), bsrc + (size_t)k0 * ldb, true);
    };

    int nK = K >> 4;
    prefetch(0, 0);
    cp_commit();
    for (int kt = 0; kt < nK; kt++) {
        if (kt + 1 < nK) prefetch((kt + 1) & 1, (kt + 1) << 4);
        cp_commit();
        cp_wait1();
        __syncthreads();
        int st = kt & 1;
#pragma unroll
        for (int kk = 0; kk < 16; kk += 8) {
            uint32_t af[2][4];
#pragma unroll
            for (int mi = 0; mi < 2; mi++) {
                int rm = wm + mi * 16;
                af[mi][0] = As[st][rm + grp][kk + t4];
                af[mi][1] = As[st][rm + grp + 8][kk + t4];
                af[mi][2] = As[st][rm + grp][kk + t4 + 4];
                af[mi][3] = As[st][rm + grp + 8][kk + t4 + 4];
            }
            uint32_t bf[4][2];
#pragma unroll
            for (int ni = 0; ni < 4; ni++) {
                int cn = wn + ni * 8 + grp;
                bf[ni][0] = Bs[st][kk + t4][cn];
                bf[ni][1] = Bs[st][kk + t4 + 4][cn];
            }
#pragma unroll
            for (int mi = 0; mi < 2; mi++)
#pragma unroll
                for (int ni = 0; ni < 4; ni++)
                    mma_tf32(acc[mi][ni], af[mi], bf[ni]);
        }
        __syncthreads();
    }
#pragma unroll
    for (int mi = 0; mi < 2; mi++) {
        int r0r = m0 + wm + mi * 16 + grp;
        int r1r = r0r + 8;
#pragma unroll
        for (int ni = 0; ni < 4; ni++) {
            int c = n0 + wn + ni * 8 + t4 * 2;
            float b0 = bias ? bias[c] : 0.f;
            float b1 = bias ? bias[c + 1] : 0.f;
            if (geglu) {
                int co = c >> 1;
                if (r0r < M)
                    C[(size_t)r0r * Csm + co] = (acc[mi][ni][0] + b0) * gelu_f(acc[mi][ni][1] + b1);
                if (r1r < M)
                    C[(size_t)r1r * Csm + co] = (acc[mi][ni][2] + b0) * gelu_f(acc[mi][ni][3] + b1);
            } else {
                if (r0r < M) {
                    size_t o0 = (size_t)r0r * Csm + (size_t)c * Csn;
                    size_t o1 = o0 + Csn;
                    float v0 = acc[mi][ni][0] + b0;
                    float v1 = acc[mi][ni][1] + b1;
                    if (resid) { v0 += resid[o0]; v1 += resid[o1]; }
                    C[o0] = v0; C[o1] = v1;
                }
                if (r1r < M) {
                    size_t o0 = (size_t)r1r * Csm + (size_t)c * Csn;
                    size_t o1 = o0 + Csn;
                    float v0 = acc[mi][ni][2] + b0;
                    float v1 = acc[mi][ni][3] + b1;
                    if (resid) { v0 += resid[o0]; v1 += resid[o1]; }
                    C[o0] = v0; C[o1] = v1;
                }
            }
        }
    }
}

// ---------------- LayerNorm: warp per row ----------------
__global__ __launch_bounds__(256) void ln_kernel(const float* __restrict__ in,
                                                 const float* __restrict__ w,
                                                 const float* __restrict__ b,
                                                 float* __restrict__ out) {
    int warp = threadIdx.x >> 5, lane = threadIdx.x & 31;
    int m = blockIdx.x * 8 + warp;
    const float* row = in + (size_t)m * DMODEL;
    float vals[10];
    float s = 0.f, ss = 0.f;
#pragma unroll
    for (int i = 0; i < 10; i++) {
        float v = row[lane + i * 32];
        vals[i] = v;
        s += v; ss += v * v;
    }
#pragma unroll
    for (int off = 16; off > 0; off >>= 1) {
        s += __shfl_xor_sync(0xffffffffu, s, off);
        ss += __shfl_xor_sync(0xffffffffu, ss, off);
    }
    float mu = s / (float)DMODEL;
    float var = ss / (float)DMODEL - mu * mu;
    float rs = rsqrtf(var + 1e-5f);
#pragma unroll
    for (int i = 0; i < 10; i++) {
        int c = lane + i * 32;
        out[(size_t)m * DMODEL + c] = (vals[i] - mu) * rs * w[c] + b[c];
    }
}

// ---------------- flash attention: tf32 QK^T + bf16 PV, exp2 softmax ----------------
// smem words: KR[2][64][44]@0, VR[2][64][40]@5632, Vt32[40][36]@10752, Ps32[128][36]@12192
#define ATTN_SMEM_BYTES (16800 * 4)
__global__ __launch_bounds__(256) void attn_tc(
    const float* __restrict__ Q, int ldq,
    const float* __restrict__ K, const float* __restrict__ V, int ldkv,
    float* __restrict__ O, int n_k) {
    extern __shared__ __align__(16) uint32_t dyn[];
    uint32_t* KrS = dyn;
    uint32_t* VrS = dyn + 5632;
    uint32_t* VtS = dyn + 10752;
    uint32_t* PsS = dyn + 12192;
#define KR(st, r, c) KrS[(st) * 2816 + (r) * 44 + (c)]
#define VR(st, r, c) VrS[(st) * 2560 + (r) * 40 + (c)]

    int h = blockIdx.y;
    int m0 = blockIdx.x * 128;
    int tid = threadIdx.x;
    int warp = tid >> 5, lane = tid & 31;
    int grp = lane >> 2, t4 = lane & 3;
    int wm = warp * 16;
    int row0 = m0 + wm + grp, row1 = row0 + 8;

    const float scale = 0.15811388300841897f * 1.44269504088896f;  // dh^-0.5 * log2(e)
    uint32_t qf[5][4];
#pragma unroll
    for (int kt = 0; kt < 5; kt++) {
        int c = kt * 8 + t4;
        qf[kt][0] = __float_as_uint(Q[(size_t)row0 * ldq + h * DH + c] * scale);
        qf[kt][1] = __float_as_uint(Q[(size_t)row1 * ldq + h * DH + c] * scale);
        qf[kt][2] = __float_as_uint(Q[(size_t)row0 * ldq + h * DH + c + 4] * scale);
        qf[kt][3] = __float_as_uint(Q[(size_t)row1 * ldq + h * DH + c + 4] * scale);
    }

    float o[5][4];
#pragma unroll
    for (int d = 0; d < 5; d++)
#pragma unroll
        for (int r = 0; r < 4; r++) o[d][r] = 0.f;
    float m_r0 = -1e30f, m_r1 = -1e30f, l_r0 = 0.f, l_r1 = 0.f;

    auto prefetch = [&](int st, int kt0) {
        for (int t = tid; t < 640; t += 256) {
            int r = t / 10, c4 = (t - r * 10) * 4;
            bool pred = (kt0 + r) < n_k;
            size_t g = (size_t)(pred ? (kt0 + r) : 0) * ldkv + h * DH + c4;
            cp16(smem_u32(&KR(st, r, c4)), K + g, pred);
            cp16(smem_u32(&VR(st, r, c4)), V + g, pred);
        }
    };

    int nT = (n_k + 63) >> 6;
    prefetch(0, 0);
    cp_commit();
    for (int it = 0; it < nT; it++) {
        if (it + 1 < nT) prefetch((it + 1) & 1, (it + 1) * 64);
        cp_commit();
        cp_wait1();
        __syncthreads();
        int st = it & 1;
        int kcount = min(64, n_k - it * 64);

        // convert V tile -> transposed packed bf16 (zfill'd tails give zeros)
#pragma unroll
        for (int i = 0; i < 5; i++) {
            int idx = tid + i * 256;
            int d = idx >> 5, kp = idx & 31;
            float v0 = __uint_as_float(VR(st, 2 * kp, d));
            float v1 = __uint_as_float(VR(st, 2 * kp + 1, d));
            VtS[d * 36 + kp] = packbf2(v0, v1);
        }

        // S = Q @ K^T (tf32, log2 domain)
        float s[8][4];
#pragma unroll
        for (int nt = 0; nt < 8; nt++)
#pragma unroll
            for (int r = 0; r < 4; r++) s[nt][r] = 0.f;
#pragma unroll
        for (int kt = 0; kt < 5; kt++) {
#pragma unroll
            for (int nt = 0; nt < 8; nt++) {
                uint32_t bf[2];
                bf[0] = KR(st, nt * 8 + grp, kt * 8 + t4);
                bf[1] = KR(st, nt * 8 + grp, kt * 8 + t4 + 4);
                mma_tf32(s[nt], qf[kt], bf);
            }
        }
        if (kcount < 64) {
#pragma unroll
            for (int nt = 0; nt < 8; nt++) {
                int c0 = nt * 8 + 2 * t4;
                if (c0 >= kcount)     { s[nt][0] = -1e30f; s[nt][2] = -1e30f; }
                if (c0 + 1 >= kcount) { s[nt][1] = -1e30f; s[nt][3] = -1e30f; }
            }
        }

        // online softmax (exp2)
        float mx0 = m_r0, mx1 = m_r1;
#pragma unroll
        for (int nt = 0; nt < 8; nt++) {
            mx0 = fmaxf(mx0, fmaxf(s[nt][0], s[nt][1]));
            mx1 = fmaxf(mx1, fmaxf(s[nt][2], s[nt][3]));
        }
        mx0 = fmaxf(mx0, __shfl_xor_sync(0xffffffffu, mx0, 1));
        mx0 = fmaxf(mx0, __shfl_xor_sync(0xffffffffu, mx0, 2));
        mx1 = fmaxf(mx1, __shfl_xor_sync(0xffffffffu, mx1, 1));
        mx1 = fmaxf(mx1, __shfl_xor_sync(0xffffffffu, mx1, 2));
        float f0 = exp2f(m_r0 - mx0), f1 = exp2f(m_r1 - mx1);
        float sum0 = 0.f, sum1 = 0.f;
#pragma unroll
        for (int nt = 0; nt < 8; nt++) {
            float p0 = exp2f(s[nt][0] - mx0);
            float p1 = exp2f(s[nt][1] - mx0);
            float p2 = exp2f(s[nt][2] - mx1);
            float p3 = exp2f(s[nt][3] - mx1);
            sum0 += p0 + p1; sum1 += p2 + p3;
            PsS[(wm + grp) * 36 + nt * 4 + t4]     = packbf2(p0, p1);
            PsS[(wm + grp + 8) * 36 + nt * 4 + t4] = packbf2(p2, p3);
        }
        sum0 += __shfl_xor_sync(0xffffffffu, sum0, 1);
        sum0 += __shfl_xor_sync(0xffffffffu, sum0, 2);
        sum1 += __shfl_xor_sync(0xffffffffu, sum1, 1);
        sum1 += __shfl_xor_sync(0xffffffffu, sum1, 2);
        l_r0 = l_r0 * f0 + sum0; m_r0 = mx0;
        l_r1 = l_r1 * f1 + sum1; m_r1 = mx1;

#pragma unroll
        for (int d = 0; d < 5; d++) {
            o[d][0] *= f0; o[d][1] *= f0;
            o[d][2] *= f1; o[d][3] *= f1;
        }
        __syncthreads();  // Vt32 (cross-warp) + Ps visible

        // O += P @ V (bf16 m16n8k16): 5 d-tiles x 4 k16-steps
        uint32_t pa[4][4];
#pragma unroll
        for (int ks = 0; ks < 4; ks++) {
            pa[ks][0] = PsS[(wm + grp) * 36 + ks * 8 + t4];
            pa[ks][1] = PsS[(wm + grp + 8) * 36 + ks * 8 + t4];
            pa[ks][2] = PsS[(wm + grp) * 36 + ks * 8 + 4 + t4];
            pa[ks][3] = PsS[(wm + grp + 8) * 36 + ks * 8 + 4 + t4];
        }
#pragma unroll
        for (int d = 0; d < 5; d++) {
            int vrow = (d * 8 + grp) * 36;
#pragma unroll
            for (int ks = 0; ks < 4; ks++) {
                uint32_t b0 = VtS[vrow + ks * 8 + t4];
                uint32_t b1 = VtS[vrow + ks * 8 + 4 + t4];
                mma_bf16(o[d], pa[ks], b0, b1);
            }
        }
        __syncthreads();
    }

    float inv0 = 1.f / l_r0, inv1 = 1.f / l_r1;
#pragma unroll
    for (int d = 0; d < 5; d++) {
        int c = h * DH + d * 8 + 2 * t4;
        O[(size_t)row0 * DMODEL + c]     = o[d][0] * inv0;
        O[(size_t)row0 * DMODEL + c + 1] = o[d][1] * inv0;
        O[(size_t)row1 * DMODEL + c]     = o[d][2] * inv1;
        O[(size_t)row1 * DMODEL + c + 1] = o[d][3] * inv1;
    }
#undef KR
#undef VR
}

// ---------------- host launch ----------------
extern "C" void kernel_launch(void* const* d_in, const int* in_sizes, int n_in,
                              void* d_out, int out_size) {
    const float* x      = (const float*)d_in[0];
    const float* ctx    = (const float*)d_in[1];
    const float* gn_w   = (const float*)d_in[2];
    const float* gn_b   = (const float*)d_in[3];
    const float* pin_w  = (const float*)d_in[4];
    const float* pin_b  = (const float*)d_in[5];
    const float* ln1_w  = (const float*)d_in[6];
    const float* ln1_b  = (const float*)d_in[7];
    const float* q1     = (const float*)d_in[8];
    const float* k1     = (const float*)d_in[9];
    const float* v1     = (const float*)d_in[10];
    const float* o1_w   = (const float*)d_in[11];
    const float* o1_b   = (const float*)d_in[12];
    const float* ln2_w  = (const float*)d_in[13];
    const float* ln2_b  = (const float*)d_in[14];
    const float* q2     = (const float*)d_in[15];
    const float* k2     = (const float*)d_in[16];
    const float* v2     = (const float*)d_in[17];
    const float* o2_w   = (const float*)d_in[18];
    const float* o2_b   = (const float*)d_in[19];
    const float* ln3_w  = (const float*)d_in[20];
    const float* ln3_b  = (const float*)d_in[21];
    const float* ff1_w  = (const float*)d_in[22];
    const float* ff1_b  = (const float*)d_in[23];
    const float* ff2_w  = (const float*)d_in[24];
    const float* ff2_b  = (const float*)d_in[25];
    const float* pout_w = (const float*)d_in[26];
    const float* pout_b = (const float*)d_in[27];
    float* out = (float*)d_out;

    float *Wp, *Wq, *bp, *xt, *h, *ln, *qb, *qkv, *kv2, *ao, *fa;
    float *wqkv, *wkv2, *wff1, *bff1;
    cudaGetSymbolAddress((void**)&Wp, g_Wp);
    cudaGetSymbolAddress((void**)&Wq, g_Wq);
    cudaGetSymbolAddress((void**)&bp, g_bp);
    cudaGetSymbolAddress((void**)&xt, g_xt);
    cudaGetSymbolAddress((void**)&h,  g_h);
    cudaGetSymbolAddress((void**)&ln, g_ln);
    cudaGetSymbolAddress((void**)&qb, g_qb);
    cudaGetSymbolAddress((void**)&qkv, g_qkv);
    cudaGetSymbolAddress((void**)&kv2, g_kv2);
    cudaGetSymbolAddress((void**)&ao, g_ao);
    cudaGetSymbolAddress((void**)&fa, g_fa);
    cudaGetSymbolAddress((void**)&wqkv, g_wqkv);
    cudaGetSymbolAddress((void**)&wkv2, g_wkv2);
    cudaGetSymbolAddress((void**)&wff1, g_wff1);
    cudaGetSymbolAddress((void**)&bff1, g_bff1);

    static bool attr_set = false;
    if (!attr_set) {
        cudaFuncSetAttribute(attn_tc, cudaFuncAttributeMaxDynamicSharedMemorySize,
                             ATTN_SMEM_BYTES);
        attr_set = true;
    }

    // prep
    gn_stats_kernel<<<32, 256>>>(x, gn_w, gn_b);
    fold_pin_kernel<<<DMODEL, 64>>>(pin_w, pin_b);
    transpose_kernel<<<dim3(128, 10), dim3(32, 8)>>>(x, xt, DMODEL, NTOK);
    transpose_kernel<<<dim3(10, 10), dim3(32, 8)>>>(pout_w, Wq, DMODEL, DMODEL);
    concat3_kernel<<<(DMODEL * DMODEL + 255) / 256, 256>>>(q1, k1, v1, wqkv, DMODEL, DMODEL);
    concat2_kernel<<<(CTXD * DMODEL + 255) / 256, 256>>>(k2, v2, wkv2, CTXD, DMODEL);
    ffperm_kernel<<<(DMODEL * FFI + 255) / 256, 256>>>(ff1_w, ff1_b, wff1, bff1);

    // pin projection
    gemm_tc<<<dim3(32, 5), 256>>>(xt, Wp, h, bp, nullptr,
        NTOK, DMODEL, DMODEL, DMODEL, DMODEL, DMODEL, 1, 0);

    // self-attention block
    ln_kernel<<<NTOK / 8, 256>>>(h, ln1_w, ln1_b, ln);
    gemm_tc<<<dim3(32, 15), 256>>>(ln, wqkv, qkv, nullptr, nullptr,
        NTOK, 3 * DMODEL, DMODEL, DMODEL, 3 * DMODEL, 3 * DMODEL, 1, 0);
    attn_tc<<<dim3(NTOK / 128, HEADS), 256, ATTN_SMEM_BYTES>>>(
        qkv, 3 * DMODEL, qkv + DMODEL, qkv + 2 * DMODEL, 3 * DMODEL, ao, NTOK);
    gemm_tc<<<dim3(32, 5), 256>>>(ao, o1_w, h, o1_b, h,
        NTOK, DMODEL, DMODEL, DMODEL, DMODEL, DMODEL, 1, 0);

    // cross-attention block
    ln_kernel<<<NTOK / 8, 256>>>(h, ln2_w, ln2_b, ln);
    gemm_tc<<<dim3(32, 5), 256>>>(ln, q2, qb, nullptr, nullptr,
        NTOK, DMODEL, DMODEL, DMODEL, DMODEL, DMODEL, 1, 0);
    gemm_tc<<<dim3(1, 10), 256>>>(ctx, wkv2, kv2, nullptr, nullptr,
        CTXN, 2 * DMODEL, CTXD, CTXD, 2 * DMODEL, 2 * DMODEL, 1, 0);
    attn_tc<<<dim3(NTOK / 128, HEADS), 256, ATTN_SMEM_BYTES>>>(
        qb, DMODEL, kv2, kv2 + DMODEL, 2 * DMODEL, ao, CTXN);
    gemm_tc<<<dim3(32, 5), 256>>>(ao, o2_w, h, o2_b, h,
        NTOK, DMODEL, DMODEL, DMODEL, DMODEL, DMODEL, 1, 0);

    // GEGLU FF block
    ln_kernel<<<NTOK / 8, 256>>>(h, ln3_w, ln3_b, ln);
    gemm_tc<<<dim3(32, 40), 256>>>(ln, wff1, fa, bff1, nullptr,
        NTOK, 2 * FFI, DMODEL, DMODEL, 2 * FFI, FFI, 1, 1);
    gemm_tc<<<dim3(32, 5), 256>>>(fa, ff2_w, h, ff2_b, h,
        NTOK, DMODEL, FFI, FFI, DMODEL, DMODEL, 1, 0);

    // output projection (transposed store) + input residual
    gemm_tc<<<dim3(32, 5), 256>>>(h, Wq, out, pout_b, x,
        NTOK, DMODEL, DMODEL, DMODEL, DMODEL, 1, NTOK, 0);
}

// round 9
// speedup vs baseline: 1.1548x; 1.1548x over previous
#include <cuda_runtime.h>
#include <cuda_fp16.h>
#include <math.h>
#include <stdint.h>

#define NTOK 4096
#define DMODEL 320
#define FFI 1280
#define HEADS 8
#define DH 40
#define CTXN 77
#define CTXD 768

// ---------------- scratch ----------------
__device__ float g_s[DMODEL];
__device__ float g_t[DMODEL];
__device__ float g_bp[DMODEL];
__device__ float g_h[NTOK * DMODEL];
__device__ float g_qb[NTOK * DMODEL];
__device__ float g_qkv[NTOK * 3 * DMODEL];
__device__ float g_kv2[CTXN * 2 * DMODEL];
__device__ float g_wff1[DMODEL * 2 * FFI];   // interleaved fp32 temp
__device__ float g_bff1[2 * FFI];

// fp16 activations
__device__ __align__(16) __half g_x16[NTOK * DMODEL];
__device__ __align__(16) __half g_ln16[NTOK * DMODEL];
__device__ __align__(16) __half g_ao16[NTOK * DMODEL];
__device__ __align__(16) __half g_fa16[NTOK * FFI];
__device__ __align__(16) __half g_hh16[NTOK * DMODEL];
__device__ __align__(16) __half g_ctx16[CTXN * CTXD];
// fp16 weights, [N][K]
__device__ __align__(16) __half g_wpin16[DMODEL * DMODEL];
__device__ __align__(16) __half g_wqkv16[3 * DMODEL * DMODEL];
__device__ __align__(16) __half g_wq216[DMODEL * DMODEL];
__device__ __align__(16) __half g_wkv216[2 * DMODEL * CTXD];
__device__ __align__(16) __half g_wo116[DMODEL * DMODEL];
__device__ __align__(16) __half g_wo216[DMODEL * DMODEL];
__device__ __align__(16) __half g_wff116[2 * FFI * DMODEL];
__device__ __align__(16) __half g_wff216[DMODEL * FFI];
__device__ __align__(16) __half g_wpo16[DMODEL * DMODEL];

// ---------------- helpers ----------------
__device__ __forceinline__ uint32_t smem_u32(const void* p) {
    return (uint32_t)__cvta_generic_to_shared(p);
}
__device__ __forceinline__ void cp16(uint32_t dst, const void* src, bool pred) {
    int sz = pred ? 16 : 0;
    asm volatile("cp.async.cg.shared.global [%0], [%1], 16, %2;" :: "r"(dst), "l"(src), "r"(sz));
}
__device__ __forceinline__ void cp_commit() { asm volatile("cp.async.commit_group;"); }
__device__ __forceinline__ void cp_wait1() { asm volatile("cp.async.wait_group 1;"); }

__device__ __forceinline__ void mma_tf32(float* d, const uint32_t* a, const uint32_t* b) {
    asm volatile(
        "mma.sync.aligned.m16n8k8.row.col.f32.tf32.tf32.f32 "
        "{%0,%1,%2,%3}, {%4,%5,%6,%7}, {%8,%9}, {%0,%1,%2,%3};"
        : "+f"(d[0]), "+f"(d[1]), "+f"(d[2]), "+f"(d[3])
        : "r"(a[0]), "r"(a[1]), "r"(a[2]), "r"(a[3]), "r"(b[0]), "r"(b[1]));
}
__device__ __forceinline__ void mma_f16(float* d, const uint32_t* a, uint32_t b0, uint32_t b1) {
    asm volatile(
        "mma.sync.aligned.m16n8k16.row.col.f32.f16.f16.f32 "
        "{%0,%1,%2,%3}, {%4,%5,%6,%7}, {%8,%9}, {%0,%1,%2,%3};"
        : "+f"(d[0]), "+f"(d[1]), "+f"(d[2]), "+f"(d[3])
        : "r"(a[0]), "r"(a[1]), "r"(a[2]), "r"(a[3]), "r"(b0), "r"(b1));
}
__device__ __forceinline__ float gelu_f(float g) {
    return 0.5f * g * (1.f + erff(g * 0.70710678118654752f));
}

// ---------------- GroupNorm stats ----------------
__global__ void gn_stats_kernel(const float* __restrict__ x,
                                const float* __restrict__ gn_w,
                                const float* __restrict__ gn_b) {
    int g = blockIdx.x;
    int tid = threadIdx.x;
    const float* base = x + (size_t)g * 10 * 4096;
    float s = 0.f, ss = 0.f;
    for (int i = tid; i < 40960; i += 256) {
        float v = base[i];
        s += v; ss += v * v;
    }
    __shared__ float r1[256], r2[256];
    r1[tid] = s; r2[tid] = ss;
    __syncthreads();
    for (int off = 128; off > 0; off >>= 1) {
        if (tid < off) { r1[tid] += r1[tid + off]; r2[tid] += r2[tid + off]; }
        __syncthreads();
    }
    if (tid < 10) {
        float mu = r1[0] / 40960.f;
        float var = r2[0] / 40960.f - mu * mu;
        float inv = rsqrtf(var + 1e-6f);
        int c = g * 10 + tid;
        float w = gn_w[c];
        g_s[c] = inv * w;
        g_t[c] = gn_b[c] - mu * inv * w;
    }
}

// fold GN affine into pin weight; write fp16 [o][c] = [N][K] directly
__global__ void fold_pin_kernel(const float* __restrict__ pin_w,
                                const float* __restrict__ pin_b) {
    int o = blockIdx.x;
    int tid = threadIdx.x;
    float acc = 0.f;
    for (int c = tid; c < DMODEL; c += 64) {
        float w = pin_w[o * DMODEL + c];
        g_wpin16[o * DMODEL + c] = __float2half(w * g_s[c]);
        acc += w * g_t[c];
    }
    __shared__ float r[64];
    r[tid] = acc;
    __syncthreads();
    for (int off = 32; off > 0; off >>= 1) {
        if (tid < off) r[tid] += r[tid + off];
        __syncthreads();
    }
    if (tid == 0) g_bp[o] = pin_b[o] + r[0];
}

// ---------------- transpose fp32 -> fp16: out[c][r] = in[r][c] ----------------
__global__ void transpose16(const float* __restrict__ in, __half* __restrict__ out,
                            int R, int Cc) {
    __shared__ float tile[32][33];
    int c0 = blockIdx.x * 32, r0 = blockIdx.y * 32;
    int tx = threadIdx.x, ty = threadIdx.y;
#pragma unroll
    for (int i = 0; i < 4; i++) {
        int r = r0 + ty + i * 8, c = c0 + tx;
        if (r < R && c < Cc) tile[ty + i * 8][tx] = in[(size_t)r * Cc + c];
    }
    __syncthreads();
#pragma unroll
    for (int i = 0; i < 4; i++) {
        int c = c0 + ty + i * 8, r = r0 + tx;
        if (c < Cc && r < R) out[(size_t)c * R + r] = __float2half(tile[tx][ty + i * 8]);
    }
}

// ---------------- elementwise fp32 -> fp16 ----------------
__global__ void cvt16_kernel(const float* __restrict__ in, __half* __restrict__ out, int n) {
    int i = blockIdx.x * 256 + threadIdx.x;
    if (i < n) out[i] = __float2half(in[i]);
}

// interleave ff1 columns (fp32 temp)
__global__ void ffperm_kernel(const float* __restrict__ w, const float* __restrict__ bias,
                              float* __restrict__ wo, float* __restrict__ bo) {
    int idx = blockIdx.x * 256 + threadIdx.x;
    if (idx >= DMODEL * FFI) return;
    int k = idx / FFI, j = idx - k * FFI;
    size_t rb = (size_t)k * 2 * FFI;
    wo[rb + 2 * j]     = w[rb + j];
    wo[rb + 2 * j + 1] = w[rb + FFI + j];
    if (k == 0) {
        bo[2 * j] = bias[j];
        bo[2 * j + 1] = bias[FFI + j];
    }
}

// ---------------- fp16 tensor-core GEMM (m16n8k16) ----------------
// A fp16 [M][K] row-major, B fp16 [N][K] row-major. BM=128, BN=64, BK=16,
// 256 threads / 8 warps (4m x 2n), warp tile 32x32. acc fp32.
// Output: C fp32 (strided, bias, resid) and/or Ch fp16; geglu mode -> Ch only.
__global__ __launch_bounds__(256) void gemm_fp16(
    const __half* __restrict__ A, const __half* __restrict__ B,
    float* __restrict__ C, __half* __restrict__ Ch,
    const float* __restrict__ bias, const float* __restrict__ resid,
    int M, int N, int K, int Csm, int Csn, int geglu) {
    __shared__ __align__(16) uint32_t As[2][128][12];
    __shared__ __align__(16) uint32_t Bs[2][64][12];
    int tid = threadIdx.x;
    int warp = tid >> 5, lane = tid & 31;
    int grp = lane >> 2, t4 = lane & 3;
    int m0 = blockIdx.x * 128, n0 = blockIdx.y * 64;
    int wm = (warp >> 1) * 32, wn = (warp & 1) * 32;

    float acc[2][4][4];
#pragma unroll
    for (int mi = 0; mi < 2; mi++)
#pragma unroll
        for (int ni = 0; ni < 4; ni++)
#pragma unroll
            for (int r = 0; r < 4; r++) acc[mi][ni][r] = 0.f;

    // A: 128 rows x 2 halves-of-row (16B each); B: 64 rows x 2
    int ar = tid >> 1, apart = tid & 1;
    bool ap = (m0 + ar) < M;
    const __half* asrc = A + (size_t)(ap ? (m0 + ar) : 0) * K + apart * 8;
    int br = (tid & 127) >> 1, bpart = tid & 1;
    const __half* bsrc = B + (size_t)(n0 + br) * K + bpart * 8;
    bool bthread = tid < 128;

    auto prefetch = [&](int st, int k0) {
        cp16(smem_u32(&As[st][ar][apart * 4]), asrc + k0, ap);
        if (bthread) cp16(smem_u32(&Bs[st][br][bpart * 4]), bsrc + k0, true);
    };

    int nK = K >> 4;
    prefetch(0, 0);
    cp_commit();
    for (int kt = 0; kt < nK; kt++) {
        if (kt + 1 < nK) prefetch((kt + 1) & 1, (kt + 1) << 4);
        cp_commit();
        cp_wait1();
        __syncthreads();
        int st = kt & 1;
        uint32_t af[2][4];
#pragma unroll
        for (int mi = 0; mi < 2; mi++) {
            int rm = wm + mi * 16;
            af[mi][0] = As[st][rm + grp][t4];
            af[mi][1] = As[st][rm + grp + 8][t4];
            af[mi][2] = As[st][rm + grp][t4 + 4];
            af[mi][3] = As[st][rm + grp + 8][t4 + 4];
        }
        uint32_t bf[4][2];
#pragma unroll
        for (int ni = 0; ni < 4; ni++) {
            int cn = wn + ni * 8 + grp;
            bf[ni][0] = Bs[st][cn][t4];
            bf[ni][1] = Bs[st][cn][t4 + 4];
        }
#pragma unroll
        for (int mi = 0; mi < 2; mi++)
#pragma unroll
            for (int ni = 0; ni < 4; ni++)
                mma_f16(acc[mi][ni], af[mi], bf[ni][0], bf[ni][1]);
        __syncthreads();
    }
#pragma unroll
    for (int mi = 0; mi < 2; mi++) {
        int r0r = m0 + wm + mi * 16 + grp;
        int r1r = r0r + 8;
#pragma unroll
        for (int ni = 0; ni < 4; ni++) {
            int c = n0 + wn + ni * 8 + t4 * 2;
            float b0 = bias ? bias[c] : 0.f;
            float b1 = bias ? bias[c + 1] : 0.f;
            if (geglu) {
                int co = c >> 1;
                if (r0r < M)
                    Ch[(size_t)r0r * Csm + co] =
                        __float2half((acc[mi][ni][0] + b0) * gelu_f(acc[mi][ni][1] + b1));
                if (r1r < M)
                    Ch[(size_t)r1r * Csm + co] =
                        __float2half((acc[mi][ni][2] + b0) * gelu_f(acc[mi][ni][3] + b1));
            } else {
                if (r0r < M) {
                    size_t o0 = (size_t)r0r * Csm + (size_t)c * Csn;
                    size_t o1 = o0 + Csn;
                    float v0 = acc[mi][ni][0] + b0;
                    float v1 = acc[mi][ni][1] + b1;
                    if (resid) { v0 += resid[o0]; v1 += resid[o1]; }
                    C[o0] = v0; C[o1] = v1;
                    if (Ch) { Ch[o0] = __float2half(v0); Ch[o1] = __float2half(v1); }
                }
                if (r1r < M) {
                    size_t o0 = (size_t)r1r * Csm + (size_t)c * Csn;
                    size_t o1 = o0 + Csn;
                    float v0 = acc[mi][ni][2] + b0;
                    float v1 = acc[mi][ni][3] + b1;
                    if (resid) { v0 += resid[o0]; v1 += resid[o1]; }
                    C[o0] = v0; C[o1] = v1;
                    if (Ch) { Ch[o0] = __float2half(v0); Ch[o1] = __float2half(v1); }
                }
            }
        }
    }
}

// ---------------- LayerNorm: warp per row, fp16 out ----------------
__global__ __launch_bounds__(256) void ln_kernel(const float* __restrict__ in,
                                                 const float* __restrict__ w,
                                                 const float* __restrict__ b,
                                                 __half* __restrict__ out) {
    int warp = threadIdx.x >> 5, lane = threadIdx.x & 31;
    int m = blockIdx.x * 8 + warp;
    const float* row = in + (size_t)m * DMODEL;
    float vals[10];
    float s = 0.f, ss = 0.f;
#pragma unroll
    for (int i = 0; i < 10; i++) {
        float v = row[lane + i * 32];
        vals[i] = v;
        s += v; ss += v * v;
    }
#pragma unroll
    for (int off = 16; off > 0; off >>= 1) {
        s += __shfl_xor_sync(0xffffffffu, s, off);
        ss += __shfl_xor_sync(0xffffffffu, ss, off);
    }
    float mu = s / (float)DMODEL;
    float var = ss / (float)DMODEL - mu * mu;
    float rs = rsqrtf(var + 1e-5f);
#pragma unroll
    for (int i = 0; i < 10; i++) {
        int c = lane + i * 32;
        out[(size_t)m * DMODEL + c] = __float2half((vals[i] - mu) * rs * w[c] + b[c]);
    }
}

// ---------------- tensor-core flash attention (R7 version, fp16 out) ----------------
#define ATTN_SMEM_BYTES (19456 * 4)
__global__ __launch_bounds__(256) void attn_tc(
    const float* __restrict__ Q, int ldq,
    const float* __restrict__ K, const float* __restrict__ V, int ldkv,
    __half* __restrict__ O, int n_k) {
    extern __shared__ __align__(16) uint32_t dyn[];
    uint32_t* KrS = dyn;            // [2][64][44]
    uint32_t* VrS = dyn + 5632;     // [2][64][40]
    uint32_t* PsS = dyn + 10752;    // [128][68]
#define KR(st, r, c) KrS[(st) * 2816 + (r) * 44 + (c)]
#define VR(st, r, c) VrS[(st) * 2560 + (r) * 40 + (c)]
#define PS(r, c)     PsS[(r) * 68 + (c)]

    int h = blockIdx.y;
    int m0 = blockIdx.x * 128;
    int tid = threadIdx.x;
    int warp = tid >> 5, lane = tid & 31;
    int grp = lane >> 2, t4 = lane & 3;
    int wm = warp * 16;
    int row0 = m0 + wm + grp, row1 = row0 + 8;

    const float scale = 0.15811388300841897f;
    uint32_t qf[5][4];
#pragma unroll
    for (int kt = 0; kt < 5; kt++) {
        int c = kt * 8 + t4;
        qf[kt][0] = __float_as_uint(Q[(size_t)row0 * ldq + h * DH + c] * scale);
        qf[kt][1] = __float_as_uint(Q[(size_t)row1 * ldq + h * DH + c] * scale);
        qf[kt][2] = __float_as_uint(Q[(size_t)row0 * ldq + h * DH + c + 4] * scale);
        qf[kt][3] = __float_as_uint(Q[(size_t)row1 * ldq + h * DH + c + 4] * scale);
    }

    float o[5][4];
#pragma unroll
    for (int d = 0; d < 5; d++)
#pragma unroll
        for (int r = 0; r < 4; r++) o[d][r] = 0.f;
    float m_r0 = -1e30f, m_r1 = -1e30f, l_r0 = 0.f, l_r1 = 0.f;

    auto prefetch = [&](int st, int kt0) {
        for (int t = tid; t < 640; t += 256) {
            int r = t / 10, c4 = (t - r * 10) * 4;
            bool pred = (kt0 + r) < n_k;
            size_t g = (size_t)(pred ? (kt0 + r) : 0) * ldkv + h * DH + c4;
            cp16(smem_u32(&KR(st, r, c4)), K + g, pred);
            cp16(smem_u32(&VR(st, r, c4)), V + g, pred);
        }
    };

    int nT = (n_k + 63) >> 6;
    prefetch(0, 0);
    cp_commit();
    for (int it = 0; it < nT; it++) {
        if (it + 1 < nT) prefetch((it + 1) & 1, (it + 1) * 64);
        cp_commit();
        cp_wait1();
        __syncthreads();
        int st = it & 1;
        int kcount = min(64, n_k - it * 64);

        float s[8][4];
#pragma unroll
        for (int nt = 0; nt < 8; nt++)
#pragma unroll
            for (int r = 0; r < 4; r++) s[nt][r] = 0.f;
#pragma unroll
        for (int kt = 0; kt < 5; kt++) {
#pragma unroll
            for (int nt = 0; nt < 8; nt++) {
                uint32_t bf[2];
                bf[0] = KR(st, nt * 8 + grp, kt * 8 + t4);
                bf[1] = KR(st, nt * 8 + grp, kt * 8 + t4 + 4);
                mma_tf32(s[nt], qf[kt], bf);
            }
        }
        if (kcount < 64) {
#pragma unroll
            for (int nt = 0; nt < 8; nt++) {
                int c0 = nt * 8 + 2 * t4;
                if (c0 >= kcount)     { s[nt][0] = -1e30f; s[nt][2] = -1e30f; }
                if (c0 + 1 >= kcount) { s[nt][1] = -1e30f; s[nt][3] = -1e30f; }
            }
        }

        float mx0 = m_r0, mx1 = m_r1;
#pragma unroll
        for (int nt = 0; nt < 8; nt++) {
            mx0 = fmaxf(mx0, fmaxf(s[nt][0], s[nt][1]));
            mx1 = fmaxf(mx1, fmaxf(s[nt][2], s[nt][3]));
        }
        mx0 = fmaxf(mx0, __shfl_xor_sync(0xffffffffu, mx0, 1));
        mx0 = fmaxf(mx0, __shfl_xor_sync(0xffffffffu, mx0, 2));
        mx1 = fmaxf(mx1, __shfl_xor_sync(0xffffffffu, mx1, 1));
        mx1 = fmaxf(mx1, __shfl_xor_sync(0xffffffffu, mx1, 2));
        float f0 = __expf(m_r0 - mx0), f1 = __expf(m_r1 - mx1);
        float sum0 = 0.f, sum1 = 0.f;
#pragma unroll
        for (int nt = 0; nt < 8; nt++) {
            float p0 = __expf(s[nt][0] - mx0);
            float p1 = __expf(s[nt][1] - mx0);
            float p2 = __expf(s[nt][2] - mx1);
            float p3 = __expf(s[nt][3] - mx1);
            sum0 += p0 + p1; sum1 += p2 + p3;
            int c = nt * 8 + 2 * t4;
            PS(wm + grp, c)     = __float_as_uint(p0);
            PS(wm + grp, c + 1) = __float_as_uint(p1);
            PS(wm + grp + 8, c)     = __float_as_uint(p2);
            PS(wm + grp + 8, c + 1) = __float_as_uint(p3);
        }
        sum0 += __shfl_xor_sync(0xffffffffu, sum0, 1);
        sum0 += __shfl_xor_sync(0xffffffffu, sum0, 2);
        sum1 += __shfl_xor_sync(0xffffffffu, sum1, 1);
        sum1 += __shfl_xor_sync(0xffffffffu, sum1, 2);
        l_r0 = l_r0 * f0 + sum0; m_r0 = mx0;
        l_r1 = l_r1 * f1 + sum1; m_r1 = mx1;

#pragma unroll
        for (int d = 0; d < 5; d++) {
            o[d][0] *= f0; o[d][1] *= f0;
            o[d][2] *= f1; o[d][3] *= f1;
        }
        __syncwarp();

        uint32_t pa[8][4];
#pragma unroll
        for (int ks = 0; ks < 8; ks++) {
            pa[ks][0] = PS(wm + grp, ks * 8 + t4);
            pa[ks][1] = PS(wm + grp + 8, ks * 8 + t4);
            pa[ks][2] = PS(wm + grp, ks * 8 + t4 + 4);
            pa[ks][3] = PS(wm + grp + 8, ks * 8 + t4 + 4);
        }
#pragma unroll
        for (int d = 0; d < 5; d++) {
#pragma unroll
            for (int ks = 0; ks < 8; ks++) {
                uint32_t bf[2];
                bf[0] = VR(st, ks * 8 + t4, d * 8 + grp);
                bf[1] = VR(st, ks * 8 + t4 + 4, d * 8 + grp);
                mma_tf32(o[d], pa[ks], bf);
            }
        }
        __syncthreads();
    }

    float inv0 = 1.f / l_r0, inv1 = 1.f / l_r1;
#pragma unroll
    for (int d = 0; d < 5; d++) {
        int c = h * DH + d * 8 + 2 * t4;
        O[(size_t)row0 * DMODEL + c]     = __float2half(o[d][0] * inv0);
        O[(size_t)row0 * DMODEL + c + 1] = __float2half(o[d][1] * inv0);
        O[(size_t)row1 * DMODEL + c]     = __float2half(o[d][2] * inv1);
        O[(size_t)row1 * DMODEL + c + 1] = __float2half(o[d][3] * inv1);
    }
#undef KR
#undef VR
#undef PS
}

// ---------------- host launch ----------------
extern "C" void kernel_launch(void* const* d_in, const int* in_sizes, int n_in,
                              void* d_out, int out_size) {
    const float* x      = (const float*)d_in[0];
    const float* ctx    = (const float*)d_in[1];
    const float* gn_w   = (const float*)d_in[2];
    const float* gn_b   = (const float*)d_in[3];
    const float* pin_w  = (const float*)d_in[4];
    const float* pin_b  = (const float*)d_in[5];
    const float* ln1_w  = (const float*)d_in[6];
    const float* ln1_b  = (const float*)d_in[7];
    const float* q1     = (const float*)d_in[8];
    const float* k1     = (const float*)d_in[9];
    const float* v1     = (const float*)d_in[10];
    const float* o1_w   = (const float*)d_in[11];
    const float* o1_b   = (const float*)d_in[12];
    const float* ln2_w  = (const float*)d_in[13];
    const float* ln2_b  = (const float*)d_in[14];
    const float* q2     = (const float*)d_in[15];
    const float* k2     = (const float*)d_in[16];
    const float* v2     = (const float*)d_in[17];
    const float* o2_w   = (const float*)d_in[18];
    const float* o2_b   = (const float*)d_in[19];
    const float* ln3_w  = (const float*)d_in[20];
    const float* ln3_b  = (const float*)d_in[21];
    const float* ff1_w  = (const float*)d_in[22];
    const float* ff1_b  = (const float*)d_in[23];
    const float* ff2_w  = (const float*)d_in[24];
    const float* ff2_b  = (const float*)d_in[25];
    const float* pout_w = (const float*)d_in[26];
    const float* pout_b = (const float*)d_in[27];
    float* out = (float*)d_out;

    float *bp, *h, *qb, *qkv, *kv2, *wff1, *bff1;
    __half *x16, *ln16, *ao16, *fa16, *hh16, *ctx16;
    __half *wpin16, *wqkv16, *wq216, *wkv216, *wo116, *wo216, *wff116, *wff216, *wpo16;
    cudaGetSymbolAddress((void**)&bp, g_bp);
    cudaGetSymbolAddress((void**)&h, g_h);
    cudaGetSymbolAddress((void**)&qb, g_qb);
    cudaGetSymbolAddress((void**)&qkv, g_qkv);
    cudaGetSymbolAddress((void**)&kv2, g_kv2);
    cudaGetSymbolAddress((void**)&wff1, g_wff1);
    cudaGetSymbolAddress((void**)&bff1, g_bff1);
    cudaGetSymbolAddress((void**)&x16, g_x16);
    cudaGetSymbolAddress((void**)&ln16, g_ln16);
    cudaGetSymbolAddress((void**)&ao16, g_ao16);
    cudaGetSymbolAddress((void**)&fa16, g_fa16);
    cudaGetSymbolAddress((void**)&hh16, g_hh16);
    cudaGetSymbolAddress((void**)&ctx16, g_ctx16);
    cudaGetSymbolAddress((void**)&wpin16, g_wpin16);
    cudaGetSymbolAddress((void**)&wqkv16, g_wqkv16);
    cudaGetSymbolAddress((void**)&wq216, g_wq216);
    cudaGetSymbolAddress((void**)&wkv216, g_wkv216);
    cudaGetSymbolAddress((void**)&wo116, g_wo116);
    cudaGetSymbolAddress((void**)&wo216, g_wo216);
    cudaGetSymbolAddress((void**)&wff116, g_wff116);
    cudaGetSymbolAddress((void**)&wff216, g_wff216);
    cudaGetSymbolAddress((void**)&wpo16, g_wpo16);

    static bool attr_set = false;
    if (!attr_set) {
        cudaFuncSetAttribute(attn_tc, cudaFuncAttributeMaxDynamicSharedMemorySize,
                             ATTN_SMEM_BYTES);
        attr_set = true;
    }

    dim3 t32x8(32, 8);
    // prep: stats + weight conversion (all to fp16 [N][K])
    gn_stats_kernel<<<32, 256>>>(x, gn_w, gn_b);
    fold_pin_kernel<<<DMODEL, 64>>>(pin_w, pin_b);
    transpose16<<<dim3(128, 10), t32x8>>>(x, x16, DMODEL, NTOK);
    transpose16<<<dim3(10, 10), t32x8>>>(q1, wqkv16, DMODEL, DMODEL);
    transpose16<<<dim3(10, 10), t32x8>>>(k1, wqkv16 + DMODEL * DMODEL, DMODEL, DMODEL);
    transpose16<<<dim3(10, 10), t32x8>>>(v1, wqkv16 + 2 * DMODEL * DMODEL, DMODEL, DMODEL);
    transpose16<<<dim3(10, 10), t32x8>>>(o1_w, wo116, DMODEL, DMODEL);
    transpose16<<<dim3(10, 10), t32x8>>>(q2, wq216, DMODEL, DMODEL);
    transpose16<<<dim3(10, 24), t32x8>>>(k2, wkv216, CTXD, DMODEL);
    transpose16<<<dim3(10, 24), t32x8>>>(v2, wkv216 + DMODEL * CTXD, CTXD, DMODEL);
    transpose16<<<dim3(10, 10), t32x8>>>(o2_w, wo216, DMODEL, DMODEL);
    ffperm_kernel<<<(DMODEL * FFI + 255) / 256, 256>>>(ff1_w, ff1_b, wff1, bff1);
    transpose16<<<dim3(80, 10), t32x8>>>(wff1, wff116, DMODEL, 2 * FFI);
    transpose16<<<dim3(10, 40), t32x8>>>(ff2_w, wff216, FFI, DMODEL);
    cvt16_kernel<<<(DMODEL * DMODEL + 255) / 256, 256>>>(pout_w, wpo16, DMODEL * DMODEL);
    cvt16_kernel<<<(CTXN * CTXD + 255) / 256, 256>>>(ctx, ctx16, CTXN * CTXD);

    // pin projection
    gemm_fp16<<<dim3(32, 5), 256>>>(x16, wpin16, h, nullptr, bp, nullptr,
        NTOK, DMODEL, DMODEL, DMODEL, 1, 0);

    // self-attention block
    ln_kernel<<<NTOK / 8, 256>>>(h, ln1_w, ln1_b, ln16);
    gemm_fp16<<<dim3(32, 15), 256>>>(ln16, wqkv16, qkv, nullptr, nullptr, nullptr,
        NTOK, 3 * DMODEL, DMODEL, 3 * DMODEL, 1, 0);
    attn_tc<<<dim3(NTOK / 128, HEADS), 256, ATTN_SMEM_BYTES>>>(
        qkv, 3 * DMODEL, qkv + DMODEL, qkv + 2 * DMODEL, 3 * DMODEL, ao16, NTOK);
    gemm_fp16<<<dim3(32, 5), 256>>>(ao16, wo116, h, nullptr, o1_b, h,
        NTOK, DMODEL, DMODEL, DMODEL, 1, 0);

    // cross-attention block
    ln_kernel<<<NTOK / 8, 256>>>(h, ln2_w, ln2_b, ln16);
    gemm_fp16<<<dim3(32, 5), 256>>>(ln16, wq216, qb, nullptr, nullptr, nullptr,
        NTOK, DMODEL, DMODEL, DMODEL, 1, 0);
    gemm_fp16<<<dim3(1, 10), 256>>>(ctx16, wkv216, kv2, nullptr, nullptr, nullptr,
        CTXN, 2 * DMODEL, CTXD, 2 * DMODEL, 1, 0);
    attn_tc<<<dim3(NTOK / 128, HEADS), 256, ATTN_SMEM_BYTES>>>(
        qb, DMODEL, kv2, kv2 + DMODEL, 2 * DMODEL, ao16, CTXN);
    gemm_fp16<<<dim3(32, 5), 256>>>(ao16, wo216, h, nullptr, o2_b, h,
        NTOK, DMODEL, DMODEL, DMODEL, 1, 0);

    // GEGLU FF block (gelu fused into ff1 epilogue, fp16 out)
    ln_kernel<<<NTOK / 8, 256>>>(h, ln3_w, ln3_b, ln16);
    gemm_fp16<<<dim3(32, 40), 256>>>(ln16, wff116, nullptr, fa16, bff1, nullptr,
        NTOK, 2 * FFI, DMODEL, FFI, 1, 1);
    gemm_fp16<<<dim3(32, 5), 256>>>(fa16, wff216, h, hh16, ff2_b, h,
        NTOK, DMODEL, FFI, DMODEL, 1, 0);

    // output projection (transposed store) + input residual
    gemm_fp16<<<dim3(32, 5), 256>>>(hh16, wpo16, out, nullptr, pout_b, x,
        NTOK, DMODEL, DMODEL, 1, NTOK, 0);
}

// round 10
// speedup vs baseline: 1.3465x; 1.1660x over previous
#include <cuda_runtime.h>
#include <cuda_fp16.h>
#include <math.h>
#include <stdint.h>

#define NTOK 4096
#define DMODEL 320
#define FFI 1280
#define HEADS 8
#define DH 40
#define CTXN 77
#define CTXD 768
#define CTXP 128   // padded cross-attn key count

// ---------------- scratch ----------------
__device__ float g_s[DMODEL];
__device__ float g_t[DMODEL];
__device__ float g_bp[DMODEL];
__device__ float g_h[NTOK * DMODEL];
__device__ float g_wff1[DMODEL * 2 * FFI];
__device__ float g_bff1[2 * FFI];

// fp16 activations
__device__ __align__(16) __half g_x16[NTOK * DMODEL];
__device__ __align__(16) __half g_ln16[NTOK * DMODEL];
__device__ __align__(16) __half g_qk16[NTOK * 2 * DMODEL];   // [tok][q|k] ld 640
__device__ __align__(16) __half g_vt16[DMODEL * NTOK];       // V^T [d][tok]
__device__ __align__(16) __half g_q216[NTOK * DMODEL];
__device__ __align__(16) __half g_k216[CTXN * DMODEL];
__device__ __align__(16) __half g_vt2c16[DMODEL * CTXP];     // cross V^T, zero-padded
__device__ __align__(16) __half g_ao16[NTOK * DMODEL];
__device__ __align__(16) __half g_fa16[NTOK * FFI];
__device__ __align__(16) __half g_hh16[NTOK * DMODEL];
__device__ __align__(16) __half g_ctx16[CTXN * CTXD];
// fp16 weights, [N][K]
__device__ __align__(16) __half g_wpin16[DMODEL * DMODEL];
__device__ __align__(16) __half g_wqk16[2 * DMODEL * DMODEL]; // q1(scaled)|k1
__device__ __align__(16) __half g_wv116[DMODEL * DMODEL];
__device__ __align__(16) __half g_wq216[DMODEL * DMODEL];     // scaled
__device__ __align__(16) __half g_wk216[DMODEL * CTXD];
__device__ __align__(16) __half g_wv216[DMODEL * CTXD];
__device__ __align__(16) __half g_wo116[DMODEL * DMODEL];
__device__ __align__(16) __half g_wo216[DMODEL * DMODEL];
__device__ __align__(16) __half g_wff116[2 * FFI * DMODEL];
__device__ __align__(16) __half g_wff216[DMODEL * FFI];
__device__ __align__(16) __half g_wpo16[DMODEL * DMODEL];

// ---------------- helpers ----------------
__device__ __forceinline__ uint32_t smem_u32(const void* p) {
    return (uint32_t)__cvta_generic_to_shared(p);
}
__device__ __forceinline__ void cp16(uint32_t dst, const void* src, bool pred) {
    int sz = pred ? 16 : 0;
    asm volatile("cp.async.cg.shared.global [%0], [%1], 16, %2;" :: "r"(dst), "l"(src), "r"(sz));
}
__device__ __forceinline__ void cp_commit() { asm volatile("cp.async.commit_group;"); }
__device__ __forceinline__ void cp_wait1() { asm volatile("cp.async.wait_group 1;"); }

__device__ __forceinline__ void mma_f16(float* d, const uint32_t* a, uint32_t b0, uint32_t b1) {
    asm volatile(
        "mma.sync.aligned.m16n8k16.row.col.f32.f16.f16.f32 "
        "{%0,%1,%2,%3}, {%4,%5,%6,%7}, {%8,%9}, {%0,%1,%2,%3};"
        : "+f"(d[0]), "+f"(d[1]), "+f"(d[2]), "+f"(d[3])
        : "r"(a[0]), "r"(a[1]), "r"(a[2]), "r"(a[3]), "r"(b0), "r"(b1));
}
__device__ __forceinline__ float gelu_f(float g) {
    return 0.5f * g * (1.f + erff(g * 0.70710678118654752f));
}
__device__ __forceinline__ uint32_t packh2(float a, float b) {
    __half2 p = __floats2half2_rn(a, b);
    return *(uint32_t*)&p;
}

// ---------------- GroupNorm stats ----------------
__global__ void gn_stats_kernel(const float* __restrict__ x,
                                const float* __restrict__ gn_w,
                                const float* __restrict__ gn_b) {
    int g = blockIdx.x;
    int tid = threadIdx.x;
    const float* base = x + (size_t)g * 10 * 4096;
    float s = 0.f, ss = 0.f;
    for (int i = tid; i < 40960; i += 256) {
        float v = base[i];
        s += v; ss += v * v;
    }
    __shared__ float r1[256], r2[256];
    r1[tid] = s; r2[tid] = ss;
    __syncthreads();
    for (int off = 128; off > 0; off >>= 1) {
        if (tid < off) { r1[tid] += r1[tid + off]; r2[tid] += r2[tid + off]; }
        __syncthreads();
    }
    if (tid < 10) {
        float mu = r1[0] / 40960.f;
        float var = r2[0] / 40960.f - mu * mu;
        float inv = rsqrtf(var + 1e-6f);
        int c = g * 10 + tid;
        float w = gn_w[c];
        g_s[c] = inv * w;
        g_t[c] = gn_b[c] - mu * inv * w;
    }
}

__global__ void fold_pin_kernel(const float* __restrict__ pin_w,
                                const float* __restrict__ pin_b) {
    int o = blockIdx.x;
    int tid = threadIdx.x;
    float acc = 0.f;
    for (int c = tid; c < DMODEL; c += 64) {
        float w = pin_w[o * DMODEL + c];
        g_wpin16[o * DMODEL + c] = __float2half(w * g_s[c]);
        acc += w * g_t[c];
    }
    __shared__ float r[64];
    r[tid] = acc;
    __syncthreads();
    for (int off = 32; off > 0; off >>= 1) {
        if (tid < off) r[tid] += r[tid + off];
        __syncthreads();
    }
    if (tid == 0) g_bp[o] = pin_b[o] + r[0];
}

// ---------------- transpose fp32 -> fp16 (with scale) ----------------
__global__ void transpose16(const float* __restrict__ in, __half* __restrict__ out,
                            int R, int Cc, float scale) {
    __shared__ float tile[32][33];
    int c0 = blockIdx.x * 32, r0 = blockIdx.y * 32;
    int tx = threadIdx.x, ty = threadIdx.y;
#pragma unroll
    for (int i = 0; i < 4; i++) {
        int r = r0 + ty + i * 8, c = c0 + tx;
        if (r < R && c < Cc) tile[ty + i * 8][tx] = in[(size_t)r * Cc + c];
    }
    __syncthreads();
#pragma unroll
    for (int i = 0; i < 4; i++) {
        int c = c0 + ty + i * 8, r = r0 + tx;
        if (c < Cc && r < R) out[(size_t)c * R + r] = __float2half(tile[tx][ty + i * 8] * scale);
    }
}

__global__ void cvt16_kernel(const float* __restrict__ in, __half* __restrict__ out, int n) {
    int i = blockIdx.x * 256 + threadIdx.x;
    if (i < n) out[i] = __float2half(in[i]);
}

__global__ void ffperm_kernel(const float* __restrict__ w, const float* __restrict__ bias,
                              float* __restrict__ wo, float* __restrict__ bo) {
    int idx = blockIdx.x * 256 + threadIdx.x;
    if (idx >= DMODEL * FFI) return;
    int k = idx / FFI, j = idx - k * FFI;
    size_t rb = (size_t)k * 2 * FFI;
    wo[rb + 2 * j]     = w[rb + j];
    wo[rb + 2 * j + 1] = w[rb + FFI + j];
    if (k == 0) {
        bo[2 * j] = bias[j];
        bo[2 * j + 1] = bias[FFI + j];
    }
}

// ---------------- fp16 tensor-core GEMM (m16n8k16) ----------------
__global__ __launch_bounds__(256) void gemm_fp16(
    const __half* __restrict__ A, const __half* __restrict__ B,
    float* __restrict__ C, __half* __restrict__ Ch,
    const float* __restrict__ bias, const float* __restrict__ resid,
    int M, int N, int K, int Csm, int Csn, int geglu) {
    __shared__ __align__(16) uint32_t As[2][128][12];
    __shared__ __align__(16) uint32_t Bs[2][64][12];
    int tid = threadIdx.x;
    int warp = tid >> 5, lane = tid & 31;
    int grp = lane >> 2, t4 = lane & 3;
    int m0 = blockIdx.x * 128, n0 = blockIdx.y * 64;
    int wm = (warp >> 1) * 32, wn = (warp & 1) * 32;

    float acc[2][4][4];
#pragma unroll
    for (int mi = 0; mi < 2; mi++)
#pragma unroll
        for (int ni = 0; ni < 4; ni++)
#pragma unroll
            for (int r = 0; r < 4; r++) acc[mi][ni][r] = 0.f;

    int ar = tid >> 1, apart = tid & 1;
    bool ap = (m0 + ar) < M;
    const __half* asrc = A + (size_t)(ap ? (m0 + ar) : 0) * K + apart * 8;
    int br = (tid & 127) >> 1, bpart = tid & 1;
    const __half* bsrc = B + (size_t)(n0 + br) * K + bpart * 8;
    bool bthread = tid < 128;

    auto prefetch = [&](int st, int k0) {
        cp16(smem_u32(&As[st][ar][apart * 4]), asrc + k0, ap);
        if (bthread) cp16(smem_u32(&Bs[st][br][bpart * 4]), bsrc + k0, true);
    };

    int nK = K >> 4;
    prefetch(0, 0);
    cp_commit();
    for (int kt = 0; kt < nK; kt++) {
        if (kt + 1 < nK) prefetch((kt + 1) & 1, (kt + 1) << 4);
        cp_commit();
        cp_wait1();
        __syncthreads();
        int st = kt & 1;
        uint32_t af[2][4];
#pragma unroll
        for (int mi = 0; mi < 2; mi++) {
            int rm = wm + mi * 16;
            af[mi][0] = As[st][rm + grp][t4];
            af[mi][1] = As[st][rm + grp + 8][t4];
            af[mi][2] = As[st][rm + grp][t4 + 4];
            af[mi][3] = As[st][rm + grp + 8][t4 + 4];
        }
        uint32_t bf[4][2];
#pragma unroll
        for (int ni = 0; ni < 4; ni++) {
            int cn = wn + ni * 8 + grp;
            bf[ni][0] = Bs[st][cn][t4];
            bf[ni][1] = Bs[st][cn][t4 + 4];
        }
#pragma unroll
        for (int mi = 0; mi < 2; mi++)
#pragma unroll
            for (int ni = 0; ni < 4; ni++)
                mma_f16(acc[mi][ni], af[mi], bf[ni][0], bf[ni][1]);
        __syncthreads();
    }
#pragma unroll
    for (int mi = 0; mi < 2; mi++) {
        int r0r = m0 + wm + mi * 16 + grp;
        int r1r = r0r + 8;
#pragma unroll
        for (int ni = 0; ni < 4; ni++) {
            int c = n0 + wn + ni * 8 + t4 * 2;
            float b0 = bias ? bias[c] : 0.f;
            float b1 = bias ? bias[c + 1] : 0.f;
            if (geglu) {
                int co = c >> 1;
                if (r0r < M)
                    Ch[(size_t)r0r * Csm + co] =
                        __float2half((acc[mi][ni][0] + b0) * gelu_f(acc[mi][ni][1] + b1));
                if (r1r < M)
                    Ch[(size_t)r1r * Csm + co] =
                        __float2half((acc[mi][ni][2] + b0) * gelu_f(acc[mi][ni][3] + b1));
            } else {
                if (r0r < M) {
                    size_t o0 = (size_t)r0r * Csm + (size_t)c * Csn;
                    size_t o1 = o0 + Csn;
                    float v0 = acc[mi][ni][0] + b0;
                    float v1 = acc[mi][ni][1] + b1;
                    if (resid) { v0 += resid[o0]; v1 += resid[o1]; }
                    if (C) { C[o0] = v0; C[o1] = v1; }
                    if (Ch) { Ch[o0] = __float2half(v0); Ch[o1] = __float2half(v1); }
                }
                if (r1r < M) {
                    size_t o0 = (size_t)r1r * Csm + (size_t)c * Csn;
                    size_t o1 = o0 + Csn;
                    float v0 = acc[mi][ni][2] + b0;
                    float v1 = acc[mi][ni][3] + b1;
                    if (resid) { v0 += resid[o0]; v1 += resid[o1]; }
                    if (C) { C[o0] = v0; C[o1] = v1; }
                    if (Ch) { Ch[o0] = __float2half(v0); Ch[o1] = __float2half(v1); }
                }
            }
        }
    }
}

// ---------------- LayerNorm: warp per row, fp16 out ----------------
__global__ __launch_bounds__(256) void ln_kernel(const float* __restrict__ in,
                                                 const float* __restrict__ w,
                                                 const float* __restrict__ b,
                                                 __half* __restrict__ out) {
    int warp = threadIdx.x >> 5, lane = threadIdx.x & 31;
    int m = blockIdx.x * 8 + warp;
    const float* row = in + (size_t)m * DMODEL;
    float vals[10];
    float s = 0.f, ss = 0.f;
#pragma unroll
    for (int i = 0; i < 10; i++) {
        float v = row[lane + i * 32];
        vals[i] = v;
        s += v; ss += v * v;
    }
#pragma unroll
    for (int off = 16; off > 0; off >>= 1) {
        s += __shfl_xor_sync(0xffffffffu, s, off);
        ss += __shfl_xor_sync(0xffffffffu, ss, off);
    }
    float mu = s / (float)DMODEL;
    float var = ss / (float)DMODEL - mu * mu;
    float rs = rsqrtf(var + 1e-5f);
#pragma unroll
    for (int i = 0; i < 10; i++) {
        int c = lane + i * 32;
        out[(size_t)m * DMODEL + c] = __float2half((vals[i] - mu) * rs * w[c] + b[c]);
    }
}

// ---------------- fp16 flash attention ----------------
// Q fp16 [tok][ldq] (scale pre-folded into weights), K fp16 [key][ldk],
// Vt fp16 [d_global][ldv] (head h rows h*DH..). 128 q x 1 head per block, 8 warps.
__global__ __launch_bounds__(256) void attn16(
    const __half* __restrict__ Q, int ldq,
    const __half* __restrict__ K, int ldk,
    const __half* __restrict__ Vt, int ldv,
    __half* __restrict__ O, int n_k) {
    __shared__ __align__(16) uint32_t Ks[2][64][20];  // key rows, 40 halves
    __shared__ __align__(16) uint32_t Vs[2][40][36];  // d rows, 64 halves (32 u32 used)

    int h = blockIdx.y;
    int m0 = blockIdx.x * 128;
    int tid = threadIdx.x;
    int warp = tid >> 5, lane = tid & 31;
    int grp = lane >> 2, t4 = lane & 3;
    int wm = warp * 16;
    int row0 = m0 + wm + grp, row1 = row0 + 8;

    // Q fragments: 3 k16-steps (d 0..47, tail zero)
    uint32_t qf[3][4];
#pragma unroll
    for (int kt = 0; kt < 3; kt++) {
        int d0 = h * DH + kt * 16 + 2 * t4;
        qf[kt][0] = *(const uint32_t*)(Q + (size_t)row0 * ldq + d0);
        qf[kt][1] = *(const uint32_t*)(Q + (size_t)row1 * ldq + d0);
        if (kt < 2) {
            qf[kt][2] = *(const uint32_t*)(Q + (size_t)row0 * ldq + d0 + 8);
            qf[kt][3] = *(const uint32_t*)(Q + (size_t)row1 * ldq + d0 + 8);
        } else {
            qf[kt][2] = 0; qf[kt][3] = 0;
        }
    }

    float o[5][4];
#pragma unroll
    for (int d = 0; d < 5; d++)
#pragma unroll
        for (int r = 0; r < 4; r++) o[d][r] = 0.f;
    float m_r0 = -1e30f, m_r1 = -1e30f, l_r0 = 0.f, l_r1 = 0.f;

    auto prefetch = [&](int st, int kt0) {
        // K: 64 rows x 5 cp16
        for (int t = tid; t < 320; t += 256) {
            int r = t / 5, ch = t - r * 5;
            bool pred = (kt0 + r) < n_k;
            const __half* src = K + (size_t)(pred ? (kt0 + r) : 0) * ldk + h * DH + ch * 8;
            cp16(smem_u32(&Ks[st][r][ch * 4]), src, pred);
        }
        // Vt: 40 rows x 4 cp16 (pad region of Vt is zero-initialized global)
        if (tid < 160) {
            int r = tid >> 2, ch = tid & 3;
            const __half* src = Vt + (size_t)(h * DH + r) * ldv + kt0 + ch * 16;
            cp16(smem_u32(&Vs[st][r][ch * 8]), src, true);
            src += 8;
            cp16(smem_u32(&Vs[st][r][ch * 8 + 4]), src, true);
        }
    };
    // NOTE: Vt chunk math: 64 halves per row = 8 cp16 of 8 halves; using 4 threads x 2 each.

    int nT = (n_k + 63) >> 6;
    prefetch(0, 0);
    cp_commit();
    for (int it = 0; it < nT; it++) {
        if (it + 1 < nT) prefetch((it + 1) & 1, (it + 1) * 64);
        cp_commit();
        cp_wait1();
        __syncthreads();
        int st = it & 1;
        int kcount = min(64, n_k - it * 64);

        // S = Q @ K^T  (fp16 k16)
        float s[8][4];
#pragma unroll
        for (int nt = 0; nt < 8; nt++)
#pragma unroll
            for (int r = 0; r < 4; r++) s[nt][r] = 0.f;
#pragma unroll
        for (int kt = 0; kt < 3; kt++) {
#pragma unroll
            for (int nt = 0; nt < 8; nt++) {
                int kr = nt * 8 + grp;
                uint32_t b0 = Ks[st][kr][kt * 8 + t4];
                uint32_t b1 = (kt < 2) ? Ks[st][kr][kt * 8 + 4 + t4] : 0u;
                mma_f16(s[nt], qf[kt], b0, b1);
            }
        }
        if (kcount < 64) {
#pragma unroll
            for (int nt = 0; nt < 8; nt++) {
                int c0 = nt * 8 + 2 * t4;
                if (c0 >= kcount)     { s[nt][0] = -1e30f; s[nt][2] = -1e30f; }
                if (c0 + 1 >= kcount) { s[nt][1] = -1e30f; s[nt][3] = -1e30f; }
            }
        }

        // online softmax
        float mx0 = m_r0, mx1 = m_r1;
#pragma unroll
        for (int nt = 0; nt < 8; nt++) {
            mx0 = fmaxf(mx0, fmaxf(s[nt][0], s[nt][1]));
            mx1 = fmaxf(mx1, fmaxf(s[nt][2], s[nt][3]));
        }
        mx0 = fmaxf(mx0, __shfl_xor_sync(0xffffffffu, mx0, 1));
        mx0 = fmaxf(mx0, __shfl_xor_sync(0xffffffffu, mx0, 2));
        mx1 = fmaxf(mx1, __shfl_xor_sync(0xffffffffu, mx1, 1));
        mx1 = fmaxf(mx1, __shfl_xor_sync(0xffffffffu, mx1, 2));
        float f0 = __expf(m_r0 - mx0), f1 = __expf(m_r1 - mx1);
        float p[8][4];
        float sum0 = 0.f, sum1 = 0.f;
#pragma unroll
        for (int nt = 0; nt < 8; nt++) {
            p[nt][0] = __expf(s[nt][0] - mx0);
            p[nt][1] = __expf(s[nt][1] - mx0);
            p[nt][2] = __expf(s[nt][2] - mx1);
            p[nt][3] = __expf(s[nt][3] - mx1);
            sum0 += p[nt][0] + p[nt][1];
            sum1 += p[nt][2] + p[nt][3];
        }
        sum0 += __shfl_xor_sync(0xffffffffu, sum0, 1);
        sum0 += __shfl_xor_sync(0xffffffffu, sum0, 2);
        sum1 += __shfl_xor_sync(0xffffffffu, sum1, 1);
        sum1 += __shfl_xor_sync(0xffffffffu, sum1, 2);
        l_r0 = l_r0 * f0 + sum0; m_r0 = mx0;
        l_r1 = l_r1 * f1 + sum1; m_r1 = mx1;

        // pack P into register A-fragments (no smem round-trip)
        uint32_t pa[4][4];
#pragma unroll
        for (int ks = 0; ks < 4; ks++) {
            pa[ks][0] = packh2(p[2 * ks][0],     p[2 * ks][1]);
            pa[ks][1] = packh2(p[2 * ks][2],     p[2 * ks][3]);
            pa[ks][2] = packh2(p[2 * ks + 1][0], p[2 * ks + 1][1]);
            pa[ks][3] = packh2(p[2 * ks + 1][2], p[2 * ks + 1][3]);
        }

#pragma unroll
        for (int d = 0; d < 5; d++) {
            o[d][0] *= f0; o[d][1] *= f0;
            o[d][2] *= f1; o[d][3] *= f1;
        }

        // O += P @ V (fp16 k16, V from transposed smem)
#pragma unroll
        for (int d = 0; d < 5; d++) {
            int vr = d * 8 + grp;
#pragma unroll
            for (int ks = 0; ks < 4; ks++) {
                uint32_t b0 = Vs[st][vr][ks * 8 + t4];
                uint32_t b1 = Vs[st][vr][ks * 8 + 4 + t4];
                mma_f16(o[d], pa[ks], b0, b1);
            }
        }
        __syncthreads();
    }

    float inv0 = 1.f / l_r0, inv1 = 1.f / l_r1;
#pragma unroll
    for (int d = 0; d < 5; d++) {
        int c = h * DH + d * 8 + 2 * t4;
        O[(size_t)row0 * DMODEL + c]     = __float2half(o[d][0] * inv0);
        O[(size_t)row0 * DMODEL + c + 1] = __float2half(o[d][1] * inv0);
        O[(size_t)row1 * DMODEL + c]     = __float2half(o[d][2] * inv1);
        O[(size_t)row1 * DMODEL + c + 1] = __float2half(o[d][3] * inv1);
    }
}

// ---------------- host launch ----------------
extern "C" void kernel_launch(void* const* d_in, const int* in_sizes, int n_in,
                              void* d_out, int out_size) {
    const float* x      = (const float*)d_in[0];
    const float* ctx    = (const float*)d_in[1];
    const float* gn_w   = (const float*)d_in[2];
    const float* gn_b   = (const float*)d_in[3];
    const float* pin_w  = (const float*)d_in[4];
    const float* pin_b  = (const float*)d_in[5];
    const float* ln1_w  = (const float*)d_in[6];
    const float* ln1_b  = (const float*)d_in[7];
    const float* q1     = (const float*)d_in[8];
    const float* k1     = (const float*)d_in[9];
    const float* v1     = (const float*)d_in[10];
    const float* o1_w   = (const float*)d_in[11];
    const float* o1_b   = (const float*)d_in[12];
    const float* ln2_w  = (const float*)d_in[13];
    const float* ln2_b  = (const float*)d_in[14];
    const float* q2     = (const float*)d_in[15];
    const float* k2     = (const float*)d_in[16];
    const float* v2     = (const float*)d_in[17];
    const float* o2_w   = (const float*)d_in[18];
    const float* o2_b   = (const float*)d_in[19];
    const float* ln3_w  = (const float*)d_in[20];
    const float* ln3_b  = (const float*)d_in[21];
    const float* ff1_w  = (const float*)d_in[22];
    const float* ff1_b  = (const float*)d_in[23];
    const float* ff2_w  = (const float*)d_in[24];
    const float* ff2_b  = (const float*)d_in[25];
    const float* pout_w = (const float*)d_in[26];
    const float* pout_b = (const float*)d_in[27];
    float* out = (float*)d_out;

    float *bp, *h, *wff1, *bff1;
    __half *x16, *ln16, *qk16, *vt16, *q216, *k216, *vt2c16, *ao16, *fa16, *hh16, *ctx16;
    __half *wpin16, *wqk16, *wv116, *wq216, *wk216, *wv216, *wo116, *wo216;
    __half *wff116, *wff216, *wpo16;
    cudaGetSymbolAddress((void**)&bp, g_bp);
    cudaGetSymbolAddress((void**)&h, g_h);
    cudaGetSymbolAddress((void**)&wff1, g_wff1);
    cudaGetSymbolAddress((void**)&bff1, g_bff1);
    cudaGetSymbolAddress((void**)&x16, g_x16);
    cudaGetSymbolAddress((void**)&ln16, g_ln16);
    cudaGetSymbolAddress((void**)&qk16, g_qk16);
    cudaGetSymbolAddress((void**)&vt16, g_vt16);
    cudaGetSymbolAddress((void**)&q216, g_q216);
    cudaGetSymbolAddress((void**)&k216, g_k216);
    cudaGetSymbolAddress((void**)&vt2c16, g_vt2c16);
    cudaGetSymbolAddress((void**)&ao16, g_ao16);
    cudaGetSymbolAddress((void**)&fa16, g_fa16);
    cudaGetSymbolAddress((void**)&hh16, g_hh16);
    cudaGetSymbolAddress((void**)&ctx16, g_ctx16);
    cudaGetSymbolAddress((void**)&wpin16, g_wpin16);
    cudaGetSymbolAddress((void**)&wqk16, g_wqk16);
    cudaGetSymbolAddress((void**)&wv116, g_wv116);
    cudaGetSymbolAddress((void**)&wq216, g_wq216);
    cudaGetSymbolAddress((void**)&wk216, g_wk216);
    cudaGetSymbolAddress((void**)&wv216, g_wv216);
    cudaGetSymbolAddress((void**)&wo116, g_wo116);
    cudaGetSymbolAddress((void**)&wo216, g_wo216);
    cudaGetSymbolAddress((void**)&wff116, g_wff116);
    cudaGetSymbolAddress((void**)&wff216, g_wff216);
    cudaGetSymbolAddress((void**)&wpo16, g_wpo16);

    const float SC = 0.15811388300841897f;  // dh^-0.5 folded into q weights
    dim3 t32x8(32, 8);
    // prep
    gn_stats_kernel<<<32, 256>>>(x, gn_w, gn_b);
    fold_pin_kernel<<<DMODEL, 64>>>(pin_w, pin_b);
    transpose16<<<dim3(128, 10), t32x8>>>(x, x16, DMODEL, NTOK, 1.f);
    transpose16<<<dim3(10, 10), t32x8>>>(q1, wqk16, DMODEL, DMODEL, SC);
    transpose16<<<dim3(10, 10), t32x8>>>(k1, wqk16 + DMODEL * DMODEL, DMODEL, DMODEL, 1.f);
    transpose16<<<dim3(10, 10), t32x8>>>(v1, wv116, DMODEL, DMODEL, 1.f);
    transpose16<<<dim3(10, 10), t32x8>>>(o1_w, wo116, DMODEL, DMODEL, 1.f);
    transpose16<<<dim3(10, 10), t32x8>>>(q2, wq216, DMODEL, DMODEL, SC);
    transpose16<<<dim3(10, 24), t32x8>>>(k2, wk216, CTXD, DMODEL, 1.f);
    transpose16<<<dim3(10, 24), t32x8>>>(v2, wv216, CTXD, DMODEL, 1.f);
    transpose16<<<dim3(10, 10), t32x8>>>(o2_w, wo216, DMODEL, DMODEL, 1.f);
    ffperm_kernel<<<(DMODEL * FFI + 255) / 256, 256>>>(ff1_w, ff1_b, wff1, bff1);
    transpose16<<<dim3(80, 10), t32x8>>>(wff1, wff116, DMODEL, 2 * FFI, 1.f);
    transpose16<<<dim3(10, 40), t32x8>>>(ff2_w, wff216, FFI, DMODEL, 1.f);
    cvt16_kernel<<<(DMODEL * DMODEL + 255) / 256, 256>>>(pout_w, wpo16, DMODEL * DMODEL);
    cvt16_kernel<<<(CTXN * CTXD + 255) / 256, 256>>>(ctx, ctx16, CTXN * CTXD);

    // pin projection
    gemm_fp16<<<dim3(32, 5), 256>>>(x16, wpin16, h, nullptr, bp, nullptr,
        NTOK, DMODEL, DMODEL, DMODEL, 1, 0);

    // self-attention block
    ln_kernel<<<NTOK / 8, 256>>>(h, ln1_w, ln1_b, ln16);
    gemm_fp16<<<dim3(32, 10), 256>>>(ln16, wqk16, nullptr, qk16, nullptr, nullptr,
        NTOK, 2 * DMODEL, DMODEL, 2 * DMODEL, 1, 0);
    gemm_fp16<<<dim3(32, 5), 256>>>(ln16, wv116, nullptr, vt16, nullptr, nullptr,
        NTOK, DMODEL, DMODEL, 1, NTOK, 0);   // V^T [d][tok]
    attn16<<<dim3(NTOK / 128, HEADS), 256>>>(
        qk16, 2 * DMODEL, qk16 + DMODEL, 2 * DMODEL, vt16, NTOK, ao16, NTOK);
    gemm_fp16<<<dim3(32, 5), 256>>>(ao16, wo116, h, nullptr, o1_b, h,
        NTOK, DMODEL, DMODEL, DMODEL, 1, 0);

    // cross-attention block
    ln_kernel<<<NTOK / 8, 256>>>(h, ln2_w, ln2_b, ln16);
    gemm_fp16<<<dim3(32, 5), 256>>>(ln16, wq216, nullptr, q216, nullptr, nullptr,
        NTOK, DMODEL, DMODEL, DMODEL, 1, 0);
    gemm_fp16<<<dim3(1, 5), 256>>>(ctx16, wk216, nullptr, k216, nullptr, nullptr,
        CTXN, DMODEL, CTXD, DMODEL, 1, 0);
    gemm_fp16<<<dim3(1, 5), 256>>>(ctx16, wv216, nullptr, vt2c16, nullptr, nullptr,
        CTXN, DMODEL, CTXD, 1, CTXP, 0);     // V^T [d][key], pad stays zero
    attn16<<<dim3(NTOK / 128, HEADS), 256>>>(
        q216, DMODEL, k216, DMODEL, vt2c16, CTXP, ao16, CTXN);
    gemm_fp16<<<dim3(32, 5), 256>>>(ao16, wo216, h, nullptr, o2_b, h,
        NTOK, DMODEL, DMODEL, DMODEL, 1, 0);

    // GEGLU FF block
    ln_kernel<<<NTOK / 8, 256>>>(h, ln3_w, ln3_b, ln16);
    gemm_fp16<<<dim3(32, 40), 256>>>(ln16, wff116, nullptr, fa16, bff1, nullptr,
        NTOK, 2 * FFI, DMODEL, FFI, 1, 1);
    gemm_fp16<<<dim3(32, 5), 256>>>(fa16, wff216, h, hh16, ff2_b, h,
        NTOK, DMODEL, FFI, DMODEL, 1, 0);

    // output projection (transposed store) + input residual
    gemm_fp16<<<dim3(32, 5), 256>>>(hh16, wpo16, out, nullptr, pout_b, x,
        NTOK, DMODEL, DMODEL, 1, NTOK, 0);
}

// round 11
// speedup vs baseline: 1.4194x; 1.0541x over previous
#include <cuda_runtime.h>
#include <cuda_fp16.h>
#include <math.h>
#include <stdint.h>

#define NTOK 4096
#define DMODEL 320
#define FFI 1280
#define HEADS 8
#define DH 40
#define CTXN 77
#define CTXD 768
#define CTXP 128   // padded cross-attn key count
#define QSCALE 0.15811388300841897f

// ---------------- scratch ----------------
__device__ float g_s[DMODEL];
__device__ float g_t[DMODEL];
__device__ float g_bp[DMODEL];
__device__ float g_h[NTOK * DMODEL];
__device__ float g_bff1[2 * FFI];

// fp16 activations
__device__ __align__(16) __half g_x16[NTOK * DMODEL];
__device__ __align__(16) __half g_ln16[NTOK * DMODEL];
__device__ __align__(16) __half g_qk16[NTOK * 2 * DMODEL];   // [tok][q|k] ld 640
__device__ __align__(16) __half g_vt16[DMODEL * NTOK];       // V^T [d][tok]
__device__ __align__(16) __half g_q216[NTOK * DMODEL];
__device__ __align__(16) __half g_k216[CTXN * DMODEL];
__device__ __align__(16) __half g_vt2c16[DMODEL * CTXP];     // cross V^T, zero-padded
__device__ __align__(16) __half g_ao16[NTOK * DMODEL];
__device__ __align__(16) __half g_fa16[NTOK * FFI];
__device__ __align__(16) __half g_hh16[NTOK * DMODEL];
__device__ __align__(16) __half g_ctx16[CTXN * CTXD];
// fp16 weights, [N][K]
__device__ __align__(16) __half g_wpin16[DMODEL * DMODEL];
__device__ __align__(16) __half g_wqk16[2 * DMODEL * DMODEL]; // q1(scaled)|k1
__device__ __align__(16) __half g_wv116[DMODEL * DMODEL];
__device__ __align__(16) __half g_wq216[DMODEL * DMODEL];     // scaled
__device__ __align__(16) __half g_wk216[DMODEL * CTXD];
__device__ __align__(16) __half g_wv216[DMODEL * CTXD];
__device__ __align__(16) __half g_wo116[DMODEL * DMODEL];
__device__ __align__(16) __half g_wo216[DMODEL * DMODEL];
__device__ __align__(16) __half g_wff116[2 * FFI * DMODEL];   // interleaved (a,g)
__device__ __align__(16) __half g_wff216[DMODEL * FFI];
__device__ __align__(16) __half g_wpo16[DMODEL * DMODEL];

// ---------------- helpers ----------------
__device__ __forceinline__ uint32_t smem_u32(const void* p) {
    return (uint32_t)__cvta_generic_to_shared(p);
}
__device__ __forceinline__ void cp16(uint32_t dst, const void* src, bool pred) {
    int sz = pred ? 16 : 0;
    asm volatile("cp.async.cg.shared.global [%0], [%1], 16, %2;" :: "r"(dst), "l"(src), "r"(sz));
}
__device__ __forceinline__ void cp_commit() { asm volatile("cp.async.commit_group;"); }
__device__ __forceinline__ void cp_wait1() { asm volatile("cp.async.wait_group 1;"); }

__device__ __forceinline__ void mma_f16(float* d, const uint32_t* a, uint32_t b0, uint32_t b1) {
    asm volatile(
        "mma.sync.aligned.m16n8k16.row.col.f32.f16.f16.f32 "
        "{%0,%1,%2,%3}, {%4,%5,%6,%7}, {%8,%9}, {%0,%1,%2,%3};"
        : "+f"(d[0]), "+f"(d[1]), "+f"(d[2]), "+f"(d[3])
        : "r"(a[0]), "r"(a[1]), "r"(a[2]), "r"(a[3]), "r"(b0), "r"(b1));
}
__device__ __forceinline__ float gelu_f(float g) {
    return 0.5f * g * (1.f + erff(g * 0.70710678118654752f));
}
__device__ __forceinline__ uint32_t packh2(float a, float b) {
    __half2 p = __floats2half2_rn(a, b);
    return *(uint32_t*)&p;
}

// ---------------- GroupNorm stats ----------------
__global__ void gn_stats_kernel(const float* __restrict__ x,
                                const float* __restrict__ gn_w,
                                const float* __restrict__ gn_b) {
    int g = blockIdx.x;
    int tid = threadIdx.x;
    const float* base = x + (size_t)g * 10 * 4096;
    float s = 0.f, ss = 0.f;
    for (int i = tid; i < 40960; i += 256) {
        float v = base[i];
        s += v; ss += v * v;
    }
    __shared__ float r1[256], r2[256];
    r1[tid] = s; r2[tid] = ss;
    __syncthreads();
    for (int off = 128; off > 0; off >>= 1) {
        if (tid < off) { r1[tid] += r1[tid + off]; r2[tid] += r2[tid + off]; }
        __syncthreads();
    }
    if (tid < 10) {
        float mu = r1[0] / 40960.f;
        float var = r2[0] / 40960.f - mu * mu;
        float inv = rsqrtf(var + 1e-6f);
        int c = g * 10 + tid;
        float w = gn_w[c];
        g_s[c] = inv * w;
        g_t[c] = gn_b[c] - mu * inv * w;
    }
}

__global__ void fold_pin_kernel(const float* __restrict__ pin_w,
                                const float* __restrict__ pin_b) {
    int o = blockIdx.x;
    int tid = threadIdx.x;
    float acc = 0.f;
    for (int c = tid; c < DMODEL; c += 64) {
        float w = pin_w[o * DMODEL + c];
        g_wpin16[o * DMODEL + c] = __float2half(w * g_s[c]);
        acc += w * g_t[c];
    }
    __shared__ float r[64];
    r[tid] = acc;
    __syncthreads();
    for (int off = 32; off > 0; off >>= 1) {
        if (tid < off) r[tid] += r[tid + off];
        __syncthreads();
    }
    if (tid == 0) g_bp[o] = pin_b[o] + r[0];
}

// ---------------- unified weight prep: one launch, blockIdx range-dispatch ----------------
__device__ __forceinline__ void tr_tile(const float* __restrict__ in, __half* __restrict__ out,
                                        int R, int Cc, int bx, int by, float scale) {
    __shared__ float tile[32][33];
    int tx = threadIdx.x & 31, ty = threadIdx.x >> 5;
    int c0 = bx * 32, r0 = by * 32;
#pragma unroll
    for (int i = 0; i < 4; i++) {
        int r = r0 + ty + i * 8, c = c0 + tx;
        if (r < R && c < Cc) tile[ty + i * 8][tx] = in[(size_t)r * Cc + c];
    }
    __syncthreads();
#pragma unroll
    for (int i = 0; i < 4; i++) {
        int c = c0 + ty + i * 8, r = r0 + tx;
        if (c < Cc && r < R) out[(size_t)c * R + r] = __float2half(tile[tx][ty + i * 8] * scale);
    }
}

#define PREP_BLOCKS 3728
__global__ __launch_bounds__(256) void prep_kernel(
    const float* __restrict__ x,
    const float* __restrict__ q1, const float* __restrict__ k1,
    const float* __restrict__ v1, const float* __restrict__ o1w,
    const float* __restrict__ q2, const float* __restrict__ k2,
    const float* __restrict__ v2, const float* __restrict__ o2w,
    const float* __restrict__ ff1w, const float* __restrict__ ff1b,
    const float* __restrict__ ff2w, const float* __restrict__ poutw,
    const float* __restrict__ ctx) {
    int b = blockIdx.x;
    int tid = threadIdx.x;
    if (b < 1280) { tr_tile(x, g_x16, DMODEL, NTOK, b % 128, b / 128, 1.f); return; }
    b -= 1280;
    if (b < 100) { tr_tile(q1, g_wqk16, DMODEL, DMODEL, b % 10, b / 10, QSCALE); return; }
    b -= 100;
    if (b < 100) { tr_tile(k1, g_wqk16 + DMODEL * DMODEL, DMODEL, DMODEL, b % 10, b / 10, 1.f); return; }
    b -= 100;
    if (b < 100) { tr_tile(v1, g_wv116, DMODEL, DMODEL, b % 10, b / 10, 1.f); return; }
    b -= 100;
    if (b < 100) { tr_tile(o1w, g_wo116, DMODEL, DMODEL, b % 10, b / 10, 1.f); return; }
    b -= 100;
    if (b < 100) { tr_tile(q2, g_wq216, DMODEL, DMODEL, b % 10, b / 10, QSCALE); return; }
    b -= 100;
    if (b < 240) { tr_tile(k2, g_wk216, CTXD, DMODEL, b % 10, b / 10, 1.f); return; }
    b -= 240;
    if (b < 240) { tr_tile(v2, g_wv216, CTXD, DMODEL, b % 10, b / 10, 1.f); return; }
    b -= 240;
    if (b < 100) { tr_tile(o2w, g_wo216, DMODEL, DMODEL, b % 10, b / 10, 1.f); return; }
    b -= 100;
    if (b < 400) { tr_tile(ff2w, g_wff216, FFI, DMODEL, b % 10, b / 10, 1.f); return; }
    b -= 400;
    if (b < 800) {
        // ff1: fused column-interleave + transpose: wff116[n][k] = ff1w[k][perm(n)]
        __shared__ float tile[32][33];
        int tx = tid & 31, ty = tid >> 5;
        int bx = b % 80, by = b / 80;
        int c0 = bx * 32, r0 = by * 32;  // c: output col n (0..2559), r: k (0..319)
#pragma unroll
        for (int i = 0; i < 4; i++) {
            int k = r0 + ty + i * 8, n = c0 + tx;
            int src = (n & 1) ? (FFI + (n >> 1)) : (n >> 1);
            tile[ty + i * 8][tx] = ff1w[(size_t)k * 2 * FFI + src];
        }
        __syncthreads();
#pragma unroll
        for (int i = 0; i < 4; i++) {
            int n = c0 + ty + i * 8, k = r0 + tx;
            g_wff116[(size_t)n * DMODEL + k] = __float2half(tile[tx][ty + i * 8]);
        }
        return;
    }
    b -= 800;
    if (b < 100) {
        int i0 = b * 1024 + tid * 4;
#pragma unroll
        for (int i = 0; i < 4; i++) g_wpo16[i0 + i] = __float2half(poutw[i0 + i]);
        return;
    }
    b -= 100;
    if (b < 58) {
        int i0 = b * 1024 + tid * 4;
#pragma unroll
        for (int i = 0; i < 4; i++) {
            int idx = i0 + i;
            if (idx < CTXN * CTXD) g_ctx16[idx] = __float2half(ctx[idx]);
        }
        return;
    }
    b -= 58;
    // bias interleave: 10 blocks x 256
    int idx = b * 256 + tid;
    int j = idx >> 1;
    g_bff1[idx] = (idx & 1) ? ff1b[FFI + j] : ff1b[j];
}

// ---------------- fp16 tensor-core GEMM (m16n8k16) ----------------
__global__ __launch_bounds__(256) void gemm_fp16(
    const __half* __restrict__ A, const __half* __restrict__ B,
    float* __restrict__ C, __half* __restrict__ Ch,
    const float* __restrict__ bias, const float* __restrict__ resid,
    int M, int N, int K, int Csm, int Csn, int geglu) {
    __shared__ __align__(16) uint32_t As[2][128][12];
    __shared__ __align__(16) uint32_t Bs[2][64][12];
    int tid = threadIdx.x;
    int warp = tid >> 5, lane = tid & 31;
    int grp = lane >> 2, t4 = lane & 3;
    int m0 = blockIdx.x * 128, n0 = blockIdx.y * 64;
    int wm = (warp >> 1) * 32, wn = (warp & 1) * 32;

    float acc[2][4][4];
#pragma unroll
    for (int mi = 0; mi < 2; mi++)
#pragma unroll
        for (int ni = 0; ni < 4; ni++)
#pragma unroll
            for (int r = 0; r < 4; r++) acc[mi][ni][r] = 0.f;

    int ar = tid >> 1, apart = tid & 1;
    bool ap = (m0 + ar) < M;
    const __half* asrc = A + (size_t)(ap ? (m0 + ar) : 0) * K + apart * 8;
    int br = (tid & 127) >> 1, bpart = tid & 1;
    const __half* bsrc = B + (size_t)(n0 + br) * K + bpart * 8;
    bool bthread = tid < 128;

    auto prefetch = [&](int st, int k0) {
        cp16(smem_u32(&As[st][ar][apart * 4]), asrc + k0, ap);
        if (bthread) cp16(smem_u32(&Bs[st][br][bpart * 4]), bsrc + k0, true);
    };

    int nK = K >> 4;
    prefetch(0, 0);
    cp_commit();
    for (int kt = 0; kt < nK; kt++) {
        if (kt + 1 < nK) prefetch((kt + 1) & 1, (kt + 1) << 4);
        cp_commit();
        cp_wait1();
        __syncthreads();
        int st = kt & 1;
        uint32_t af[2][4];
#pragma unroll
        for (int mi = 0; mi < 2; mi++) {
            int rm = wm + mi * 16;
            af[mi][0] = As[st][rm + grp][t4];
            af[mi][1] = As[st][rm + grp + 8][t4];
            af[mi][2] = As[st][rm + grp][t4 + 4];
            af[mi][3] = As[st][rm + grp + 8][t4 + 4];
        }
        uint32_t bf[4][2];
#pragma unroll
        for (int ni = 0; ni < 4; ni++) {
            int cn = wn + ni * 8 + grp;
            bf[ni][0] = Bs[st][cn][t4];
            bf[ni][1] = Bs[st][cn][t4 + 4];
        }
#pragma unroll
        for (int mi = 0; mi < 2; mi++)
#pragma unroll
            for (int ni = 0; ni < 4; ni++)
                mma_f16(acc[mi][ni], af[mi], bf[ni][0], bf[ni][1]);
        __syncthreads();
    }
#pragma unroll
    for (int mi = 0; mi < 2; mi++) {
        int r0r = m0 + wm + mi * 16 + grp;
        int r1r = r0r + 8;
#pragma unroll
        for (int ni = 0; ni < 4; ni++) {
            int c = n0 + wn + ni * 8 + t4 * 2;
            float b0 = bias ? bias[c] : 0.f;
            float b1 = bias ? bias[c + 1] : 0.f;
            if (geglu) {
                int co = c >> 1;
                if (r0r < M)
                    Ch[(size_t)r0r * Csm + co] =
                        __float2half((acc[mi][ni][0] + b0) * gelu_f(acc[mi][ni][1] + b1));
                if (r1r < M)
                    Ch[(size_t)r1r * Csm + co] =
                        __float2half((acc[mi][ni][2] + b0) * gelu_f(acc[mi][ni][3] + b1));
            } else {
                if (r0r < M) {
                    size_t o0 = (size_t)r0r * Csm + (size_t)c * Csn;
                    size_t o1 = o0 + Csn;
                    float v0 = acc[mi][ni][0] + b0;
                    float v1 = acc[mi][ni][1] + b1;
                    if (resid) { v0 += resid[o0]; v1 += resid[o1]; }
                    if (C) { C[o0] = v0; C[o1] = v1; }
                    if (Ch) { Ch[o0] = __float2half(v0); Ch[o1] = __float2half(v1); }
                }
                if (r1r < M) {
                    size_t o0 = (size_t)r1r * Csm + (size_t)c * Csn;
                    size_t o1 = o0 + Csn;
                    float v0 = acc[mi][ni][2] + b0;
                    float v1 = acc[mi][ni][3] + b1;
                    if (resid) { v0 += resid[o0]; v1 += resid[o1]; }
                    if (C) { C[o0] = v0; C[o1] = v1; }
                    if (Ch) { Ch[o0] = __float2half(v0); Ch[o1] = __float2half(v1); }
                }
            }
        }
    }
}

// ---------------- LayerNorm: warp per row, fp16 out ----------------
__global__ __launch_bounds__(256) void ln_kernel(const float* __restrict__ in,
                                                 const float* __restrict__ w,
                                                 const float* __restrict__ b,
                                                 __half* __restrict__ out) {
    int warp = threadIdx.x >> 5, lane = threadIdx.x & 31;
    int m = blockIdx.x * 8 + warp;
    const float* row = in + (size_t)m * DMODEL;
    float vals[10];
    float s = 0.f, ss = 0.f;
#pragma unroll
    for (int i = 0; i < 10; i++) {
        float v = row[lane + i * 32];
        vals[i] = v;
        s += v; ss += v * v;
    }
#pragma unroll
    for (int off = 16; off > 0; off >>= 1) {
        s += __shfl_xor_sync(0xffffffffu, s, off);
        ss += __shfl_xor_sync(0xffffffffu, ss, off);
    }
    float mu = s / (float)DMODEL;
    float var = ss / (float)DMODEL - mu * mu;
    float rs = rsqrtf(var + 1e-5f);
#pragma unroll
    for (int i = 0; i < 10; i++) {
        int c = lane + i * 32;
        out[(size_t)m * DMODEL + c] = __float2half((vals[i] - mu) * rs * w[c] + b[c]);
    }
}

// ---------------- fp16 flash attention ----------------
__global__ __launch_bounds__(256) void attn16(
    const __half* __restrict__ Q, int ldq,
    const __half* __restrict__ K, int ldk,
    const __half* __restrict__ Vt, int ldv,
    __half* __restrict__ O, int n_k) {
    __shared__ __align__(16) uint32_t Ks[2][64][20];  // key rows, 40 halves
    __shared__ __align__(16) uint32_t Vs[2][40][36];  // d rows, 64 halves (32 u32 used)

    int h = blockIdx.y;
    int m0 = blockIdx.x * 128;
    int tid = threadIdx.x;
    int warp = tid >> 5, lane = tid & 31;
    int grp = lane >> 2, t4 = lane & 3;
    int wm = warp * 16;
    int row0 = m0 + wm + grp, row1 = row0 + 8;

    uint32_t qf[3][4];
#pragma unroll
    for (int kt = 0; kt < 3; kt++) {
        int d0 = h * DH + kt * 16 + 2 * t4;
        qf[kt][0] = *(const uint32_t*)(Q + (size_t)row0 * ldq + d0);
        qf[kt][1] = *(const uint32_t*)(Q + (size_t)row1 * ldq + d0);
        if (kt < 2) {
            qf[kt][2] = *(const uint32_t*)(Q + (size_t)row0 * ldq + d0 + 8);
            qf[kt][3] = *(const uint32_t*)(Q + (size_t)row1 * ldq + d0 + 8);
        } else {
            qf[kt][2] = 0; qf[kt][3] = 0;
        }
    }

    float o[5][4];
#pragma unroll
    for (int d = 0; d < 5; d++)
#pragma unroll
        for (int r = 0; r < 4; r++) o[d][r] = 0.f;
    float m_r0 = -1e30f, m_r1 = -1e30f, l_r0 = 0.f, l_r1 = 0.f;

    auto prefetch = [&](int st, int kt0) {
        for (int t = tid; t < 320; t += 256) {
            int r = t / 5, ch = t - r * 5;
            bool pred = (kt0 + r) < n_k;
            const __half* src = K + (size_t)(pred ? (kt0 + r) : 0) * ldk + h * DH + ch * 8;
            cp16(smem_u32(&Ks[st][r][ch * 4]), src, pred);
        }
        if (tid < 160) {
            int r = tid >> 2, ch = tid & 3;
            const __half* src = Vt + (size_t)(h * DH + r) * ldv + kt0 + ch * 16;
            cp16(smem_u32(&Vs[st][r][ch * 8]), src, true);
            src += 8;
            cp16(smem_u32(&Vs[st][r][ch * 8 + 4]), src, true);
        }
    };

    int nT = (n_k + 63) >> 6;
    prefetch(0, 0);
    cp_commit();
    for (int it = 0; it < nT; it++) {
        if (it + 1 < nT) prefetch((it + 1) & 1, (it + 1) * 64);
        cp_commit();
        cp_wait1();
        __syncthreads();
        int st = it & 1;
        int kcount = min(64, n_k - it * 64);

        float s[8][4];
#pragma unroll
        for (int nt = 0; nt < 8; nt++)
#pragma unroll
            for (int r = 0; r < 4; r++) s[nt][r] = 0.f;
#pragma unroll
        for (int kt = 0; kt < 3; kt++) {
#pragma unroll
            for (int nt = 0; nt < 8; nt++) {
                int kr = nt * 8 + grp;
                uint32_t b0 = Ks[st][kr][kt * 8 + t4];
                uint32_t b1 = (kt < 2) ? Ks[st][kr][kt * 8 + 4 + t4] : 0u;
                mma_f16(s[nt], qf[kt], b0, b1);
            }
        }
        if (kcount < 64) {
#pragma unroll
            for (int nt = 0; nt < 8; nt++) {
                int c0 = nt * 8 + 2 * t4;
                if (c0 >= kcount)     { s[nt][0] = -1e30f; s[nt][2] = -1e30f; }
                if (c0 + 1 >= kcount) { s[nt][1] = -1e30f; s[nt][3] = -1e30f; }
            }
        }

        float mx0 = m_r0, mx1 = m_r1;
#pragma unroll
        for (int nt = 0; nt < 8; nt++) {
            mx0 = fmaxf(mx0, fmaxf(s[nt][0], s[nt][1]));
            mx1 = fmaxf(mx1, fmaxf(s[nt][2], s[nt][3]));
        }
        mx0 = fmaxf(mx0, __shfl_xor_sync(0xffffffffu, mx0, 1));
        mx0 = fmaxf(mx0, __shfl_xor_sync(0xffffffffu, mx0, 2));
        mx1 = fmaxf(mx1, __shfl_xor_sync(0xffffffffu, mx1, 1));
        mx1 = fmaxf(mx1, __shfl_xor_sync(0xffffffffu, mx1, 2));
        float f0 = __expf(m_r0 - mx0), f1 = __expf(m_r1 - mx1);
        float p[8][4];
        float sum0 = 0.f, sum1 = 0.f;
#pragma unroll
        for (int nt = 0; nt < 8; nt++) {
            p[nt][0] = __expf(s[nt][0] - mx0);
            p[nt][1] = __expf(s[nt][1] - mx0);
            p[nt][2] = __expf(s[nt][2] - mx1);
            p[nt][3] = __expf(s[nt][3] - mx1);
            sum0 += p[nt][0] + p[nt][1];
            sum1 += p[nt][2] + p[nt][3];
        }
        sum0 += __shfl_xor_sync(0xffffffffu, sum0, 1);
        sum0 += __shfl_xor_sync(0xffffffffu, sum0, 2);
        sum1 += __shfl_xor_sync(0xffffffffu, sum1, 1);
        sum1 += __shfl_xor_sync(0xffffffffu, sum1, 2);
        l_r0 = l_r0 * f0 + sum0; m_r0 = mx0;
        l_r1 = l_r1 * f1 + sum1; m_r1 = mx1;

        uint32_t pa[4][4];
#pragma unroll
        for (int ks = 0; ks < 4; ks++) {
            pa[ks][0] = packh2(p[2 * ks][0],     p[2 * ks][1]);
            pa[ks][1] = packh2(p[2 * ks][2],     p[2 * ks][3]);
            pa[ks][2] = packh2(p[2 * ks + 1][0], p[2 * ks + 1][1]);
            pa[ks][3] = packh2(p[2 * ks + 1][2], p[2 * ks + 1][3]);
        }

#pragma unroll
        for (int d = 0; d < 5; d++) {
            o[d][0] *= f0; o[d][1] *= f0;
            o[d][2] *= f1; o[d][3] *= f1;
        }

#pragma unroll
        for (int d = 0; d < 5; d++) {
            int vr = d * 8 + grp;
#pragma unroll
            for (int ks = 0; ks < 4; ks++) {
                uint32_t b0 = Vs[st][vr][ks * 8 + t4];
                uint32_t b1 = Vs[st][vr][ks * 8 + 4 + t4];
                mma_f16(o[d], pa[ks], b0, b1);
            }
        }
        __syncthreads();
    }

    float inv0 = 1.f / l_r0, inv1 = 1.f / l_r1;
#pragma unroll
    for (int d = 0; d < 5; d++) {
        int c = h * DH + d * 8 + 2 * t4;
        O[(size_t)row0 * DMODEL + c]     = __float2half(o[d][0] * inv0);
        O[(size_t)row0 * DMODEL + c + 1] = __float2half(o[d][1] * inv0);
        O[(size_t)row1 * DMODEL + c]     = __float2half(o[d][2] * inv1);
        O[(size_t)row1 * DMODEL + c + 1] = __float2half(o[d][3] * inv1);
    }
}

// ---------------- host launch ----------------
extern "C" void kernel_launch(void* const* d_in, const int* in_sizes, int n_in,
                              void* d_out, int out_size) {
    const float* x      = (const float*)d_in[0];
    const float* ctx    = (const float*)d_in[1];
    const float* gn_w   = (const float*)d_in[2];
    const float* gn_b   = (const float*)d_in[3];
    const float* pin_w  = (const float*)d_in[4];
    const float* pin_b  = (const float*)d_in[5];
    const float* ln1_w  = (const float*)d_in[6];
    const float* ln1_b  = (const float*)d_in[7];
    const float* q1     = (const float*)d_in[8];
    const float* k1     = (const float*)d_in[9];
    const float* v1     = (const float*)d_in[10];
    const float* o1_w   = (const float*)d_in[11];
    const float* o1_b   = (const float*)d_in[12];
    const float* ln2_w  = (const float*)d_in[13];
    const float* ln2_b  = (const float*)d_in[14];
    const float* q2     = (const float*)d_in[15];
    const float* k2     = (const float*)d_in[16];
    const float* v2     = (const float*)d_in[17];
    const float* o2_w   = (const float*)d_in[18];
    const float* o2_b   = (const float*)d_in[19];
    const float* ln3_w  = (const float*)d_in[20];
    const float* ln3_b  = (const float*)d_in[21];
    const float* ff1_w  = (const float*)d_in[22];
    const float* ff1_b  = (const float*)d_in[23];
    const float* ff2_w  = (const float*)d_in[24];
    const float* ff2_b  = (const float*)d_in[25];
    const float* pout_w = (const float*)d_in[26];
    const float* pout_b = (const float*)d_in[27];
    float* out = (float*)d_out;

    float *bp, *h, *bff1;
    __half *x16, *ln16, *qk16, *vt16, *q216, *k216, *vt2c16, *ao16, *fa16, *hh16, *ctx16;
    __half *wpin16, *wqk16, *wv116, *wq216, *wk216, *wv216, *wo116, *wo216;
    __half *wff116, *wff216, *wpo16;
    cudaGetSymbolAddress((void**)&bp, g_bp);
    cudaGetSymbolAddress((void**)&h, g_h);
    cudaGetSymbolAddress((void**)&bff1, g_bff1);
    cudaGetSymbolAddress((void**)&x16, g_x16);
    cudaGetSymbolAddress((void**)&ln16, g_ln16);
    cudaGetSymbolAddress((void**)&qk16, g_qk16);
    cudaGetSymbolAddress((void**)&vt16, g_vt16);
    cudaGetSymbolAddress((void**)&q216, g_q216);
    cudaGetSymbolAddress((void**)&k216, g_k216);
    cudaGetSymbolAddress((void**)&vt2c16, g_vt2c16);
    cudaGetSymbolAddress((void**)&ao16, g_ao16);
    cudaGetSymbolAddress((void**)&fa16, g_fa16);
    cudaGetSymbolAddress((void**)&hh16, g_hh16);
    cudaGetSymbolAddress((void**)&ctx16, g_ctx16);
    cudaGetSymbolAddress((void**)&wpin16, g_wpin16);
    cudaGetSymbolAddress((void**)&wqk16, g_wqk16);
    cudaGetSymbolAddress((void**)&wv116, g_wv116);
    cudaGetSymbolAddress((void**)&wq216, g_wq216);
    cudaGetSymbolAddress((void**)&wk216, g_wk216);
    cudaGetSymbolAddress((void**)&wv216, g_wv216);
    cudaGetSymbolAddress((void**)&wo116, g_wo116);
    cudaGetSymbolAddress((void**)&wo216, g_wo216);
    cudaGetSymbolAddress((void**)&wff116, g_wff116);
    cudaGetSymbolAddress((void**)&wff216, g_wff216);
    cudaGetSymbolAddress((void**)&wpo16, g_wpo16);

    // prep: 3 launches total
    gn_stats_kernel<<<32, 256>>>(x, gn_w, gn_b);
    fold_pin_kernel<<<DMODEL, 64>>>(pin_w, pin_b);
    prep_kernel<<<PREP_BLOCKS, 256>>>(x, q1, k1, v1, o1_w, q2, k2, v2, o2_w,
                                      ff1_w, ff1_b, ff2_w, pout_w, ctx);

    // pin projection
    gemm_fp16<<<dim3(32, 5), 256>>>(x16, wpin16, h, nullptr, bp, nullptr,
        NTOK, DMODEL, DMODEL, DMODEL, 1, 0);

    // self-attention block
    ln_kernel<<<NTOK / 8, 256>>>(h, ln1_w, ln1_b, ln16);
    gemm_fp16<<<dim3(32, 10), 256>>>(ln16, wqk16, nullptr, qk16, nullptr, nullptr,
        NTOK, 2 * DMODEL, DMODEL, 2 * DMODEL, 1, 0);
    gemm_fp16<<<dim3(32, 5), 256>>>(ln16, wv116, nullptr, vt16, nullptr, nullptr,
        NTOK, DMODEL, DMODEL, 1, NTOK, 0);   // V^T [d][tok]
    attn16<<<dim3(NTOK / 128, HEADS), 256>>>(
        qk16, 2 * DMODEL, qk16 + DMODEL, 2 * DMODEL, vt16, NTOK, ao16, NTOK);
    gemm_fp16<<<dim3(32, 5), 256>>>(ao16, wo116, h, nullptr, o1_b, h,
        NTOK, DMODEL, DMODEL, DMODEL, 1, 0);

    // cross-attention block
    ln_kernel<<<NTOK / 8, 256>>>(h, ln2_w, ln2_b, ln16);
    gemm_fp16<<<dim3(32, 5), 256>>>(ln16, wq216, nullptr, q216, nullptr, nullptr,
        NTOK, DMODEL, DMODEL, DMODEL, 1, 0);
    gemm_fp16<<<dim3(1, 5), 256>>>(ctx16, wk216, nullptr, k216, nullptr, nullptr,
        CTXN, DMODEL, CTXD, DMODEL, 1, 0);
    gemm_fp16<<<dim3(1, 5), 256>>>(ctx16, wv216, nullptr, vt2c16, nullptr, nullptr,
        CTXN, DMODEL, CTXD, 1, CTXP, 0);     // V^T [d][key], pad stays zero
    attn16<<<dim3(NTOK / 128, HEADS), 256>>>(
        q216, DMODEL, k216, DMODEL, vt2c16, CTXP, ao16, CTXN);
    gemm_fp16<<<dim3(32, 5), 256>>>(ao16, wo216, h, nullptr, o2_b, h,
        NTOK, DMODEL, DMODEL, DMODEL, 1, 0);

    // GEGLU FF block
    ln_kernel<<<NTOK / 8, 256>>>(h, ln3_w, ln3_b, ln16);
    gemm_fp16<<<dim3(32, 40), 256>>>(ln16, wff116, nullptr, fa16, bff1, nullptr,
        NTOK, 2 * FFI, DMODEL, FFI, 1, 1);
    gemm_fp16<<<dim3(32, 5), 256>>>(fa16, wff216, h, hh16, ff2_b, h,
        NTOK, DMODEL, FFI, DMODEL, 1, 0);

    // output projection (transposed store) + input residual
    gemm_fp16<<<dim3(32, 5), 256>>>(hh16, wpo16, out, nullptr, pout_b, x,
        NTOK, DMODEL, DMODEL, 1, NTOK, 0);
}

// round 12
// speedup vs baseline: 1.5325x; 1.0797x over previous
#include <cuda_runtime.h>
#include <cuda_fp16.h>
#include <math.h>
#include <stdint.h>

#define NTOK 4096
#define DMODEL 320
#define FFI 1280
#define HEADS 8
#define DH 40
#define CTXN 77
#define CTXD 768
#define CTXP 128
#define QSCALE 0.15811388300841897f

// ---------------- scratch ----------------
__device__ float g_s[DMODEL];
__device__ float g_t[DMODEL];
__device__ float g_bp[DMODEL];
__device__ float g_h[NTOK * DMODEL];
__device__ float g_bff1[2 * FFI];

// fp16 activations
__device__ __align__(16) __half g_x16[NTOK * DMODEL];
__device__ __align__(16) __half g_ln16[NTOK * DMODEL];
__device__ __align__(16) __half g_qk16[NTOK * 2 * DMODEL];
__device__ __align__(16) __half g_vt16[DMODEL * NTOK];
__device__ __align__(16) __half g_q216[NTOK * DMODEL];
__device__ __align__(16) __half g_k216[CTXN * DMODEL];
__device__ __align__(16) __half g_vt2c16[DMODEL * CTXP];
__device__ __align__(16) __half g_ao16[NTOK * DMODEL];
__device__ __align__(16) __half g_fa16[NTOK * FFI];
__device__ __align__(16) __half g_hh16[NTOK * DMODEL];
__device__ __align__(16) __half g_ctx16[CTXN * CTXD];
// fp16 weights, [N][K]
__device__ __align__(16) __half g_wpin16[DMODEL * DMODEL];
__device__ __align__(16) __half g_wqk16[2 * DMODEL * DMODEL];
__device__ __align__(16) __half g_wv116[DMODEL * DMODEL];
__device__ __align__(16) __half g_wq216[DMODEL * DMODEL];
__device__ __align__(16) __half g_wk216[DMODEL * CTXD];
__device__ __align__(16) __half g_wv216[DMODEL * CTXD];
__device__ __align__(16) __half g_wo116[DMODEL * DMODEL];
__device__ __align__(16) __half g_wo216[DMODEL * DMODEL];
__device__ __align__(16) __half g_wff116[2 * FFI * DMODEL];
__device__ __align__(16) __half g_wff216[DMODEL * FFI];
__device__ __align__(16) __half g_wpo16[DMODEL * DMODEL];

// ---------------- helpers ----------------
__device__ __forceinline__ uint32_t smem_u32(const void* p) {
    return (uint32_t)__cvta_generic_to_shared(p);
}
__device__ __forceinline__ void cp16(uint32_t dst, const void* src, bool pred) {
    int sz = pred ? 16 : 0;
    asm volatile("cp.async.cg.shared.global [%0], [%1], 16, %2;" :: "r"(dst), "l"(src), "r"(sz));
}
__device__ __forceinline__ void cp_commit() { asm volatile("cp.async.commit_group;"); }
__device__ __forceinline__ void cp_wait1() { asm volatile("cp.async.wait_group 1;"); }

__device__ __forceinline__ void mma_f16(float* d, const uint32_t* a, uint32_t b0, uint32_t b1) {
    asm volatile(
        "mma.sync.aligned.m16n8k16.row.col.f32.f16.f16.f32 "
        "{%0,%1,%2,%3}, {%4,%5,%6,%7}, {%8,%9}, {%0,%1,%2,%3};"
        : "+f"(d[0]), "+f"(d[1]), "+f"(d[2]), "+f"(d[3])
        : "r"(a[0]), "r"(a[1]), "r"(a[2]), "r"(a[3]), "r"(b0), "r"(b1));
}
__device__ __forceinline__ float gelu_f(float g) {
    return 0.5f * g * (1.f + erff(g * 0.70710678118654752f));
}
__device__ __forceinline__ uint32_t packh2(float a, float b) {
    __half2 p = __floats2half2_rn(a, b);
    return *(uint32_t*)&p;
}

// ---------------- GroupNorm stats ----------------
__global__ void gn_stats_kernel(const float* __restrict__ x,
                                const float* __restrict__ gn_w,
                                const float* __restrict__ gn_b) {
    int g = blockIdx.x;
    int tid = threadIdx.x;
    const float* base = x + (size_t)g * 10 * 4096;
    float s = 0.f, ss = 0.f;
    for (int i = tid; i < 40960; i += 256) {
        float v = base[i];
        s += v; ss += v * v;
    }
    __shared__ float r1[256], r2[256];
    r1[tid] = s; r2[tid] = ss;
    __syncthreads();
    for (int off = 128; off > 0; off >>= 1) {
        if (tid < off) { r1[tid] += r1[tid + off]; r2[tid] += r2[tid + off]; }
        __syncthreads();
    }
    if (tid < 10) {
        float mu = r1[0] / 40960.f;
        float var = r2[0] / 40960.f - mu * mu;
        float inv = rsqrtf(var + 1e-6f);
        int c = g * 10 + tid;
        float w = gn_w[c];
        g_s[c] = inv * w;
        g_t[c] = gn_b[c] - mu * inv * w;
    }
}

__global__ void fold_pin_kernel(const float* __restrict__ pin_w,
                                const float* __restrict__ pin_b) {
    int o = blockIdx.x;
    int tid = threadIdx.x;
    float acc = 0.f;
    for (int c = tid; c < DMODEL; c += 64) {
        float w = pin_w[o * DMODEL + c];
        g_wpin16[o * DMODEL + c] = __float2half(w * g_s[c]);
        acc += w * g_t[c];
    }
    __shared__ float r[64];
    r[tid] = acc;
    __syncthreads();
    for (int off = 32; off > 0; off >>= 1) {
        if (tid < off) r[tid] += r[tid + off];
        __syncthreads();
    }
    if (tid == 0) g_bp[o] = pin_b[o] + r[0];
}

// ---------------- unified weight prep ----------------
__device__ __forceinline__ void tr_tile(const float* __restrict__ in, __half* __restrict__ out,
                                        int R, int Cc, int bx, int by, float scale) {
    __shared__ float tile[32][33];
    int tx = threadIdx.x & 31, ty = threadIdx.x >> 5;
    int c0 = bx * 32, r0 = by * 32;
#pragma unroll
    for (int i = 0; i < 4; i++) {
        int r = r0 + ty + i * 8, c = c0 + tx;
        if (r < R && c < Cc) tile[ty + i * 8][tx] = in[(size_t)r * Cc + c];
    }
    __syncthreads();
#pragma unroll
    for (int i = 0; i < 4; i++) {
        int c = c0 + ty + i * 8, r = r0 + tx;
        if (c < Cc && r < R) out[(size_t)c * R + r] = __float2half(tile[tx][ty + i * 8] * scale);
    }
}

#define PREP_BLOCKS 3728
__global__ __launch_bounds__(256) void prep_kernel(
    const float* __restrict__ x,
    const float* __restrict__ q1, const float* __restrict__ k1,
    const float* __restrict__ v1, const float* __restrict__ o1w,
    const float* __restrict__ q2, const float* __restrict__ k2,
    const float* __restrict__ v2, const float* __restrict__ o2w,
    const float* __restrict__ ff1w, const float* __restrict__ ff1b,
    const float* __restrict__ ff2w, const float* __restrict__ poutw,
    const float* __restrict__ ctx) {
    int b = blockIdx.x;
    int tid = threadIdx.x;
    if (b < 1280) { tr_tile(x, g_x16, DMODEL, NTOK, b % 128, b / 128, 1.f); return; }
    b -= 1280;
    if (b < 100) { tr_tile(q1, g_wqk16, DMODEL, DMODEL, b % 10, b / 10, QSCALE); return; }
    b -= 100;
    if (b < 100) { tr_tile(k1, g_wqk16 + DMODEL * DMODEL, DMODEL, DMODEL, b % 10, b / 10, 1.f); return; }
    b -= 100;
    if (b < 100) { tr_tile(v1, g_wv116, DMODEL, DMODEL, b % 10, b / 10, 1.f); return; }
    b -= 100;
    if (b < 100) { tr_tile(o1w, g_wo116, DMODEL, DMODEL, b % 10, b / 10, 1.f); return; }
    b -= 100;
    if (b < 100) { tr_tile(q2, g_wq216, DMODEL, DMODEL, b % 10, b / 10, QSCALE); return; }
    b -= 100;
    if (b < 240) { tr_tile(k2, g_wk216, CTXD, DMODEL, b % 10, b / 10, 1.f); return; }
    b -= 240;
    if (b < 240) { tr_tile(v2, g_wv216, CTXD, DMODEL, b % 10, b / 10, 1.f); return; }
    b -= 240;
    if (b < 100) { tr_tile(o2w, g_wo216, DMODEL, DMODEL, b % 10, b / 10, 1.f); return; }
    b -= 100;
    if (b < 400) { tr_tile(ff2w, g_wff216, FFI, DMODEL, b % 10, b / 10, 1.f); return; }
    b -= 400;
    if (b < 800) {
        __shared__ float tile[32][33];
        int tx = tid & 31, ty = tid >> 5;
        int bx = b % 80, by = b / 80;
        int c0 = bx * 32, r0 = by * 32;
#pragma unroll
        for (int i = 0; i < 4; i++) {
            int k = r0 + ty + i * 8, n = c0 + tx;
            int src = (n & 1) ? (FFI + (n >> 1)) : (n >> 1);
            tile[ty + i * 8][tx] = ff1w[(size_t)k * 2 * FFI + src];
        }
        __syncthreads();
#pragma unroll
        for (int i = 0; i < 4; i++) {
            int n = c0 + ty + i * 8, k = r0 + tx;
            g_wff116[(size_t)n * DMODEL + k] = __float2half(tile[tx][ty + i * 8]);
        }
        return;
    }
    b -= 800;
    if (b < 100) {
        int i0 = b * 1024 + tid * 4;
#pragma unroll
        for (int i = 0; i < 4; i++) g_wpo16[i0 + i] = __float2half(poutw[i0 + i]);
        return;
    }
    b -= 100;
    if (b < 58) {
        int i0 = b * 1024 + tid * 4;
#pragma unroll
        for (int i = 0; i < 4; i++) {
            int idx = i0 + i;
            if (idx < CTXN * CTXD) g_ctx16[idx] = __float2half(ctx[idx]);
        }
        return;
    }
    b -= 58;
    int idx = b * 256 + tid;
    int j = idx >> 1;
    g_bff1[idx] = (idx & 1) ? ff1b[FFI + j] : ff1b[j];
}

// ---------------- fp16 tensor-core GEMM (m16n8k16), 64x64 tile, 128 thr ----------------
__global__ __launch_bounds__(128) void gemm_fp16(
    const __half* __restrict__ A, const __half* __restrict__ B,
    float* __restrict__ C, __half* __restrict__ Ch,
    const float* __restrict__ bias, const float* __restrict__ resid,
    int M, int N, int K, int Csm, int Csn, int geglu) {
    __shared__ __align__(16) uint32_t As[2][64][12];
    __shared__ __align__(16) uint32_t Bs[2][64][12];
    int tid = threadIdx.x;
    int warp = tid >> 5, lane = tid & 31;
    int grp = lane >> 2, t4 = lane & 3;
    int m0 = blockIdx.x * 64, n0 = blockIdx.y * 64;
    int wm = (warp >> 1) * 32, wn = (warp & 1) * 32;

    float acc[2][4][4];
#pragma unroll
    for (int mi = 0; mi < 2; mi++)
#pragma unroll
        for (int ni = 0; ni < 4; ni++)
#pragma unroll
            for (int r = 0; r < 4; r++) acc[mi][ni][r] = 0.f;

    int ar = tid >> 1, apart = tid & 1;
    bool ap = (m0 + ar) < M;
    const __half* asrc = A + (size_t)(ap ? (m0 + ar) : 0) * K + apart * 8;
    const __half* bsrc = B + (size_t)(n0 + ar) * K + apart * 8;

    auto prefetch = [&](int st, int k0) {
        cp16(smem_u32(&As[st][ar][apart * 4]), asrc + k0, ap);
        cp16(smem_u32(&Bs[st][ar][apart * 4]), bsrc + k0, true);
    };

    int nK = K >> 4;
    prefetch(0, 0);
    cp_commit();
    for (int kt = 0; kt < nK; kt++) {
        if (kt + 1 < nK) prefetch((kt + 1) & 1, (kt + 1) << 4);
        cp_commit();
        cp_wait1();
        __syncthreads();
        int st = kt & 1;
        uint32_t af[2][4];
#pragma unroll
        for (int mi = 0; mi < 2; mi++) {
            int rm = wm + mi * 16;
            af[mi][0] = As[st][rm + grp][t4];
            af[mi][1] = As[st][rm + grp + 8][t4];
            af[mi][2] = As[st][rm + grp][t4 + 4];
            af[mi][3] = As[st][rm + grp + 8][t4 + 4];
        }
        uint32_t bf[4][2];
#pragma unroll
        for (int ni = 0; ni < 4; ni++) {
            int cn = wn + ni * 8 + grp;
            bf[ni][0] = Bs[st][cn][t4];
            bf[ni][1] = Bs[st][cn][t4 + 4];
        }
#pragma unroll
        for (int mi = 0; mi < 2; mi++)
#pragma unroll
            for (int ni = 0; ni < 4; ni++)
                mma_f16(acc[mi][ni], af[mi], bf[ni][0], bf[ni][1]);
        __syncthreads();
    }
#pragma unroll
    for (int mi = 0; mi < 2; mi++) {
        int r0r = m0 + wm + mi * 16 + grp;
        int r1r = r0r + 8;
#pragma unroll
        for (int ni = 0; ni < 4; ni++) {
            int c = n0 + wn + ni * 8 + t4 * 2;
            float b0 = bias ? bias[c] : 0.f;
            float b1 = bias ? bias[c + 1] : 0.f;
            if (geglu) {
                int co = c >> 1;
                if (r0r < M)
                    Ch[(size_t)r0r * Csm + co] =
                        __float2half((acc[mi][ni][0] + b0) * gelu_f(acc[mi][ni][1] + b1));
                if (r1r < M)
                    Ch[(size_t)r1r * Csm + co] =
                        __float2half((acc[mi][ni][2] + b0) * gelu_f(acc[mi][ni][3] + b1));
            } else {
                if (r0r < M) {
                    size_t o0 = (size_t)r0r * Csm + (size_t)c * Csn;
                    size_t o1 = o0 + Csn;
                    float v0 = acc[mi][ni][0] + b0;
                    float v1 = acc[mi][ni][1] + b1;
                    if (resid) { v0 += resid[o0]; v1 += resid[o1]; }
                    if (C) { C[o0] = v0; C[o1] = v1; }
                    if (Ch) { Ch[o0] = __float2half(v0); Ch[o1] = __float2half(v1); }
                }
                if (r1r < M) {
                    size_t o0 = (size_t)r1r * Csm + (size_t)c * Csn;
                    size_t o1 = o0 + Csn;
                    float v0 = acc[mi][ni][2] + b0;
                    float v1 = acc[mi][ni][3] + b1;
                    if (resid) { v0 += resid[o0]; v1 += resid[o1]; }
                    if (C) { C[o0] = v0; C[o1] = v1; }
                    if (Ch) { Ch[o0] = __float2half(v0); Ch[o1] = __float2half(v1); }
                }
            }
        }
    }
}

// ---------------- LayerNorm: warp per row, fp16 out ----------------
__global__ __launch_bounds__(256) void ln_kernel(const float* __restrict__ in,
                                                 const float* __restrict__ w,
                                                 const float* __restrict__ b,
                                                 __half* __restrict__ out) {
    int warp = threadIdx.x >> 5, lane = threadIdx.x & 31;
    int m = blockIdx.x * 8 + warp;
    const float* row = in + (size_t)m * DMODEL;
    float vals[10];
    float s = 0.f, ss = 0.f;
#pragma unroll
    for (int i = 0; i < 10; i++) {
        float v = row[lane + i * 32];
        vals[i] = v;
        s += v; ss += v * v;
    }
#pragma unroll
    for (int off = 16; off > 0; off >>= 1) {
        s += __shfl_xor_sync(0xffffffffu, s, off);
        ss += __shfl_xor_sync(0xffffffffu, ss, off);
    }
    float mu = s / (float)DMODEL;
    float var = ss / (float)DMODEL - mu * mu;
    float rs = rsqrtf(var + 1e-5f);
#pragma unroll
    for (int i = 0; i < 10; i++) {
        int c = lane + i * 32;
        out[(size_t)m * DMODEL + c] = __float2half((vals[i] - mu) * rs * w[c] + b[c]);
    }
}

// ---------------- fp16 flash attention ----------------
__global__ __launch_bounds__(256) void attn16(
    const __half* __restrict__ Q, int ldq,
    const __half* __restrict__ K, int ldk,
    const __half* __restrict__ Vt, int ldv,
    __half* __restrict__ O, int n_k) {
    __shared__ __align__(16) uint32_t Ks[2][64][20];
    __shared__ __align__(16) uint32_t Vs[2][40][36];

    int h = blockIdx.y;
    int m0 = blockIdx.x * 128;
    int tid = threadIdx.x;
    int warp = tid >> 5, lane = tid & 31;
    int grp = lane >> 2, t4 = lane & 3;
    int wm = warp * 16;
    int row0 = m0 + wm + grp, row1 = row0 + 8;

    uint32_t qf[3][4];
#pragma unroll
    for (int kt = 0; kt < 3; kt++) {
        int d0 = h * DH + kt * 16 + 2 * t4;
        qf[kt][0] = *(const uint32_t*)(Q + (size_t)row0 * ldq + d0);
        qf[kt][1] = *(const uint32_t*)(Q + (size_t)row1 * ldq + d0);
        if (kt < 2) {
            qf[kt][2] = *(const uint32_t*)(Q + (size_t)row0 * ldq + d0 + 8);
            qf[kt][3] = *(const uint32_t*)(Q + (size_t)row1 * ldq + d0 + 8);
        } else {
            qf[kt][2] = 0; qf[kt][3] = 0;
        }
    }

    float o[5][4];
#pragma unroll
    for (int d = 0; d < 5; d++)
#pragma unroll
        for (int r = 0; r < 4; r++) o[d][r] = 0.f;
    float m_r0 = -1e30f, m_r1 = -1e30f, l_r0 = 0.f, l_r1 = 0.f;

    auto prefetch = [&](int st, int kt0) {
        for (int t = tid; t < 320; t += 256) {
            int r = t / 5, ch = t - r * 5;
            bool pred = (kt0 + r) < n_k;
            const __half* src = K + (size_t)(pred ? (kt0 + r) : 0) * ldk + h * DH + ch * 8;
            cp16(smem_u32(&Ks[st][r][ch * 4]), src, pred);
        }
        if (tid < 160) {
            int r = tid >> 2, ch = tid & 3;
            const __half* src = Vt + (size_t)(h * DH + r) * ldv + kt0 + ch * 16;
            cp16(smem_u32(&Vs[st][r][ch * 8]), src, true);
            src += 8;
            cp16(smem_u32(&Vs[st][r][ch * 8 + 4]), src, true);
        }
    };

    int nT = (n_k + 63) >> 6;
    prefetch(0, 0);
    cp_commit();
    for (int it = 0; it < nT; it++) {
        if (it + 1 < nT) prefetch((it + 1) & 1, (it + 1) * 64);
        cp_commit();
        cp_wait1();
        __syncthreads();
        int st = it & 1;
        int kcount = min(64, n_k - it * 64);

        float s[8][4];
#pragma unroll
        for (int nt = 0; nt < 8; nt++)
#pragma unroll
            for (int r = 0; r < 4; r++) s[nt][r] = 0.f;
#pragma unroll
        for (int kt = 0; kt < 3; kt++) {
#pragma unroll
            for (int nt = 0; nt < 8; nt++) {
                int kr = nt * 8 + grp;
                uint32_t b0 = Ks[st][kr][kt * 8 + t4];
                uint32_t b1 = (kt < 2) ? Ks[st][kr][kt * 8 + 4 + t4] : 0u;
                mma_f16(s[nt], qf[kt], b0, b1);
            }
        }
        if (kcount < 64) {
#pragma unroll
            for (int nt = 0; nt < 8; nt++) {
                int c0 = nt * 8 + 2 * t4;
                if (c0 >= kcount)     { s[nt][0] = -1e30f; s[nt][2] = -1e30f; }
                if (c0 + 1 >= kcount) { s[nt][1] = -1e30f; s[nt][3] = -1e30f; }
            }
        }

        float mx0 = m_r0, mx1 = m_r1;
#pragma unroll
        for (int nt = 0; nt < 8; nt++) {
            mx0 = fmaxf(mx0, fmaxf(s[nt][0], s[nt][1]));
            mx1 = fmaxf(mx1, fmaxf(s[nt][2], s[nt][3]));
        }
        mx0 = fmaxf(mx0, __shfl_xor_sync(0xffffffffu, mx0, 1));
        mx0 = fmaxf(mx0, __shfl_xor_sync(0xffffffffu, mx0, 2));
        mx1 = fmaxf(mx1, __shfl_xor_sync(0xffffffffu, mx1, 1));
        mx1 = fmaxf(mx1, __shfl_xor_sync(0xffffffffu, mx1, 2));
        float f0 = __expf(m_r0 - mx0), f1 = __expf(m_r1 - mx1);
        float p[8][4];
        float sum0 = 0.f, sum1 = 0.f;
#pragma unroll
        for (int nt = 0; nt < 8; nt++) {
            p[nt][0] = __expf(s[nt][0] - mx0);
            p[nt][1] = __expf(s[nt][1] - mx0);
            p[nt][2] = __expf(s[nt][2] - mx1);
            p[nt][3] = __expf(s[nt][3] - mx1);
            sum0 += p[nt][0] + p[nt][1];
            sum1 += p[nt][2] + p[nt][3];
        }
        sum0 += __shfl_xor_sync(0xffffffffu, sum0, 1);
        sum0 += __shfl_xor_sync(0xffffffffu, sum0, 2);
        sum1 += __shfl_xor_sync(0xffffffffu, sum1, 1);
        sum1 += __shfl_xor_sync(0xffffffffu, sum1, 2);
        l_r0 = l_r0 * f0 + sum0; m_r0 = mx0;
        l_r1 = l_r1 * f1 + sum1; m_r1 = mx1;

        uint32_t pa[4][4];
#pragma unroll
        for (int ks = 0; ks < 4; ks++) {
            pa[ks][0] = packh2(p[2 * ks][0],     p[2 * ks][1]);
            pa[ks][1] = packh2(p[2 * ks][2],     p[2 * ks][3]);
            pa[ks][2] = packh2(p[2 * ks + 1][0], p[2 * ks + 1][1]);
            pa[ks][3] = packh2(p[2 * ks + 1][2], p[2 * ks + 1][3]);
        }

#pragma unroll
        for (int d = 0; d < 5; d++) {
            o[d][0] *= f0; o[d][1] *= f0;
            o[d][2] *= f1; o[d][3] *= f1;
        }

#pragma unroll
        for (int d = 0; d < 5; d++) {
            int vr = d * 8 + grp;
#pragma unroll
            for (int ks = 0; ks < 4; ks++) {
                uint32_t b0 = Vs[st][vr][ks * 8 + t4];
                uint32_t b1 = Vs[st][vr][ks * 8 + 4 + t4];
                mma_f16(o[d], pa[ks], b0, b1);
            }
        }
        __syncthreads();
    }

    float inv0 = 1.f / l_r0, inv1 = 1.f / l_r1;
#pragma unroll
    for (int d = 0; d < 5; d++) {
        int c = h * DH + d * 8 + 2 * t4;
        O[(size_t)row0 * DMODEL + c]     = __float2half(o[d][0] * inv0);
        O[(size_t)row0 * DMODEL + c + 1] = __float2half(o[d][1] * inv0);
        O[(size_t)row1 * DMODEL + c]     = __float2half(o[d][2] * inv1);
        O[(size_t)row1 * DMODEL + c + 1] = __float2half(o[d][3] * inv1);
    }
}

// ---------------- host launch ----------------
extern "C" void kernel_launch(void* const* d_in, const int* in_sizes, int n_in,
                              void* d_out, int out_size) {
    const float* x      = (const float*)d_in[0];
    const float* ctx    = (const float*)d_in[1];
    const float* gn_w   = (const float*)d_in[2];
    const float* gn_b   = (const float*)d_in[3];
    const float* pin_w  = (const float*)d_in[4];
    const float* pin_b  = (const float*)d_in[5];
    const float* ln1_w  = (const float*)d_in[6];
    const float* ln1_b  = (const float*)d_in[7];
    const float* q1     = (const float*)d_in[8];
    const float* k1     = (const float*)d_in[9];
    const float* v1     = (const float*)d_in[10];
    const float* o1_w   = (const float*)d_in[11];
    const float* o1_b   = (const float*)d_in[12];
    const float* ln2_w  = (const float*)d_in[13];
    const float* ln2_b  = (const float*)d_in[14];
    const float* q2     = (const float*)d_in[15];
    const float* k2     = (const float*)d_in[16];
    const float* v2     = (const float*)d_in[17];
    const float* o2_w   = (const float*)d_in[18];
    const float* o2_b   = (const float*)d_in[19];
    const float* ln3_w  = (const float*)d_in[20];
    const float* ln3_b  = (const float*)d_in[21];
    const float* ff1_w  = (const float*)d_in[22];
    const float* ff1_b  = (const float*)d_in[23];
    const float* ff2_w  = (const float*)d_in[24];
    const float* ff2_b  = (const float*)d_in[25];
    const float* pout_w = (const float*)d_in[26];
    const float* pout_b = (const float*)d_in[27];
    float* out = (float*)d_out;

    float *bp, *h, *bff1;
    __half *x16, *ln16, *qk16, *vt16, *q216, *k216, *vt2c16, *ao16, *fa16, *hh16, *ctx16;
    __half *wpin16, *wqk16, *wv116, *wq216, *wk216, *wv216, *wo116, *wo216;
    __half *wff116, *wff216, *wpo16;
    cudaGetSymbolAddress((void**)&bp, g_bp);
    cudaGetSymbolAddress((void**)&h, g_h);
    cudaGetSymbolAddress((void**)&bff1, g_bff1);
    cudaGetSymbolAddress((void**)&x16, g_x16);
    cudaGetSymbolAddress((void**)&ln16, g_ln16);
    cudaGetSymbolAddress((void**)&qk16, g_qk16);
    cudaGetSymbolAddress((void**)&vt16, g_vt16);
    cudaGetSymbolAddress((void**)&q216, g_q216);
    cudaGetSymbolAddress((void**)&k216, g_k216);
    cudaGetSymbolAddress((void**)&vt2c16, g_vt2c16);
    cudaGetSymbolAddress((void**)&ao16, g_ao16);
    cudaGetSymbolAddress((void**)&fa16, g_fa16);
    cudaGetSymbolAddress((void**)&hh16, g_hh16);
    cudaGetSymbolAddress((void**)&ctx16, g_ctx16);
    cudaGetSymbolAddress((void**)&wpin16, g_wpin16);
    cudaGetSymbolAddress((void**)&wqk16, g_wqk16);
    cudaGetSymbolAddress((void**)&wv116, g_wv116);
    cudaGetSymbolAddress((void**)&wq216, g_wq216);
    cudaGetSymbolAddress((void**)&wk216, g_wk216);
    cudaGetSymbolAddress((void**)&wv216, g_wv216);
    cudaGetSymbolAddress((void**)&wo116, g_wo116);
    cudaGetSymbolAddress((void**)&wo216, g_wo216);
    cudaGetSymbolAddress((void**)&wff116, g_wff116);
    cudaGetSymbolAddress((void**)&wff216, g_wff216);
    cudaGetSymbolAddress((void**)&wpo16, g_wpo16);

    // prep: 3 launches total
    gn_stats_kernel<<<32, 256>>>(x, gn_w, gn_b);
    fold_pin_kernel<<<DMODEL, 64>>>(pin_w, pin_b);
    prep_kernel<<<PREP_BLOCKS, 256>>>(x, q1, k1, v1, o1_w, q2, k2, v2, o2_w,
                                      ff1_w, ff1_b, ff2_w, pout_w, ctx);

    // pin projection
    gemm_fp16<<<dim3(64, 5), 128>>>(x16, wpin16, h, nullptr, bp, nullptr,
        NTOK, DMODEL, DMODEL, DMODEL, 1, 0);

    // self-attention block
    ln_kernel<<<NTOK / 8, 256>>>(h, ln1_w, ln1_b, ln16);
    gemm_fp16<<<dim3(64, 10), 128>>>(ln16, wqk16, nullptr, qk16, nullptr, nullptr,
        NTOK, 2 * DMODEL, DMODEL, 2 * DMODEL, 1, 0);
    gemm_fp16<<<dim3(64, 5), 128>>>(ln16, wv116, nullptr, vt16, nullptr, nullptr,
        NTOK, DMODEL, DMODEL, 1, NTOK, 0);   // V^T [d][tok]
    attn16<<<dim3(NTOK / 128, HEADS), 256>>>(
        qk16, 2 * DMODEL, qk16 + DMODEL, 2 * DMODEL, vt16, NTOK, ao16, NTOK);
    gemm_fp16<<<dim3(64, 5), 128>>>(ao16, wo116, h, nullptr, o1_b, h,
        NTOK, DMODEL, DMODEL, DMODEL, 1, 0);

    // cross-attention block
    ln_kernel<<<NTOK / 8, 256>>>(h, ln2_w, ln2_b, ln16);
    gemm_fp16<<<dim3(64, 5), 128>>>(ln16, wq216, nullptr, q216, nullptr, nullptr,
        NTOK, DMODEL, DMODEL, DMODEL, 1, 0);
    gemm_fp16<<<dim3(2, 5), 128>>>(ctx16, wk216, nullptr, k216, nullptr, nullptr,
        CTXN, DMODEL, CTXD, DMODEL, 1, 0);
    gemm_fp16<<<dim3(2, 5), 128>>>(ctx16, wv216, nullptr, vt2c16, nullptr, nullptr,
        CTXN, DMODEL, CTXD, 1, CTXP, 0);     // V^T [d][key], pad stays zero
    attn16<<<dim3(NTOK / 128, HEADS), 256>>>(
        q216, DMODEL, k216, DMODEL, vt2c16, CTXP, ao16, CTXN);
    gemm_fp16<<<dim3(64, 5), 128>>>(ao16, wo216, h, nullptr, o2_b, h,
        NTOK, DMODEL, DMODEL, DMODEL, 1, 0);

    // GEGLU FF block
    ln_kernel<<<NTOK / 8, 256>>>(h, ln3_w, ln3_b, ln16);
    gemm_fp16<<<dim3(64, 40), 128>>>(ln16, wff116, nullptr, fa16, bff1, nullptr,
        NTOK, 2 * FFI, DMODEL, FFI, 1, 1);
    gemm_fp16<<<dim3(64, 5), 128>>>(fa16, wff216, h, hh16, ff2_b, h,
        NTOK, DMODEL, FFI, DMODEL, 1, 0);

    // output projection (transposed store) + input residual
    gemm_fp16<<<dim3(64, 5), 128>>>(hh16, wpo16, out, nullptr, pout_b, x,
        NTOK, DMODEL, DMODEL, 1, NTOK, 0);
}

// round 13
// speedup vs baseline: 1.6935x; 1.1051x over previous
#include <cuda_runtime.h>
#include <cuda_fp16.h>
#include <math.h>
#include <stdint.h>

#define NTOK 4096
#define DMODEL 320
#define FFI 1280
#define HEADS 8
#define DH 40
#define CTXN 77
#define CTXD 768
#define CTXP 128
#define QSCALE 0.15811388300841897f

// ---------------- scratch ----------------
__device__ float g_s[DMODEL];
__device__ float g_t[DMODEL];
__device__ float g_bp[DMODEL];
__device__ float g_h[NTOK * DMODEL];
__device__ float g_bff1[2 * FFI];

// fp16 activations
__device__ __align__(16) __half g_x16[NTOK * DMODEL];
__device__ __align__(16) __half g_ln16[NTOK * DMODEL];
__device__ __align__(16) __half g_qk16[NTOK * 2 * DMODEL];
__device__ __align__(16) __half g_vt16[DMODEL * NTOK];
__device__ __align__(16) __half g_q216[NTOK * DMODEL];
__device__ __align__(16) __half g_k216[CTXN * DMODEL];
__device__ __align__(16) __half g_vt2c16[DMODEL * CTXP];
__device__ __align__(16) __half g_ao16[NTOK * DMODEL];
__device__ __align__(16) __half g_fa16[NTOK * FFI];
__device__ __align__(16) __half g_hh16[NTOK * DMODEL];
__device__ __align__(16) __half g_ctx16[CTXN * CTXD];
// fp16 weights, [N][K]
__device__ __align__(16) __half g_wpin16[DMODEL * DMODEL];
__device__ __align__(16) __half g_wqk16[2 * DMODEL * DMODEL];
__device__ __align__(16) __half g_wv116[DMODEL * DMODEL];
__device__ __align__(16) __half g_wq216[DMODEL * DMODEL];
__device__ __align__(16) __half g_wk216[DMODEL * CTXD];
__device__ __align__(16) __half g_wv216[DMODEL * CTXD];
__device__ __align__(16) __half g_wo116[DMODEL * DMODEL];
__device__ __align__(16) __half g_wo216[DMODEL * DMODEL];
__device__ __align__(16) __half g_wff116[2 * FFI * DMODEL];
__device__ __align__(16) __half g_wff216[DMODEL * FFI];
__device__ __align__(16) __half g_wpo16[DMODEL * DMODEL];

// ---------------- helpers ----------------
__device__ __forceinline__ uint32_t smem_u32(const void* p) {
    return (uint32_t)__cvta_generic_to_shared(p);
}
__device__ __forceinline__ void cp16(uint32_t dst, const void* src, bool pred) {
    int sz = pred ? 16 : 0;
    asm volatile("cp.async.cg.shared.global [%0], [%1], 16, %2;" :: "r"(dst), "l"(src), "r"(sz));
}
__device__ __forceinline__ void cp_commit() { asm volatile("cp.async.commit_group;"); }
__device__ __forceinline__ void cp_wait1() { asm volatile("cp.async.wait_group 1;"); }

__device__ __forceinline__ void mma_f16(float* d, const uint32_t* a, uint32_t b0, uint32_t b1) {
    asm volatile(
        "mma.sync.aligned.m16n8k16.row.col.f32.f16.f16.f32 "
        "{%0,%1,%2,%3}, {%4,%5,%6,%7}, {%8,%9}, {%0,%1,%2,%3};"
        : "+f"(d[0]), "+f"(d[1]), "+f"(d[2]), "+f"(d[3])
        : "r"(a[0]), "r"(a[1]), "r"(a[2]), "r"(a[3]), "r"(b0), "r"(b1));
}
__device__ __forceinline__ float gelu_f(float g) {
    return 0.5f * g * (1.f + erff(g * 0.70710678118654752f));
}
__device__ __forceinline__ uint32_t packh2(float a, float b) {
    __half2 p = __floats2half2_rn(a, b);
    return *(uint32_t*)&p;
}

// ---------------- GroupNorm stats ----------------
__global__ void gn_stats_kernel(const float* __restrict__ x,
                                const float* __restrict__ gn_w,
                                const float* __restrict__ gn_b) {
    int g = blockIdx.x;
    int tid = threadIdx.x;
    const float* base = x + (size_t)g * 10 * 4096;
    float s = 0.f, ss = 0.f;
    for (int i = tid; i < 40960; i += 256) {
        float v = base[i];
        s += v; ss += v * v;
    }
    __shared__ float r1[256], r2[256];
    r1[tid] = s; r2[tid] = ss;
    __syncthreads();
    for (int off = 128; off > 0; off >>= 1) {
        if (tid < off) { r1[tid] += r1[tid + off]; r2[tid] += r2[tid + off]; }
        __syncthreads();
    }
    if (tid < 10) {
        float mu = r1[0] / 40960.f;
        float var = r2[0] / 40960.f - mu * mu;
        float inv = rsqrtf(var + 1e-6f);
        int c = g * 10 + tid;
        float w = gn_w[c];
        g_s[c] = inv * w;
        g_t[c] = gn_b[c] - mu * inv * w;
    }
}

__global__ void fold_pin_kernel(const float* __restrict__ pin_w,
                                const float* __restrict__ pin_b) {
    int o = blockIdx.x;
    int tid = threadIdx.x;
    float acc = 0.f;
    for (int c = tid; c < DMODEL; c += 64) {
        float w = pin_w[o * DMODEL + c];
        g_wpin16[o * DMODEL + c] = __float2half(w * g_s[c]);
        acc += w * g_t[c];
    }
    __shared__ float r[64];
    r[tid] = acc;
    __syncthreads();
    for (int off = 32; off > 0; off >>= 1) {
        if (tid < off) r[tid] += r[tid + off];
        __syncthreads();
    }
    if (tid == 0) g_bp[o] = pin_b[o] + r[0];
}

// ---------------- unified weight prep ----------------
__device__ __forceinline__ void tr_tile(const float* __restrict__ in, __half* __restrict__ out,
                                        int R, int Cc, int bx, int by, float scale) {
    __shared__ float tile[32][33];
    int tx = threadIdx.x & 31, ty = threadIdx.x >> 5;
    int c0 = bx * 32, r0 = by * 32;
#pragma unroll
    for (int i = 0; i < 4; i++) {
        int r = r0 + ty + i * 8, c = c0 + tx;
        if (r < R && c < Cc) tile[ty + i * 8][tx] = in[(size_t)r * Cc + c];
    }
    __syncthreads();
#pragma unroll
    for (int i = 0; i < 4; i++) {
        int c = c0 + ty + i * 8, r = r0 + tx;
        if (c < Cc && r < R) out[(size_t)c * R + r] = __float2half(tile[tx][ty + i * 8] * scale);
    }
}

#define PREP_BLOCKS 3728
__global__ __launch_bounds__(256) void prep_kernel(
    const float* __restrict__ x,
    const float* __restrict__ q1, const float* __restrict__ k1,
    const float* __restrict__ v1, const float* __restrict__ o1w,
    const float* __restrict__ q2, const float* __restrict__ k2,
    const float* __restrict__ v2, const float* __restrict__ o2w,
    const float* __restrict__ ff1w, const float* __restrict__ ff1b,
    const float* __restrict__ ff2w, const float* __restrict__ poutw,
    const float* __restrict__ ctx) {
    int b = blockIdx.x;
    int tid = threadIdx.x;
    if (b < 1280) { tr_tile(x, g_x16, DMODEL, NTOK, b % 128, b / 128, 1.f); return; }
    b -= 1280;
    if (b < 100) { tr_tile(q1, g_wqk16, DMODEL, DMODEL, b % 10, b / 10, QSCALE); return; }
    b -= 100;
    if (b < 100) { tr_tile(k1, g_wqk16 + DMODEL * DMODEL, DMODEL, DMODEL, b % 10, b / 10, 1.f); return; }
    b -= 100;
    if (b < 100) { tr_tile(v1, g_wv116, DMODEL, DMODEL, b % 10, b / 10, 1.f); return; }
    b -= 100;
    if (b < 100) { tr_tile(o1w, g_wo116, DMODEL, DMODEL, b % 10, b / 10, 1.f); return; }
    b -= 100;
    if (b < 100) { tr_tile(q2, g_wq216, DMODEL, DMODEL, b % 10, b / 10, QSCALE); return; }
    b -= 100;
    if (b < 240) { tr_tile(k2, g_wk216, CTXD, DMODEL, b % 10, b / 10, 1.f); return; }
    b -= 240;
    if (b < 240) { tr_tile(v2, g_wv216, CTXD, DMODEL, b % 10, b / 10, 1.f); return; }
    b -= 240;
    if (b < 100) { tr_tile(o2w, g_wo216, DMODEL, DMODEL, b % 10, b / 10, 1.f); return; }
    b -= 100;
    if (b < 400) { tr_tile(ff2w, g_wff216, FFI, DMODEL, b % 10, b / 10, 1.f); return; }
    b -= 400;
    if (b < 800) {
        __shared__ float tile[32][33];
        int tx = tid & 31, ty = tid >> 5;
        int bx = b % 80, by = b / 80;
        int c0 = bx * 32, r0 = by * 32;
#pragma unroll
        for (int i = 0; i < 4; i++) {
            int k = r0 + ty + i * 8, n = c0 + tx;
            int src = (n & 1) ? (FFI + (n >> 1)) : (n >> 1);
            tile[ty + i * 8][tx] = ff1w[(size_t)k * 2 * FFI + src];
        }
        __syncthreads();
#pragma unroll
        for (int i = 0; i < 4; i++) {
            int n = c0 + ty + i * 8, k = r0 + tx;
            g_wff116[(size_t)n * DMODEL + k] = __float2half(tile[tx][ty + i * 8]);
        }
        return;
    }
    b -= 800;
    if (b < 100) {
        int i0 = b * 1024 + tid * 4;
#pragma unroll
        for (int i = 0; i < 4; i++) g_wpo16[i0 + i] = __float2half(poutw[i0 + i]);
        return;
    }
    b -= 100;
    if (b < 58) {
        int i0 = b * 1024 + tid * 4;
#pragma unroll
        for (int i = 0; i < 4; i++) {
            int idx = i0 + i;
            if (idx < CTXN * CTXD) g_ctx16[idx] = __float2half(ctx[idx]);
        }
        return;
    }
    b -= 58;
    int idx = b * 256 + tid;
    int j = idx >> 1;
    g_bff1[idx] = (idx & 1) ? ff1b[FFI + j] : ff1b[j];
}

// ---------------- fp16 tensor-core GEMM, 64x64 tile, BK=32, 128 thr ----------------
// smem rows stride 20 u32 (16 data + 4 pad) -> conflict-free fragment loads.
__global__ __launch_bounds__(128) void gemm_fp16(
    const __half* __restrict__ A, const __half* __restrict__ B,
    float* __restrict__ C, __half* __restrict__ Ch,
    const float* __restrict__ bias, const float* __restrict__ resid,
    int M, int N, int K, int Csm, int Csn, int geglu) {
    __shared__ __align__(16) uint32_t As[2][64][20];
    __shared__ __align__(16) uint32_t Bs[2][64][20];
    int tid = threadIdx.x;
    int warp = tid >> 5, lane = tid & 31;
    int grp = lane >> 2, t4 = lane & 3;
    int m0 = blockIdx.x * 64, n0 = blockIdx.y * 64;
    int wm = (warp >> 1) * 32, wn = (warp & 1) * 32;

    float acc[2][4][4];
#pragma unroll
    for (int mi = 0; mi < 2; mi++)
#pragma unroll
        for (int ni = 0; ni < 4; ni++)
#pragma unroll
            for (int r = 0; r < 4; r++) acc[mi][ni][r] = 0.f;

    // loaders: 64 rows x 4 chunks (16B) per matrix, 2 slots/thread
    int r0s = tid >> 2, c0s = tid & 3;          // slot tid
    int r1s = (tid + 128) >> 2, c1s = tid & 3;  // slot tid+128 (same chunk idx, row+32)
    bool ap0 = (m0 + r0s) < M, ap1 = (m0 + r1s) < M;
    const __half* a0 = A + (size_t)(ap0 ? (m0 + r0s) : 0) * K + c0s * 8;
    const __half* a1 = A + (size_t)(ap1 ? (m0 + r1s) : 0) * K + c1s * 8;
    const __half* b0 = B + (size_t)(n0 + r0s) * K + c0s * 8;
    const __half* b1 = B + (size_t)(n0 + r1s) * K + c1s * 8;

    auto prefetch = [&](int st, int k0) {
        cp16(smem_u32(&As[st][r0s][c0s * 4]), a0 + k0, ap0);
        cp16(smem_u32(&As[st][r1s][c1s * 4]), a1 + k0, ap1);
        cp16(smem_u32(&Bs[st][r0s][c0s * 4]), b0 + k0, true);
        cp16(smem_u32(&Bs[st][r1s][c1s * 4]), b1 + k0, true);
    };

    int nK = K >> 5;
    prefetch(0, 0);
    cp_commit();
    for (int kt = 0; kt < nK; kt++) {
        if (kt + 1 < nK) prefetch((kt + 1) & 1, (kt + 1) << 5);
        cp_commit();
        cp_wait1();
        __syncthreads();
        int st = kt & 1;
#pragma unroll
        for (int kk = 0; kk < 2; kk++) {
            uint32_t af[2][4];
#pragma unroll
            for (int mi = 0; mi < 2; mi++) {
                int rm = wm + mi * 16;
                af[mi][0] = As[st][rm + grp][kk * 8 + t4];
                af[mi][1] = As[st][rm + grp + 8][kk * 8 + t4];
                af[mi][2] = As[st][rm + grp][kk * 8 + 4 + t4];
                af[mi][3] = As[st][rm + grp + 8][kk * 8 + 4 + t4];
            }
            uint32_t bf[4][2];
#pragma unroll
            for (int ni = 0; ni < 4; ni++) {
                int cn = wn + ni * 8 + grp;
                bf[ni][0] = Bs[st][cn][kk * 8 + t4];
                bf[ni][1] = Bs[st][cn][kk * 8 + 4 + t4];
            }
#pragma unroll
            for (int mi = 0; mi < 2; mi++)
#pragma unroll
                for (int ni = 0; ni < 4; ni++)
                    mma_f16(acc[mi][ni], af[mi], bf[ni][0], bf[ni][1]);
        }
        __syncthreads();
    }
#pragma unroll
    for (int mi = 0; mi < 2; mi++) {
        int r0r = m0 + wm + mi * 16 + grp;
        int r1r = r0r + 8;
#pragma unroll
        for (int ni = 0; ni < 4; ni++) {
            int c = n0 + wn + ni * 8 + t4 * 2;
            float b0v = bias ? bias[c] : 0.f;
            float b1v = bias ? bias[c + 1] : 0.f;
            if (geglu) {
                int co = c >> 1;
                if (r0r < M)
                    Ch[(size_t)r0r * Csm + co] =
                        __float2half((acc[mi][ni][0] + b0v) * gelu_f(acc[mi][ni][1] + b1v));
                if (r1r < M)
                    Ch[(size_t)r1r * Csm + co] =
                        __float2half((acc[mi][ni][2] + b0v) * gelu_f(acc[mi][ni][3] + b1v));
            } else {
                if (r0r < M) {
                    size_t o0 = (size_t)r0r * Csm + (size_t)c * Csn;
                    size_t o1 = o0 + Csn;
                    float v0 = acc[mi][ni][0] + b0v;
                    float v1 = acc[mi][ni][1] + b1v;
                    if (resid) { v0 += resid[o0]; v1 += resid[o1]; }
                    if (C) { C[o0] = v0; C[o1] = v1; }
                    if (Ch) { Ch[o0] = __float2half(v0); Ch[o1] = __float2half(v1); }
                }
                if (r1r < M) {
                    size_t o0 = (size_t)r1r * Csm + (size_t)c * Csn;
                    size_t o1 = o0 + Csn;
                    float v0 = acc[mi][ni][2] + b0v;
                    float v1 = acc[mi][ni][3] + b1v;
                    if (resid) { v0 += resid[o0]; v1 += resid[o1]; }
                    if (C) { C[o0] = v0; C[o1] = v1; }
                    if (Ch) { Ch[o0] = __float2half(v0); Ch[o1] = __float2half(v1); }
                }
            }
        }
    }
}

// ---------------- LayerNorm ----------------
__global__ __launch_bounds__(256) void ln_kernel(const float* __restrict__ in,
                                                 const float* __restrict__ w,
                                                 const float* __restrict__ b,
                                                 __half* __restrict__ out) {
    int warp = threadIdx.x >> 5, lane = threadIdx.x & 31;
    int m = blockIdx.x * 8 + warp;
    const float* row = in + (size_t)m * DMODEL;
    float vals[10];
    float s = 0.f, ss = 0.f;
#pragma unroll
    for (int i = 0; i < 10; i++) {
        float v = row[lane + i * 32];
        vals[i] = v;
        s += v; ss += v * v;
    }
#pragma unroll
    for (int off = 16; off > 0; off >>= 1) {
        s += __shfl_xor_sync(0xffffffffu, s, off);
        ss += __shfl_xor_sync(0xffffffffu, ss, off);
    }
    float mu = s / (float)DMODEL;
    float var = ss / (float)DMODEL - mu * mu;
    float rs = rsqrtf(var + 1e-5f);
#pragma unroll
    for (int i = 0; i < 10; i++) {
        int c = lane + i * 32;
        out[(size_t)m * DMODEL + c] = __float2half((vals[i] - mu) * rs * w[c] + b[c]);
    }
}

// ---------------- fp16 flash attention ----------------
__global__ __launch_bounds__(256) void attn16(
    const __half* __restrict__ Q, int ldq,
    const __half* __restrict__ K, int ldk,
    const __half* __restrict__ Vt, int ldv,
    __half* __restrict__ O, int n_k) {
    __shared__ __align__(16) uint32_t Ks[2][64][20];
    __shared__ __align__(16) uint32_t Vs[2][40][36];

    int h = blockIdx.y;
    int m0 = blockIdx.x * 128;
    int tid = threadIdx.x;
    int warp = tid >> 5, lane = tid & 31;
    int grp = lane >> 2, t4 = lane & 3;
    int wm = warp * 16;
    int row0 = m0 + wm + grp, row1 = row0 + 8;

    uint32_t qf[3][4];
#pragma unroll
    for (int kt = 0; kt < 3; kt++) {
        int d0 = h * DH + kt * 16 + 2 * t4;
        qf[kt][0] = *(const uint32_t*)(Q + (size_t)row0 * ldq + d0);
        qf[kt][1] = *(const uint32_t*)(Q + (size_t)row1 * ldq + d0);
        if (kt < 2) {
            qf[kt][2] = *(const uint32_t*)(Q + (size_t)row0 * ldq + d0 + 8);
            qf[kt][3] = *(const uint32_t*)(Q + (size_t)row1 * ldq + d0 + 8);
        } else {
            qf[kt][2] = 0; qf[kt][3] = 0;
        }
    }

    float o[5][4];
#pragma unroll
    for (int d = 0; d < 5; d++)
#pragma unroll
        for (int r = 0; r < 4; r++) o[d][r] = 0.f;
    float m_r0 = -1e30f, m_r1 = -1e30f, l_r0 = 0.f, l_r1 = 0.f;

    auto prefetch = [&](int st, int kt0) {
        for (int t = tid; t < 320; t += 256) {
            int r = t / 5, ch = t - r * 5;
            bool pred = (kt0 + r) < n_k;
            const __half* src = K + (size_t)(pred ? (kt0 + r) : 0) * ldk + h * DH + ch * 8;
            cp16(smem_u32(&Ks[st][r][ch * 4]), src, pred);
        }
        if (tid < 160) {
            int r = tid >> 2, ch = tid & 3;
            const __half* src = Vt + (size_t)(h * DH + r) * ldv + kt0 + ch * 16;
            cp16(smem_u32(&Vs[st][r][ch * 8]), src, true);
            src += 8;
            cp16(smem_u32(&Vs[st][r][ch * 8 + 4]), src, true);
        }
    };

    int nT = (n_k + 63) >> 6;
    prefetch(0, 0);
    cp_commit();
    for (int it = 0; it < nT; it++) {
        if (it + 1 < nT) prefetch((it + 1) & 1, (it + 1) * 64);
        cp_commit();
        cp_wait1();
        __syncthreads();
        int st = it & 1;
        int kcount = min(64, n_k - it * 64);

        float s[8][4];
#pragma unroll
        for (int nt = 0; nt < 8; nt++)
#pragma unroll
            for (int r = 0; r < 4; r++) s[nt][r] = 0.f;
#pragma unroll
        for (int kt = 0; kt < 3; kt++) {
#pragma unroll
            for (int nt = 0; nt < 8; nt++) {
                int kr = nt * 8 + grp;
                uint32_t b0 = Ks[st][kr][kt * 8 + t4];
                uint32_t b1 = (kt < 2) ? Ks[st][kr][kt * 8 + 4 + t4] : 0u;
                mma_f16(s[nt], qf[kt], b0, b1);
            }
        }
        if (kcount < 64) {
#pragma unroll
            for (int nt = 0; nt < 8; nt++) {
                int c0 = nt * 8 + 2 * t4;
                if (c0 >= kcount)     { s[nt][0] = -1e30f; s[nt][2] = -1e30f; }
                if (c0 + 1 >= kcount) { s[nt][1] = -1e30f; s[nt][3] = -1e30f; }
            }
        }

        float mx0 = m_r0, mx1 = m_r1;
#pragma unroll
        for (int nt = 0; nt < 8; nt++) {
            mx0 = fmaxf(mx0, fmaxf(s[nt][0], s[nt][1]));
            mx1 = fmaxf(mx1, fmaxf(s[nt][2], s[nt][3]));
        }
        mx0 = fmaxf(mx0, __shfl_xor_sync(0xffffffffu, mx0, 1));
        mx0 = fmaxf(mx0, __shfl_xor_sync(0xffffffffu, mx0, 2));
        mx1 = fmaxf(mx1, __shfl_xor_sync(0xffffffffu, mx1, 1));
        mx1 = fmaxf(mx1, __shfl_xor_sync(0xffffffffu, mx1, 2));
        float f0 = __expf(m_r0 - mx0), f1 = __expf(m_r1 - mx1);
        float p[8][4];
        float sum0 = 0.f, sum1 = 0.f;
#pragma unroll
        for (int nt = 0; nt < 8; nt++) {
            p[nt][0] = __expf(s[nt][0] - mx0);
            p[nt][1] = __expf(s[nt][1] - mx0);
            p[nt][2] = __expf(s[nt][2] - mx1);
            p[nt][3] = __expf(s[nt][3] - mx1);
            sum0 += p[nt][0] + p[nt][1];
            sum1 += p[nt][2] + p[nt][3];
        }
        sum0 += __shfl_xor_sync(0xffffffffu, sum0, 1);
        sum0 += __shfl_xor_sync(0xffffffffu, sum0, 2);
        sum1 += __shfl_xor_sync(0xffffffffu, sum1, 1);
        sum1 += __shfl_xor_sync(0xffffffffu, sum1, 2);
        l_r0 = l_r0 * f0 + sum0; m_r0 = mx0;
        l_r1 = l_r1 * f1 + sum1; m_r1 = mx1;

        uint32_t pa[4][4];
#pragma unroll
        for (int ks = 0; ks < 4; ks++) {
            pa[ks][0] = packh2(p[2 * ks][0],     p[2 * ks][1]);
            pa[ks][1] = packh2(p[2 * ks][2],     p[2 * ks][3]);
            pa[ks][2] = packh2(p[2 * ks + 1][0], p[2 * ks + 1][1]);
            pa[ks][3] = packh2(p[2 * ks + 1][2], p[2 * ks + 1][3]);
        }

#pragma unroll
        for (int d = 0; d < 5; d++) {
            o[d][0] *= f0; o[d][1] *= f0;
            o[d][2] *= f1; o[d][3] *= f1;
        }

#pragma unroll
        for (int d = 0; d < 5; d++) {
            int vr = d * 8 + grp;
#pragma unroll
            for (int ks = 0; ks < 4; ks++) {
                uint32_t b0 = Vs[st][vr][ks * 8 + t4];
                uint32_t b1 = Vs[st][vr][ks * 8 + 4 + t4];
                mma_f16(o[d], pa[ks], b0, b1);
            }
        }
        __syncthreads();
    }

    float inv0 = 1.f / l_r0, inv1 = 1.f / l_r1;
#pragma unroll
    for (int d = 0; d < 5; d++) {
        int c = h * DH + d * 8 + 2 * t4;
        O[(size_t)row0 * DMODEL + c]     = __float2half(o[d][0] * inv0);
        O[(size_t)row0 * DMODEL + c + 1] = __float2half(o[d][1] * inv0);
        O[(size_t)row1 * DMODEL + c]     = __float2half(o[d][2] * inv1);
        O[(size_t)row1 * DMODEL + c + 1] = __float2half(o[d][3] * inv1);
    }
}

// ---------------- host launch ----------------
extern "C" void kernel_launch(void* const* d_in, const int* in_sizes, int n_in,
                              void* d_out, int out_size) {
    const float* x      = (const float*)d_in[0];
    const float* ctx    = (const float*)d_in[1];
    const float* gn_w   = (const float*)d_in[2];
    const float* gn_b   = (const float*)d_in[3];
    const float* pin_w  = (const float*)d_in[4];
    const float* pin_b  = (const float*)d_in[5];
    const float* ln1_w  = (const float*)d_in[6];
    const float* ln1_b  = (const float*)d_in[7];
    const float* q1     = (const float*)d_in[8];
    const float* k1     = (const float*)d_in[9];
    const float* v1     = (const float*)d_in[10];
    const float* o1_w   = (const float*)d_in[11];
    const float* o1_b   = (const float*)d_in[12];
    const float* ln2_w  = (const float*)d_in[13];
    const float* ln2_b  = (const float*)d_in[14];
    const float* q2     = (const float*)d_in[15];
    const float* k2     = (const float*)d_in[16];
    const float* v2     = (const float*)d_in[17];
    const float* o2_w   = (const float*)d_in[18];
    const float* o2_b   = (const float*)d_in[19];
    const float* ln3_w  = (const float*)d_in[20];
    const float* ln3_b  = (const float*)d_in[21];
    const float* ff1_w  = (const float*)d_in[22];
    const float* ff1_b  = (const float*)d_in[23];
    const float* ff2_w  = (const float*)d_in[24];
    const float* ff2_b  = (const float*)d_in[25];
    const float* pout_w = (const float*)d_in[26];
    const float* pout_b = (const float*)d_in[27];
    float* out = (float*)d_out;

    float *bp, *h, *bff1;
    __half *x16, *ln16, *qk16, *vt16, *q216, *k216, *vt2c16, *ao16, *fa16, *hh16, *ctx16;
    __half *wpin16, *wqk16, *wv116, *wq216, *wk216, *wv216, *wo116, *wo216;
    __half *wff116, *wff216, *wpo16;
    cudaGetSymbolAddress((void**)&bp, g_bp);
    cudaGetSymbolAddress((void**)&h, g_h);
    cudaGetSymbolAddress((void**)&bff1, g_bff1);
    cudaGetSymbolAddress((void**)&x16, g_x16);
    cudaGetSymbolAddress((void**)&ln16, g_ln16);
    cudaGetSymbolAddress((void**)&qk16, g_qk16);
    cudaGetSymbolAddress((void**)&vt16, g_vt16);
    cudaGetSymbolAddress((void**)&q216, g_q216);
    cudaGetSymbolAddress((void**)&k216, g_k216);
    cudaGetSymbolAddress((void**)&vt2c16, g_vt2c16);
    cudaGetSymbolAddress((void**)&ao16, g_ao16);
    cudaGetSymbolAddress((void**)&fa16, g_fa16);
    cudaGetSymbolAddress((void**)&hh16, g_hh16);
    cudaGetSymbolAddress((void**)&ctx16, g_ctx16);
    cudaGetSymbolAddress((void**)&wpin16, g_wpin16);
    cudaGetSymbolAddress((void**)&wqk16, g_wqk16);
    cudaGetSymbolAddress((void**)&wv116, g_wv116);
    cudaGetSymbolAddress((void**)&wq216, g_wq216);
    cudaGetSymbolAddress((void**)&wk216, g_wk216);
    cudaGetSymbolAddress((void**)&wv216, g_wv216);
    cudaGetSymbolAddress((void**)&wo116, g_wo116);
    cudaGetSymbolAddress((void**)&wo216, g_wo216);
    cudaGetSymbolAddress((void**)&wff116, g_wff116);
    cudaGetSymbolAddress((void**)&wff216, g_wff216);
    cudaGetSymbolAddress((void**)&wpo16, g_wpo16);

    // prep: 3 launches
    gn_stats_kernel<<<32, 256>>>(x, gn_w, gn_b);
    fold_pin_kernel<<<DMODEL, 64>>>(pin_w, pin_b);
    prep_kernel<<<PREP_BLOCKS, 256>>>(x, q1, k1, v1, o1_w, q2, k2, v2, o2_w,
                                      ff1_w, ff1_b, ff2_w, pout_w, ctx);

    // pin projection
    gemm_fp16<<<dim3(64, 5), 128>>>(x16, wpin16, h, nullptr, bp, nullptr,
        NTOK, DMODEL, DMODEL, DMODEL, 1, 0);

    // self-attention block
    ln_kernel<<<NTOK / 8, 256>>>(h, ln1_w, ln1_b, ln16);
    gemm_fp16<<<dim3(64, 10), 128>>>(ln16, wqk16, nullptr, qk16, nullptr, nullptr,
        NTOK, 2 * DMODEL, DMODEL, 2 * DMODEL, 1, 0);
    gemm_fp16<<<dim3(64, 5), 128>>>(ln16, wv116, nullptr, vt16, nullptr, nullptr,
        NTOK, DMODEL, DMODEL, 1, NTOK, 0);   // V^T [d][tok]
    attn16<<<dim3(NTOK / 128, HEADS), 256>>>(
        qk16, 2 * DMODEL, qk16 + DMODEL, 2 * DMODEL, vt16, NTOK, ao16, NTOK);
    gemm_fp16<<<dim3(64, 5), 128>>>(ao16, wo116, h, nullptr, o1_b, h,
        NTOK, DMODEL, DMODEL, DMODEL, 1, 0);

    // cross-attention block
    ln_kernel<<<NTOK / 8, 256>>>(h, ln2_w, ln2_b, ln16);
    gemm_fp16<<<dim3(64, 5), 128>>>(ln16, wq216, nullptr, q216, nullptr, nullptr,
        NTOK, DMODEL, DMODEL, DMODEL, 1, 0);
    gemm_fp16<<<dim3(2, 5), 128>>>(ctx16, wk216, nullptr, k216, nullptr, nullptr,
        CTXN, DMODEL, CTXD, DMODEL, 1, 0);
    gemm_fp16<<<dim3(2, 5), 128>>>(ctx16, wv216, nullptr, vt2c16, nullptr, nullptr,
        CTXN, DMODEL, CTXD, 1, CTXP, 0);     // V^T [d][key], pad stays zero
    attn16<<<dim3(NTOK / 128, HEADS), 256>>>(
        q216, DMODEL, k216, DMODEL, vt2c16, CTXP, ao16, CTXN);
    gemm_fp16<<<dim3(64, 5), 128>>>(ao16, wo216, h, nullptr, o2_b, h,
        NTOK, DMODEL, DMODEL, DMODEL, 1, 0);

    // GEGLU FF block
    ln_kernel<<<NTOK / 8, 256>>>(h, ln3_w, ln3_b, ln16);
    gemm_fp16<<<dim3(64, 40), 128>>>(ln16, wff116, nullptr, fa16, bff1, nullptr,
        NTOK, 2 * FFI, DMODEL, FFI, 1, 1);
    gemm_fp16<<<dim3(64, 5), 128>>>(fa16, wff216, h, hh16, ff2_b, h,
        NTOK, DMODEL, FFI, DMODEL, 1, 0);

    // output projection (transposed store) + input residual
    gemm_fp16<<<dim3(64, 5), 128>>>(hh16, wpo16, out, nullptr, pout_b, x,
        NTOK, DMODEL, DMODEL, 1, NTOK, 0);
}

// round 14
// speedup vs baseline: 1.7712x; 1.0459x over previous
#include <cuda_runtime.h>
#include <cuda_fp16.h>
#include <math.h>
#include <stdint.h>

#define NTOK 4096
#define DMODEL 320
#define FFI 1280
#define HEADS 8
#define DH 40
#define CTXN 77
#define CTXD 768
#define CTXP 128
#define QSCALE 0.15811388300841897f

// ---------------- scratch ----------------
__device__ float g_s[DMODEL];
__device__ float g_t[DMODEL];
__device__ float g_bp[DMODEL];
__device__ float g_h[NTOK * DMODEL];
__device__ float g_bff1[2 * FFI];

// fp16 activations
__device__ __align__(16) __half g_x16[NTOK * DMODEL];
__device__ __align__(16) __half g_ln16[NTOK * DMODEL];
__device__ __align__(16) __half g_qk16[NTOK * 2 * DMODEL];
__device__ __align__(16) __half g_vt16[DMODEL * NTOK];
__device__ __align__(16) __half g_q216[NTOK * DMODEL];
__device__ __align__(16) __half g_k216[CTXN * DMODEL];
__device__ __align__(16) __half g_vt2c16[DMODEL * CTXP];
__device__ __align__(16) __half g_ao16[NTOK * DMODEL];
__device__ __align__(16) __half g_fa16[NTOK * FFI];
__device__ __align__(16) __half g_hh16[NTOK * DMODEL];
__device__ __align__(16) __half g_ctx16[CTXN * CTXD];
// fp16 weights, [N][K]
__device__ __align__(16) __half g_wpin16[DMODEL * DMODEL];
__device__ __align__(16) __half g_wqkv16[3 * DMODEL * DMODEL];  // q(scaled)|k|v
__device__ __align__(16) __half g_wq216[DMODEL * DMODEL];
__device__ __align__(16) __half g_wkv216[2 * DMODEL * CTXD];    // k2|v2
__device__ __align__(16) __half g_wo116[DMODEL * DMODEL];
__device__ __align__(16) __half g_wo216[DMODEL * DMODEL];
__device__ __align__(16) __half g_wff116[2 * FFI * DMODEL];
__device__ __align__(16) __half g_wff216[DMODEL * FFI];
__device__ __align__(16) __half g_wpo16[DMODEL * DMODEL];

// ---------------- helpers ----------------
__device__ __forceinline__ uint32_t smem_u32(const void* p) {
    return (uint32_t)__cvta_generic_to_shared(p);
}
__device__ __forceinline__ void cp16(uint32_t dst, const void* src, bool pred) {
    int sz = pred ? 16 : 0;
    asm volatile("cp.async.cg.shared.global [%0], [%1], 16, %2;" :: "r"(dst), "l"(src), "r"(sz));
}
__device__ __forceinline__ void cp_commit() { asm volatile("cp.async.commit_group;"); }
__device__ __forceinline__ void cp_wait1() { asm volatile("cp.async.wait_group 1;"); }

__device__ __forceinline__ void mma_f16(float* d, const uint32_t* a, uint32_t b0, uint32_t b1) {
    asm volatile(
        "mma.sync.aligned.m16n8k16.row.col.f32.f16.f16.f32 "
        "{%0,%1,%2,%3}, {%4,%5,%6,%7}, {%8,%9}, {%0,%1,%2,%3};"
        : "+f"(d[0]), "+f"(d[1]), "+f"(d[2]), "+f"(d[3])
        : "r"(a[0]), "r"(a[1]), "r"(a[2]), "r"(a[3]), "r"(b0), "r"(b1));
}
__device__ __forceinline__ float gelu_f(float g) {
    return 0.5f * g * (1.f + erff(g * 0.70710678118654752f));
}
__device__ __forceinline__ uint32_t packh2(float a, float b) {
    __half2 p = __floats2half2_rn(a, b);
    return *(uint32_t*)&p;
}

// ---------------- GroupNorm stats ----------------
__global__ void gn_stats_kernel(const float* __restrict__ x,
                                const float* __restrict__ gn_w,
                                const float* __restrict__ gn_b) {
    int g = blockIdx.x;
    int tid = threadIdx.x;
    const float* base = x + (size_t)g * 10 * 4096;
    float s = 0.f, ss = 0.f;
    for (int i = tid; i < 40960; i += 256) {
        float v = base[i];
        s += v; ss += v * v;
    }
    __shared__ float r1[256], r2[256];
    r1[tid] = s; r2[tid] = ss;
    __syncthreads();
    for (int off = 128; off > 0; off >>= 1) {
        if (tid < off) { r1[tid] += r1[tid + off]; r2[tid] += r2[tid + off]; }
        __syncthreads();
    }
    if (tid < 10) {
        float mu = r1[0] / 40960.f;
        float var = r2[0] / 40960.f - mu * mu;
        float inv = rsqrtf(var + 1e-6f);
        int c = g * 10 + tid;
        float w = gn_w[c];
        g_s[c] = inv * w;
        g_t[c] = gn_b[c] - mu * inv * w;
    }
}

__global__ void fold_pin_kernel(const float* __restrict__ pin_w,
                                const float* __restrict__ pin_b) {
    int o = blockIdx.x;
    int tid = threadIdx.x;
    float acc = 0.f;
    for (int c = tid; c < DMODEL; c += 64) {
        float w = pin_w[o * DMODEL + c];
        g_wpin16[o * DMODEL + c] = __float2half(w * g_s[c]);
        acc += w * g_t[c];
    }
    __shared__ float r[64];
    r[tid] = acc;
    __syncthreads();
    for (int off = 32; off > 0; off >>= 1) {
        if (tid < off) r[tid] += r[tid + off];
        __syncthreads();
    }
    if (tid == 0) g_bp[o] = pin_b[o] + r[0];
}

// ---------------- unified weight prep ----------------
__device__ __forceinline__ void tr_tile(const float* __restrict__ in, __half* __restrict__ out,
                                        int R, int Cc, int bx, int by, float scale) {
    __shared__ float tile[32][33];
    int tx = threadIdx.x & 31, ty = threadIdx.x >> 5;
    int c0 = bx * 32, r0 = by * 32;
#pragma unroll
    for (int i = 0; i < 4; i++) {
        int r = r0 + ty + i * 8, c = c0 + tx;
        if (r < R && c < Cc) tile[ty + i * 8][tx] = in[(size_t)r * Cc + c];
    }
    __syncthreads();
#pragma unroll
    for (int i = 0; i < 4; i++) {
        int c = c0 + ty + i * 8, r = r0 + tx;
        if (c < Cc && r < R) out[(size_t)c * R + r] = __float2half(tile[tx][ty + i * 8] * scale);
    }
}

#define PREP_BLOCKS 3728
__global__ __launch_bounds__(256) void prep_kernel(
    const float* __restrict__ x,
    const float* __restrict__ q1, const float* __restrict__ k1,
    const float* __restrict__ v1, const float* __restrict__ o1w,
    const float* __restrict__ q2, const float* __restrict__ k2,
    const float* __restrict__ v2, const float* __restrict__ o2w,
    const float* __restrict__ ff1w, const float* __restrict__ ff1b,
    const float* __restrict__ ff2w, const float* __restrict__ poutw,
    const float* __restrict__ ctx) {
    int b = blockIdx.x;
    int tid = threadIdx.x;
    if (b < 1280) { tr_tile(x, g_x16, DMODEL, NTOK, b % 128, b / 128, 1.f); return; }
    b -= 1280;
    if (b < 100) { tr_tile(q1, g_wqkv16, DMODEL, DMODEL, b % 10, b / 10, QSCALE); return; }
    b -= 100;
    if (b < 100) { tr_tile(k1, g_wqkv16 + DMODEL * DMODEL, DMODEL, DMODEL, b % 10, b / 10, 1.f); return; }
    b -= 100;
    if (b < 100) { tr_tile(v1, g_wqkv16 + 2 * DMODEL * DMODEL, DMODEL, DMODEL, b % 10, b / 10, 1.f); return; }
    b -= 100;
    if (b < 100) { tr_tile(o1w, g_wo116, DMODEL, DMODEL, b % 10, b / 10, 1.f); return; }
    b -= 100;
    if (b < 100) { tr_tile(q2, g_wq216, DMODEL, DMODEL, b % 10, b / 10, QSCALE); return; }
    b -= 100;
    if (b < 240) { tr_tile(k2, g_wkv216, CTXD, DMODEL, b % 10, b / 10, 1.f); return; }
    b -= 240;
    if (b < 240) { tr_tile(v2, g_wkv216 + DMODEL * CTXD, CTXD, DMODEL, b % 10, b / 10, 1.f); return; }
    b -= 240;
    if (b < 100) { tr_tile(o2w, g_wo216, DMODEL, DMODEL, b % 10, b / 10, 1.f); return; }
    b -= 100;
    if (b < 400) { tr_tile(ff2w, g_wff216, FFI, DMODEL, b % 10, b / 10, 1.f); return; }
    b -= 400;
    if (b < 800) {
        __shared__ float tile[32][33];
        int tx = tid & 31, ty = tid >> 5;
        int bx = b % 80, by = b / 80;
        int c0 = bx * 32, r0 = by * 32;
#pragma unroll
        for (int i = 0; i < 4; i++) {
            int k = r0 + ty + i * 8, n = c0 + tx;
            int src = (n & 1) ? (FFI + (n >> 1)) : (n >> 1);
            tile[ty + i * 8][tx] = ff1w[(size_t)k * 2 * FFI + src];
        }
        __syncthreads();
#pragma unroll
        for (int i = 0; i < 4; i++) {
            int n = c0 + ty + i * 8, k = r0 + tx;
            g_wff116[(size_t)n * DMODEL + k] = __float2half(tile[tx][ty + i * 8]);
        }
        return;
    }
    b -= 800;
    if (b < 100) {
        int i0 = b * 1024 + tid * 4;
#pragma unroll
        for (int i = 0; i < 4; i++) g_wpo16[i0 + i] = __float2half(poutw[i0 + i]);
        return;
    }
    b -= 100;
    if (b < 58) {
        int i0 = b * 1024 + tid * 4;
#pragma unroll
        for (int i = 0; i < 4; i++) {
            int idx = i0 + i;
            if (idx < CTXN * CTXD) g_ctx16[idx] = __float2half(ctx[idx]);
        }
        return;
    }
    b -= 58;
    int idx = b * 256 + tid;
    int j = idx >> 1;
    g_bff1[idx] = (idx & 1) ? ff1b[FFI + j] : ff1b[j];
}

// ---------------- fp16 tensor-core GEMM, 64x64 tile, BK=32, 3-stage ----------------
// mode 0: normal (C fp32 strided + optional Ch fp16 mirror, bias, resid)
// mode 1: geglu -> Ch fp16 (Csm stride)
// mode 2: split fp16: col<split -> Ch[r*Csm+c]; col>=split -> Ch2[(c-split)*ld2 + r]
__global__ __launch_bounds__(128) void gemm_fp16(
    const __half* __restrict__ A, const __half* __restrict__ B,
    float* __restrict__ C, __half* __restrict__ Ch, __half* __restrict__ Ch2,
    const float* __restrict__ bias, const float* __restrict__ resid,
    int M, int N, int K, int Csm, int Csn, int mode, int split, int ld2) {
    __shared__ __align__(16) uint32_t As[3][64][20];
    __shared__ __align__(16) uint32_t Bs[3][64][20];
    int tid = threadIdx.x;
    int warp = tid >> 5, lane = tid & 31;
    int grp = lane >> 2, t4 = lane & 3;
    int m0 = blockIdx.x * 64, n0 = blockIdx.y * 64;
    int wm = (warp >> 1) * 32, wn = (warp & 1) * 32;

    float acc[2][4][4];
#pragma unroll
    for (int mi = 0; mi < 2; mi++)
#pragma unroll
        for (int ni = 0; ni < 4; ni++)
#pragma unroll
            for (int r = 0; r < 4; r++) acc[mi][ni][r] = 0.f;

    int r0s = tid >> 2, c0s = tid & 3;
    int r1s = (tid + 128) >> 2, c1s = tid & 3;
    bool ap0 = (m0 + r0s) < M, ap1 = (m0 + r1s) < M;
    const __half* a0 = A + (size_t)(ap0 ? (m0 + r0s) : 0) * K + c0s * 8;
    const __half* a1 = A + (size_t)(ap1 ? (m0 + r1s) : 0) * K + c1s * 8;
    const __half* b0 = B + (size_t)(n0 + r0s) * K + c0s * 8;
    const __half* b1 = B + (size_t)(n0 + r1s) * K + c1s * 8;

    auto prefetch = [&](int st, int k0) {
        cp16(smem_u32(&As[st][r0s][c0s * 4]), a0 + k0, ap0);
        cp16(smem_u32(&As[st][r1s][c1s * 4]), a1 + k0, ap1);
        cp16(smem_u32(&Bs[st][r0s][c0s * 4]), b0 + k0, true);
        cp16(smem_u32(&Bs[st][r1s][c1s * 4]), b1 + k0, true);
    };

    int nK = K >> 5;
    prefetch(0, 0);
    cp_commit();
    if (nK > 1) prefetch(1, 32);
    cp_commit();
    int st = 0;
    for (int kt = 0; kt < nK; kt++) {
        cp_wait1();
        __syncthreads();
        int pf = kt + 2;
        if (pf < nK) prefetch(pf % 3, pf << 5);
        cp_commit();
#pragma unroll
        for (int kk = 0; kk < 2; kk++) {
            uint32_t af[2][4];
#pragma unroll
            for (int mi = 0; mi < 2; mi++) {
                int rm = wm + mi * 16;
                af[mi][0] = As[st][rm + grp][kk * 8 + t4];
                af[mi][1] = As[st][rm + grp + 8][kk * 8 + t4];
                af[mi][2] = As[st][rm + grp][kk * 8 + 4 + t4];
                af[mi][3] = As[st][rm + grp + 8][kk * 8 + 4 + t4];
            }
            uint32_t bf[4][2];
#pragma unroll
            for (int ni = 0; ni < 4; ni++) {
                int cn = wn + ni * 8 + grp;
                bf[ni][0] = Bs[st][cn][kk * 8 + t4];
                bf[ni][1] = Bs[st][cn][kk * 8 + 4 + t4];
            }
#pragma unroll
            for (int mi = 0; mi < 2; mi++)
#pragma unroll
                for (int ni = 0; ni < 4; ni++)
                    mma_f16(acc[mi][ni], af[mi], bf[ni][0], bf[ni][1]);
        }
        st = (st == 2) ? 0 : st + 1;
    }
#pragma unroll
    for (int mi = 0; mi < 2; mi++) {
        int r0r = m0 + wm + mi * 16 + grp;
        int r1r = r0r + 8;
#pragma unroll
        for (int ni = 0; ni < 4; ni++) {
            int c = n0 + wn + ni * 8 + t4 * 2;
            float b0v = bias ? bias[c] : 0.f;
            float b1v = bias ? bias[c + 1] : 0.f;
            if (mode == 1) {
                int co = c >> 1;
                if (r0r < M)
                    Ch[(size_t)r0r * Csm + co] =
                        __float2half((acc[mi][ni][0] + b0v) * gelu_f(acc[mi][ni][1] + b1v));
                if (r1r < M)
                    Ch[(size_t)r1r * Csm + co] =
                        __float2half((acc[mi][ni][2] + b0v) * gelu_f(acc[mi][ni][3] + b1v));
            } else if (mode == 2) {
                if (c < split) {
                    if (r0r < M) {
                        Ch[(size_t)r0r * Csm + c]     = __float2half(acc[mi][ni][0]);
                        Ch[(size_t)r0r * Csm + c + 1] = __float2half(acc[mi][ni][1]);
                    }
                    if (r1r < M) {
                        Ch[(size_t)r1r * Csm + c]     = __float2half(acc[mi][ni][2]);
                        Ch[(size_t)r1r * Csm + c + 1] = __float2half(acc[mi][ni][3]);
                    }
                } else {
                    int ct = c - split;
                    if (r0r < M) {
                        Ch2[(size_t)ct * ld2 + r0r]       = __float2half(acc[mi][ni][0]);
                        Ch2[(size_t)(ct + 1) * ld2 + r0r] = __float2half(acc[mi][ni][1]);
                    }
                    if (r1r < M) {
                        Ch2[(size_t)ct * ld2 + r1r]       = __float2half(acc[mi][ni][2]);
                        Ch2[(size_t)(ct + 1) * ld2 + r1r] = __float2half(acc[mi][ni][3]);
                    }
                }
            } else {
                if (r0r < M) {
                    size_t o0 = (size_t)r0r * Csm + (size_t)c * Csn;
                    size_t o1 = o0 + Csn;
                    float v0 = acc[mi][ni][0] + b0v;
                    float v1 = acc[mi][ni][1] + b1v;
                    if (resid) { v0 += resid[o0]; v1 += resid[o1]; }
                    if (C) { C[o0] = v0; C[o1] = v1; }
                    if (Ch) { Ch[o0] = __float2half(v0); Ch[o1] = __float2half(v1); }
                }
                if (r1r < M) {
                    size_t o0 = (size_t)r1r * Csm + (size_t)c * Csn;
                    size_t o1 = o0 + Csn;
                    float v0 = acc[mi][ni][2] + b0v;
                    float v1 = acc[mi][ni][3] + b1v;
                    if (resid) { v0 += resid[o0]; v1 += resid[o1]; }
                    if (C) { C[o0] = v0; C[o1] = v1; }
                    if (Ch) { Ch[o0] = __float2half(v0); Ch[o1] = __float2half(v1); }
                }
            }
        }
    }
}

// ---------------- LayerNorm ----------------
__global__ __launch_bounds__(256) void ln_kernel(const float* __restrict__ in,
                                                 const float* __restrict__ w,
                                                 const float* __restrict__ b,
                                                 __half* __restrict__ out) {
    int warp = threadIdx.x >> 5, lane = threadIdx.x & 31;
    int m = blockIdx.x * 8 + warp;
    const float* row = in + (size_t)m * DMODEL;
    float vals[10];
    float s = 0.f, ss = 0.f;
#pragma unroll
    for (int i = 0; i < 10; i++) {
        float v = row[lane + i * 32];
        vals[i] = v;
        s += v; ss += v * v;
    }
#pragma unroll
    for (int off = 16; off > 0; off >>= 1) {
        s += __shfl_xor_sync(0xffffffffu, s, off);
        ss += __shfl_xor_sync(0xffffffffu, ss, off);
    }
    float mu = s / (float)DMODEL;
    float var = ss / (float)DMODEL - mu * mu;
    float rs = rsqrtf(var + 1e-5f);
#pragma unroll
    for (int i = 0; i < 10; i++) {
        int c = lane + i * 32;
        out[(size_t)m * DMODEL + c] = __float2half((vals[i] - mu) * rs * w[c] + b[c]);
    }
}

// ---------------- fp16 flash attention ----------------
__global__ __launch_bounds__(256) void attn16(
    const __half* __restrict__ Q, int ldq,
    const __half* __restrict__ K, int ldk,
    const __half* __restrict__ Vt, int ldv,
    __half* __restrict__ O, int n_k) {
    __shared__ __align__(16) uint32_t Ks[2][64][20];
    __shared__ __align__(16) uint32_t Vs[2][40][36];

    int h = blockIdx.y;
    int m0 = blockIdx.x * 128;
    int tid = threadIdx.x;
    int warp = tid >> 5, lane = tid & 31;
    int grp = lane >> 2, t4 = lane & 3;
    int wm = warp * 16;
    int row0 = m0 + wm + grp, row1 = row0 + 8;

    uint32_t qf[3][4];
#pragma unroll
    for (int kt = 0; kt < 3; kt++) {
        int d0 = h * DH + kt * 16 + 2 * t4;
        qf[kt][0] = *(const uint32_t*)(Q + (size_t)row0 * ldq + d0);
        qf[kt][1] = *(const uint32_t*)(Q + (size_t)row1 * ldq + d0);
        if (kt < 2) {
            qf[kt][2] = *(const uint32_t*)(Q + (size_t)row0 * ldq + d0 + 8);
            qf[kt][3] = *(const uint32_t*)(Q + (size_t)row1 * ldq + d0 + 8);
        } else {
            qf[kt][2] = 0; qf[kt][3] = 0;
        }
    }

    float o[5][4];
#pragma unroll
    for (int d = 0; d < 5; d++)
#pragma unroll
        for (int r = 0; r < 4; r++) o[d][r] = 0.f;
    float m_r0 = -1e30f, m_r1 = -1e30f, l_r0 = 0.f, l_r1 = 0.f;

    auto prefetch = [&](int st, int kt0) {
        for (int t = tid; t < 320; t += 256) {
            int r = t / 5, ch = t - r * 5;
            bool pred = (kt0 + r) < n_k;
            const __half* src = K + (size_t)(pred ? (kt0 + r) : 0) * ldk + h * DH + ch * 8;
            cp16(smem_u32(&Ks[st][r][ch * 4]), src, pred);
        }
        if (tid < 160) {
            int r = tid >> 2, ch = tid & 3;
            const __half* src = Vt + (size_t)(h * DH + r) * ldv + kt0 + ch * 16;
            cp16(smem_u32(&Vs[st][r][ch * 8]), src, true);
            src += 8;
            cp16(smem_u32(&Vs[st][r][ch * 8 + 4]), src, true);
        }
    };

    int nT = (n_k + 63) >> 6;
    prefetch(0, 0);
    cp_commit();
    for (int it = 0; it < nT; it++) {
        if (it + 1 < nT) prefetch((it + 1) & 1, (it + 1) * 64);
        cp_commit();
        cp_wait1();
        __syncthreads();
        int st = it & 1;
        int kcount = min(64, n_k - it * 64);

        float s[8][4];
#pragma unroll
        for (int nt = 0; nt < 8; nt++)
#pragma unroll
            for (int r = 0; r < 4; r++) s[nt][r] = 0.f;
#pragma unroll
        for (int kt = 0; kt < 3; kt++) {
#pragma unroll
            for (int nt = 0; nt < 8; nt++) {
                int kr = nt * 8 + grp;
                uint32_t b0 = Ks[st][kr][kt * 8 + t4];
                uint32_t b1 = (kt < 2) ? Ks[st][kr][kt * 8 + 4 + t4] : 0u;
                mma_f16(s[nt], qf[kt], b0, b1);
            }
        }
        if (kcount < 64) {
#pragma unroll
            for (int nt = 0; nt < 8; nt++) {
                int c0 = nt * 8 + 2 * t4;
                if (c0 >= kcount)     { s[nt][0] = -1e30f; s[nt][2] = -1e30f; }
                if (c0 + 1 >= kcount) { s[nt][1] = -1e30f; s[nt][3] = -1e30f; }
            }
        }

        float mx0 = m_r0, mx1 = m_r1;
#pragma unroll
        for (int nt = 0; nt < 8; nt++) {
            mx0 = fmaxf(mx0, fmaxf(s[nt][0], s[nt][1]));
            mx1 = fmaxf(mx1, fmaxf(s[nt][2], s[nt][3]));
        }
        mx0 = fmaxf(mx0, __shfl_xor_sync(0xffffffffu, mx0, 1));
        mx0 = fmaxf(mx0, __shfl_xor_sync(0xffffffffu, mx0, 2));
        mx1 = fmaxf(mx1, __shfl_xor_sync(0xffffffffu, mx1, 1));
        mx1 = fmaxf(mx1, __shfl_xor_sync(0xffffffffu, mx1, 2));
        float f0 = __expf(m_r0 - mx0), f1 = __expf(m_r1 - mx1);
        float p[8][4];
        float sum0 = 0.f, sum1 = 0.f;
#pragma unroll
        for (int nt = 0; nt < 8; nt++) {
            p[nt][0] = __expf(s[nt][0] - mx0);
            p[nt][1] = __expf(s[nt][1] - mx0);
            p[nt][2] = __expf(s[nt][2] - mx1);
            p[nt][3] = __expf(s[nt][3] - mx1);
            sum0 += p[nt][0] + p[nt][1];
            sum1 += p[nt][2] + p[nt][3];
        }
        sum0 += __shfl_xor_sync(0xffffffffu, sum0, 1);
        sum0 += __shfl_xor_sync(0xffffffffu, sum0, 2);
        sum1 += __shfl_xor_sync(0xffffffffu, sum1, 1);
        sum1 += __shfl_xor_sync(0xffffffffu, sum1, 2);
        l_r0 = l_r0 * f0 + sum0; m_r0 = mx0;
        l_r1 = l_r1 * f1 + sum1; m_r1 = mx1;

        uint32_t pa[4][4];
#pragma unroll
        for (int ks = 0; ks < 4; ks++) {
            pa[ks][0] = packh2(p[2 * ks][0],     p[2 * ks][1]);
            pa[ks][1] = packh2(p[2 * ks][2],     p[2 * ks][3]);
            pa[ks][2] = packh2(p[2 * ks + 1][0], p[2 * ks + 1][1]);
            pa[ks][3] = packh2(p[2 * ks + 1][2], p[2 * ks + 1][3]);
        }

#pragma unroll
        for (int d = 0; d < 5; d++) {
            o[d][0] *= f0; o[d][1] *= f0;
            o[d][2] *= f1; o[d][3] *= f1;
        }

#pragma unroll
        for (int d = 0; d < 5; d++) {
            int vr = d * 8 + grp;
#pragma unroll
            for (int ks = 0; ks < 4; ks++) {
                uint32_t b0 = Vs[st][vr][ks * 8 + t4];
                uint32_t b1 = Vs[st][vr][ks * 8 + 4 + t4];
                mma_f16(o[d], pa[ks], b0, b1);
            }
        }
        __syncthreads();
    }

    float inv0 = 1.f / l_r0, inv1 = 1.f / l_r1;
#pragma unroll
    for (int d = 0; d < 5; d++) {
        int c = h * DH + d * 8 + 2 * t4;
        O[(size_t)row0 * DMODEL + c]     = __float2half(o[d][0] * inv0);
        O[(size_t)row0 * DMODEL + c + 1] = __float2half(o[d][1] * inv0);
        O[(size_t)row1 * DMODEL + c]     = __float2half(o[d][2] * inv1);
        O[(size_t)row1 * DMODEL + c + 1] = __float2half(o[d][3] * inv1);
    }
}

// ---------------- host launch ----------------
extern "C" void kernel_launch(void* const* d_in, const int* in_sizes, int n_in,
                              void* d_out, int out_size) {
    const float* x      = (const float*)d_in[0];
    const float* ctx    = (const float*)d_in[1];
    const float* gn_w   = (const float*)d_in[2];
    const float* gn_b   = (const float*)d_in[3];
    const float* pin_w  = (const float*)d_in[4];
    const float* pin_b  = (const float*)d_in[5];
    const float* ln1_w  = (const float*)d_in[6];
    const float* ln1_b  = (const float*)d_in[7];
    const float* q1     = (const float*)d_in[8];
    const float* k1     = (const float*)d_in[9];
    const float* v1     = (const float*)d_in[10];
    const float* o1_w   = (const float*)d_in[11];
    const float* o1_b   = (const float*)d_in[12];
    const float* ln2_w  = (const float*)d_in[13];
    const float* ln2_b  = (const float*)d_in[14];
    const float* q2     = (const float*)d_in[15];
    const float* k2     = (const float*)d_in[16];
    const float* v2     = (const float*)d_in[17];
    const float* o2_w   = (const float*)d_in[18];
    const float* o2_b   = (const float*)d_in[19];
    const float* ln3_w  = (const float*)d_in[20];
    const float* ln3_b  = (const float*)d_in[21];
    const float* ff1_w  = (const float*)d_in[22];
    const float* ff1_b  = (const float*)d_in[23];
    const float* ff2_w  = (const float*)d_in[24];
    const float* ff2_b  = (const float*)d_in[25];
    const float* pout_w = (const float*)d_in[26];
    const float* pout_b = (const float*)d_in[27];
    float* out = (float*)d_out;

    float *bp, *h, *bff1;
    __half *x16, *ln16, *qk16, *vt16, *q216, *k216, *vt2c16, *ao16, *fa16, *hh16, *ctx16;
    __half *wpin16, *wqkv16, *wq216, *wkv216, *wo116, *wo216;
    __half *wff116, *wff216, *wpo16;
    cudaGetSymbolAddress((void**)&bp, g_bp);
    cudaGetSymbolAddress((void**)&h, g_h);
    cudaGetSymbolAddress((void**)&bff1, g_bff1);
    cudaGetSymbolAddress((void**)&x16, g_x16);
    cudaGetSymbolAddress((void**)&ln16, g_ln16);
    cudaGetSymbolAddress((void**)&qk16, g_qk16);
    cudaGetSymbolAddress((void**)&vt16, g_vt16);
    cudaGetSymbolAddress((void**)&q216, g_q216);
    cudaGetSymbolAddress((void**)&k216, g_k216);
    cudaGetSymbolAddress((void**)&vt2c16, g_vt2c16);
    cudaGetSymbolAddress((void**)&ao16, g_ao16);
    cudaGetSymbolAddress((void**)&fa16, g_fa16);
    cudaGetSymbolAddress((void**)&hh16, g_hh16);
    cudaGetSymbolAddress((void**)&ctx16, g_ctx16);
    cudaGetSymbolAddress((void**)&wpin16, g_wpin16);
    cudaGetSymbolAddress((void**)&wqkv16, g_wqkv16);
    cudaGetSymbolAddress((void**)&wq216, g_wq216);
    cudaGetSymbolAddress((void**)&wkv216, g_wkv216);
    cudaGetSymbolAddress((void**)&wo116, g_wo116);
    cudaGetSymbolAddress((void**)&wo216, g_wo216);
    cudaGetSymbolAddress((void**)&wff116, g_wff116);
    cudaGetSymbolAddress((void**)&wff216, g_wff216);
    cudaGetSymbolAddress((void**)&wpo16, g_wpo16);

    // prep: 3 launches
    gn_stats_kernel<<<32, 256>>>(x, gn_w, gn_b);
    fold_pin_kernel<<<DMODEL, 64>>>(pin_w, pin_b);
    prep_kernel<<<PREP_BLOCKS, 256>>>(x, q1, k1, v1, o1_w, q2, k2, v2, o2_w,
                                      ff1_w, ff1_b, ff2_w, pout_w, ctx);

    // pin projection
    gemm_fp16<<<dim3(64, 5), 128>>>(x16, wpin16, h, nullptr, nullptr, bp, nullptr,
        NTOK, DMODEL, DMODEL, DMODEL, 1, 0, 0, 0);

    // self-attention block: fused QKV (split epilogue: qk row-major, v transposed)
    ln_kernel<<<NTOK / 8, 256>>>(h, ln1_w, ln1_b, ln16);
    gemm_fp16<<<dim3(64, 15), 128>>>(ln16, wqkv16, nullptr, qk16, vt16, nullptr, nullptr,
        NTOK, 3 * DMODEL, DMODEL, 2 * DMODEL, 1, 2, 2 * DMODEL, NTOK);
    attn16<<<dim3(NTOK / 128, HEADS), 256>>>(
        qk16, 2 * DMODEL, qk16 + DMODEL, 2 * DMODEL, vt16, NTOK, ao16, NTOK);
    gemm_fp16<<<dim3(64, 5), 128>>>(ao16, wo116, h, nullptr, nullptr, o1_b, h,
        NTOK, DMODEL, DMODEL, DMODEL, 1, 0, 0, 0);

    // cross-attention block: q2 + fused K2/V2
    ln_kernel<<<NTOK / 8, 256>>>(h, ln2_w, ln2_b, ln16);
    gemm_fp16<<<dim3(64, 5), 128>>>(ln16, wq216, nullptr, q216, nullptr, nullptr, nullptr,
        NTOK, DMODEL, DMODEL, DMODEL, 1, 2, DMODEL, 0);
    gemm_fp16<<<dim3(2, 10), 128>>>(ctx16, wkv216, nullptr, k216, vt2c16, nullptr, nullptr,
        CTXN, 2 * DMODEL, CTXD, DMODEL, 1, 2, DMODEL, CTXP);
    attn16<<<dim3(NTOK / 128, HEADS), 256>>>(
        q216, DMODEL, k216, DMODEL, vt2c16, CTXP, ao16, CTXN);
    gemm_fp16<<<dim3(64, 5), 128>>>(ao16, wo216, h, nullptr, nullptr, o2_b, h,
        NTOK, DMODEL, DMODEL, DMODEL, 1, 0, 0, 0);

    // GEGLU FF block
    ln_kernel<<<NTOK / 8, 256>>>(h, ln3_w, ln3_b, ln16);
    gemm_fp16<<<dim3(64, 40), 128>>>(ln16, wff116, nullptr, fa16, nullptr, bff1, nullptr,
        NTOK, 2 * FFI, DMODEL, FFI, 1, 1, 0, 0);
    gemm_fp16<<<dim3(64, 5), 128>>>(fa16, wff216, h, hh16, nullptr, ff2_b, h,
        NTOK, DMODEL, FFI, DMODEL, 1, 0, 0, 0);

    // output projection (transposed store) + input residual
    gemm_fp16<<<dim3(64, 5), 128>>>(hh16, wpo16, out, nullptr, nullptr, pout_b, x,
        NTOK, DMODEL, DMODEL, 1, NTOK, 0, 0, 0);
}